// round 1
// baseline (speedup 1.0000x reference)
#include <cuda_runtime.h>
#include <math.h>

#define SEQ 8
#define FEAT 2048
#define TLEN 28
#define DOUT 1152
#define WAY 5
#define SHOT 5
#define NQ 500
#define NS 25
#define NFRAMES ((NS + NQ) * SEQ)      /* 4200 */
#define NROWS ((NS + NQ) * TLEN)       /* 14700 */
#define SROWS (NS * TLEN)              /* 700 */
#define QROWS (NQ * TLEN)              /* 14000 */
#define CLS 140                        /* SHOT*TLEN */
#define LN_EPS 1e-5f

// ------------------------- scratch (device globals; no runtime allocs) ----
__device__ float d_PE[SEQ * FEAT];
__device__ float d_X [NFRAMES * FEAT];
__device__ float d_P [4 * NFRAMES * DOUT];          // [kw_top, kw_bot, vw_top, vw_bot] per-frame projections
__device__ float d_KS[NROWS * DOUT];                // layernormed K rows (support 0..699, queries 700..)
__device__ float d_VS[NROWS * DOUT];                // V rows
__device__ float d_VN[NROWS];                       // ||v||^2 per row
__device__ float d_QK[QROWS * SROWS];               // scores -> attn (in place)
__device__ float d_QV[QROWS * SROWS];               // q_v . s_v
__device__ float d_Hq[QROWS * SROWS];               // attn @ G_c per class block
__device__ float d_SS[SROWS * SROWS];               // s_v gram (only diag 140x140 blocks used)

__constant__ int c_TA[TLEN] = {0,0,0,0,0,0,0,1,1,1,1,1,1,2,2,2,2,2,3,3,3,3,4,4,4,5,5,6};
__constant__ int c_TB[TLEN] = {1,2,3,4,5,6,7,2,3,4,5,6,7,3,4,5,6,7,4,5,6,7,5,6,7,6,7,7};

// ------------------------- kernel 0: positional encoding table ------------
__global__ void pe_kernel() {
    int idx = blockIdx.x * blockDim.x + threadIdx.x;
    if (idx >= SEQ * FEAT) return;
    int pos = idx / FEAT, d = idx % FEAT;
    float coef = -logf(10000.0f) / (float)FEAT;
    float div  = expf((float)(d & ~1) * coef);
    float ang  = (float)pos * div;
    d_PE[idx]  = (d & 1) ? cosf(ang) : sinf(ang);
}

// ------------------------- kernel 1: gather frames + PE -------------------
__global__ void build_x(const float* __restrict__ sup, const float* __restrict__ qry) {
    int idx = blockIdx.x * blockDim.x + threadIdx.x;      // one float4 per thread
    long e = (long)idx * 4;
    if (e >= (long)NFRAMES * FEAT) return;
    int f = (int)(e / FEAT);
    int d = (int)(e % FEAT);
    int frame = f % SEQ;
    const float* src = (f < NS * SEQ) ? (sup + (long)f * FEAT + d)
                                      : (qry + (long)(f - NS * SEQ) * FEAT + d);
    float4 v = *(const float4*)src;
    float4 p = *(const float4*)(d_PE + frame * FEAT + d);
    v.x += p.x; v.y += p.y; v.z += p.z; v.w += p.w;
    *(float4*)(d_X + e) = v;
}

// ------------------------- tiled SGEMM (NN / NT) --------------------------
// C[M,N] = A[M,K] @ B   (TRANSB=0: B is [K,N]; TRANSB=1: B is [N,K])
// 128x128 tile, BK=8, 256 threads, 8x8 per thread. Requires K%4==0, N%4==0,
// lda%4==0, ldb%4==0, 16B-aligned base pointers (all call sites satisfy this).
template<int TRANSB>
__global__ void __launch_bounds__(256) sgemm(const float* __restrict__ A,
                                             const float* __restrict__ B,
                                             float* __restrict__ C,
                                             int M, int N, int K,
                                             int lda, int ldb, int ldc)
{
    __shared__ float As[8][132];
    __shared__ float Bs[8][132];
    const int tid = threadIdx.x;
    const int m0 = blockIdx.y * 128;
    const int n0 = blockIdx.x * 128;
    const int tx = tid & 15, ty = tid >> 4;

    float acc[8][8];
    #pragma unroll
    for (int i = 0; i < 8; i++)
        #pragma unroll
        for (int j = 0; j < 8; j++) acc[i][j] = 0.f;

    const int l_r = tid >> 1;          // 0..127 (row within tile)
    const int l_k = (tid & 1) * 4;     // 0 or 4

    for (int k0 = 0; k0 < K; k0 += 8) {
        // A tile (load 4 along K, scatter-transpose into As)
        {
            float4 av = make_float4(0.f, 0.f, 0.f, 0.f);
            int am = m0 + l_r, ak = k0 + l_k;
            if (am < M && ak < K) av = *(const float4*)(A + (size_t)am * lda + ak);
            As[l_k + 0][l_r] = av.x; As[l_k + 1][l_r] = av.y;
            As[l_k + 2][l_r] = av.z; As[l_k + 3][l_r] = av.w;
        }
        // B tile
        if (TRANSB) {
            float4 bv = make_float4(0.f, 0.f, 0.f, 0.f);
            int bn = n0 + l_r, bk = k0 + l_k;
            if (bn < N && bk < K) bv = *(const float4*)(B + (size_t)bn * ldb + bk);
            Bs[l_k + 0][l_r] = bv.x; Bs[l_k + 1][l_r] = bv.y;
            Bs[l_k + 2][l_r] = bv.z; Bs[l_k + 3][l_r] = bv.w;
        } else {
            int bk = k0 + (tid >> 5);
            int bn = n0 + (tid & 31) * 4;
            float4 bv = make_float4(0.f, 0.f, 0.f, 0.f);
            if (bk < K && bn < N) bv = *(const float4*)(B + (size_t)bk * ldb + bn);
            *(float4*)&Bs[tid >> 5][(tid & 31) * 4] = bv;
        }
        __syncthreads();

        #pragma unroll
        for (int kk = 0; kk < 8; kk++) {
            float a[8], b[8];
            *(float4*)(a + 0) = *(const float4*)&As[kk][ty * 8 + 0];
            *(float4*)(a + 4) = *(const float4*)&As[kk][ty * 8 + 4];
            *(float4*)(b + 0) = *(const float4*)&Bs[kk][tx * 8 + 0];
            *(float4*)(b + 4) = *(const float4*)&Bs[kk][tx * 8 + 4];
            #pragma unroll
            for (int i = 0; i < 8; i++)
                #pragma unroll
                for (int j = 0; j < 8; j++) acc[i][j] += a[i] * b[j];
        }
        __syncthreads();
    }

    #pragma unroll
    for (int i = 0; i < 8; i++) {
        int m = m0 + ty * 8 + i;
        if (m >= M) continue;
        #pragma unroll
        for (int j = 0; j < 8; j++) {
            int n = n0 + tx * 8 + j;
            if (n < N) C[(size_t)m * ldc + n] = acc[i][j];
        }
    }
}

// ------------------------- block reduction helper -------------------------
__device__ __forceinline__ float block_sum_256(float v, float* sh) {
    int tid = threadIdx.x;
    sh[tid] = v; __syncthreads();
    #pragma unroll
    for (int s = 128; s > 0; s >>= 1) {
        if (tid < s) sh[tid] += sh[tid + s];
        __syncthreads();
    }
    float r = sh[0]; __syncthreads();
    return r;
}

// ------------------------- kernel 2: assemble K (LN) and V rows -----------
__global__ void assemble(const float* __restrict__ k_b, const float* __restrict__ v_b,
                         const float* __restrict__ gamma, const float* __restrict__ beta)
{
    __shared__ float sh[256];
    int r = blockIdx.x;
    int t, fbase;
    if (r < SROWS) { fbase = (r / TLEN) * SEQ;                  t = r % TLEN; }
    else { int qr = r - SROWS; fbase = NS * SEQ + (qr / TLEN) * SEQ; t = qr % TLEN; }
    int fa = fbase + c_TA[t];
    int fb = fbase + c_TB[t];

    const float* pkt = d_P + 0L * NFRAMES * DOUT + (size_t)fa * DOUT;
    const float* pkb = d_P + 1L * NFRAMES * DOUT + (size_t)fb * DOUT;
    const float* pvt = d_P + 2L * NFRAMES * DOUT + (size_t)fa * DOUT;
    const float* pvb = d_P + 3L * NFRAMES * DOUT + (size_t)fb * DOUT;

    int tid = threadIdx.x;
    float kr[5];
    float s1 = 0.f, s2 = 0.f, vn = 0.f;
    #pragma unroll
    for (int i = 0; i < 5; i++) {
        int j = tid + i * 256;
        if (j < DOUT) {
            float k = pkt[j] + pkb[j] + k_b[j];
            kr[i] = k; s1 += k; s2 += k * k;
            float v = pvt[j] + pvb[j] + v_b[j];
            d_VS[(size_t)r * DOUT + j] = v;
            vn += v * v;
        }
    }
    float S1 = block_sum_256(s1, sh);
    float S2 = block_sum_256(s2, sh);
    float VN = block_sum_256(vn, sh);
    float mu  = S1 / (float)DOUT;
    float var = S2 / (float)DOUT - mu * mu;
    float inv = rsqrtf(var + LN_EPS);
    #pragma unroll
    for (int i = 0; i < 5; i++) {
        int j = tid + i * 256;
        if (j < DOUT)
            d_KS[(size_t)r * DOUT + j] = (kr[i] - mu) * inv * gamma[j] + beta[j];
    }
    if (tid == 0) d_VN[r] = VN;
}

// ------------------------- kernel 3: softmax over 140 per (row, class) ----
__global__ void softmax_k(float scale) {
    int row  = blockIdx.x;              // 0..QROWS-1
    int c    = threadIdx.x >> 5;        // 5 warps -> 5 classes
    int lane = threadIdx.x & 31;
    float* p = d_QK + (size_t)row * SROWS + c * CLS;

    float v[5];
    float mx = -1e30f;
    #pragma unroll
    for (int i = 0; i < 5; i++) {
        int j = lane + 32 * i;
        v[i] = (j < CLS) ? p[j] * scale : -1e30f;
        mx = fmaxf(mx, v[i]);
    }
    #pragma unroll
    for (int s = 16; s > 0; s >>= 1) mx = fmaxf(mx, __shfl_xor_sync(0xffffffffu, mx, s));
    float sum = 0.f;
    #pragma unroll
    for (int i = 0; i < 5; i++) {
        int j = lane + 32 * i;
        if (j < CLS) { v[i] = expf(v[i] - mx); sum += v[i]; }
    }
    #pragma unroll
    for (int s = 16; s > 0; s >>= 1) sum += __shfl_xor_sync(0xffffffffu, sum, s);
    float invs = 1.0f / sum;
    #pragma unroll
    for (int i = 0; i < 5; i++) {
        int j = lane + 32 * i;
        if (j < CLS) p[j] = v[i] * invs;
    }
}

// ------------------------- kernel 4: distance reduction + logits ----------
__global__ void final_k(const float* __restrict__ gt, const float* __restrict__ tw,
                        float* __restrict__ out)
{
    __shared__ float sh[256];
    int q = blockIdx.x;
    int tid = threadIdx.x;
    float temp = gt[0] * tw[0];

    float qp = (tid < TLEN) ? d_VN[SROWS + q * TLEN + tid] : 0.f;
    float qsum = block_sum_256(qp, sh);

    for (int c = 0; c < WAY; c++) {
        float part = 0.f;
        for (int idx = tid; idx < TLEN * CLS; idx += 256) {
            int t = idx / CLS, j = idx % CLS;
            size_t off = (size_t)(q * TLEN + t) * SROWS + c * CLS + j;
            float a = d_QK[off];
            part += a * (d_Hq[off] - 2.0f * d_QV[off]);
        }
        float total = block_sum_256(part, sh);
        if (tid == 0) {
            float dist = (qsum + total) / (float)TLEN;
            out[q * WAY + c] = -dist * temp;
        }
    }
}

// ------------------------- launch -----------------------------------------
extern "C" void kernel_launch(void* const* d_in, const int* in_sizes, int n_in,
                              void* d_out, int out_size) {
    const float* sup   = (const float*)d_in[0];
    const float* qry   = (const float*)d_in[2];
    const float* k_w   = (const float*)d_in[3];
    const float* k_b   = (const float*)d_in[4];
    const float* v_w   = (const float*)d_in[5];
    const float* v_b   = (const float*)d_in[6];
    const float* gamma = (const float*)d_in[7];
    const float* beta  = (const float*)d_in[8];
    const float* gt    = (const float*)d_in[9];
    const float* tw    = (const float*)d_in[10];
    float* out = (float*)d_out;

    float *pX, *pP, *pKS, *pVS, *pQK, *pQV, *pH, *pSS;
    cudaGetSymbolAddress((void**)&pX,  d_X);
    cudaGetSymbolAddress((void**)&pP,  d_P);
    cudaGetSymbolAddress((void**)&pKS, d_KS);
    cudaGetSymbolAddress((void**)&pVS, d_VS);
    cudaGetSymbolAddress((void**)&pQK, d_QK);
    cudaGetSymbolAddress((void**)&pQV, d_QV);
    cudaGetSymbolAddress((void**)&pH,  d_Hq);
    cudaGetSymbolAddress((void**)&pSS, d_SS);

    pe_kernel<<<(SEQ * FEAT + 255) / 256, 256>>>();
    build_x<<<(NFRAMES * FEAT / 4 + 255) / 256, 256>>>(sup, qry);

    // Per-frame half projections: P[p] = X @ W_half  (4 GEMMs, M=4200,N=1152,K=2048)
    dim3 gP((DOUT + 127) / 128, (NFRAMES + 127) / 128);
    const long PS = (long)NFRAMES * DOUT;
    sgemm<0><<<gP, 256>>>(pX, k_w,                pP + 0 * PS, NFRAMES, DOUT, FEAT, FEAT, DOUT, DOUT);
    sgemm<0><<<gP, 256>>>(pX, k_w + (long)FEAT * DOUT, pP + 1 * PS, NFRAMES, DOUT, FEAT, FEAT, DOUT, DOUT);
    sgemm<0><<<gP, 256>>>(pX, v_w,                pP + 2 * PS, NFRAMES, DOUT, FEAT, FEAT, DOUT, DOUT);
    sgemm<0><<<gP, 256>>>(pX, v_w + (long)FEAT * DOUT, pP + 3 * PS, NFRAMES, DOUT, FEAT, FEAT, DOUT, DOUT);

    assemble<<<NROWS, 256>>>(k_b, v_b, gamma, beta);

    // QK = q_ks @ s_ks^T ; QV = q_vs @ s_vs^T ; SS = s_vs @ s_vs^T
    dim3 gQ((SROWS + 127) / 128, (QROWS + 127) / 128);
    sgemm<1><<<gQ, 256>>>(pKS + (long)SROWS * DOUT, pKS, pQK, QROWS, SROWS, DOUT, DOUT, DOUT, SROWS);
    sgemm<1><<<gQ, 256>>>(pVS + (long)SROWS * DOUT, pVS, pQV, QROWS, SROWS, DOUT, DOUT, DOUT, SROWS);
    dim3 gS((SROWS + 127) / 128, (SROWS + 127) / 128);
    sgemm<1><<<gS, 256>>>(pVS, pVS, pSS, SROWS, SROWS, DOUT, DOUT, DOUT, SROWS);

    softmax_k<<<QROWS, 160>>>(1.0f / sqrtf((float)DOUT));

    // H_c = attn_c @ G_c  (G_c = diag 140x140 block of SS)
    dim3 gH((CLS + 127) / 128, (QROWS + 127) / 128);
    for (int c = 0; c < WAY; c++) {
        sgemm<0><<<gH, 256>>>(pQK + c * CLS,
                              pSS + (long)c * CLS * SROWS + c * CLS,
                              pH + c * CLS,
                              QROWS, CLS, CLS, SROWS, SROWS, SROWS);
    }

    final_k<<<NQ, 256>>>(gt, tw, out);
}

// round 3
// speedup vs baseline: 5.2483x; 5.2483x over previous
#include <cuda_runtime.h>
#include <cuda_bf16.h>
#include <math.h>
#include <stdint.h>

#define SEQ 8
#define FEAT 2048
#define TLEN 28
#define DOUT 1152
#define WAY 5
#define SHOT 5
#define NQ 500
#define NS 25
#define NFRAMES ((NS + NQ) * SEQ)      /* 4200 */
#define NROWS ((NS + NQ) * TLEN)       /* 14700 */
#define SROWS (NS * TLEN)              /* 700 */
#define QROWS (NQ * TLEN)              /* 14000 */
#define CLS 140                        /* SHOT*TLEN */
#define LN_EPS 1e-5f
#define WSTK (4 * DOUT)                /* 4608 */
#define ABLD 720                       /* bf16 attn row stride (5*144) */
#define CPAD 144                       /* padded class block stride */

// ------------------------- scratch (device globals) -----------------------
__device__ float          d_PE [SEQ * FEAT];
__device__ __nv_bfloat16  d_Xh [NFRAMES * FEAT];
__device__ __nv_bfloat16  d_WT [WSTK * FEAT];
__device__ float          d_P  [NFRAMES * WSTK];
__device__ __nv_bfloat16  d_KSh[NROWS * DOUT];
__device__ __nv_bfloat16  d_VSh[NROWS * DOUT];
__device__ float          d_VN [NROWS];
__device__ float          d_QK [QROWS * SROWS];
__device__ __nv_bfloat16  d_Ab [QROWS * ABLD];
__device__ float          d_QV [QROWS * SROWS];
__device__ float          d_Hq [QROWS * SROWS];
__device__ __nv_bfloat16  d_SSh[WAY * CLS * CPAD];

__constant__ int c_TA[TLEN] = {0,0,0,0,0,0,0,1,1,1,1,1,1,2,2,2,2,2,3,3,3,3,4,4,4,5,5,6};
__constant__ int c_TB[TLEN] = {1,2,3,4,5,6,7,2,3,4,5,6,7,3,4,5,6,7,4,5,6,7,5,6,7,6,7,7};

__device__ __forceinline__ uint32_t smem_u32(const void* p) {
    uint32_t a;
    asm("{ .reg .u64 t; cvta.to.shared.u64 t, %1; cvt.u32.u64 %0, t; }" : "=r"(a) : "l"(p));
    return a;
}

// ------------------------- kernel 0: positional encoding ------------------
__global__ void pe_kernel() {
    int idx = blockIdx.x * blockDim.x + threadIdx.x;
    if (idx >= SEQ * FEAT) return;
    int pos = idx / FEAT, d = idx % FEAT;
    float coef = -logf(10000.0f) / (float)FEAT;
    float div  = expf((float)(d & ~1) * coef);
    float ang  = (float)pos * div;
    d_PE[idx]  = (d & 1) ? cosf(ang) : sinf(ang);
}

// ------------------------- kernel 1: gather frames + PE -> bf16 -----------
__global__ void build_x(const float* __restrict__ sup, const float* __restrict__ qry) {
    long e = ((long)blockIdx.x * blockDim.x + threadIdx.x) * 8;
    if (e >= (long)NFRAMES * FEAT) return;
    int f = (int)(e / FEAT);
    int d = (int)(e % FEAT);
    int frame = f % SEQ;
    const float* src = (f < NS * SEQ) ? (sup + (long)f * FEAT + d)
                                      : (qry + (long)(f - NS * SEQ) * FEAT + d);
    float4 a = *(const float4*)src;
    float4 b = *(const float4*)(src + 4);
    const float* pe = d_PE + frame * FEAT + d;
    float4 pa = *(const float4*)pe;
    float4 pb = *(const float4*)(pe + 4);
    __nv_bfloat162 h[4];
    h[0] = __floats2bfloat162_rn(a.x + pa.x, a.y + pa.y);
    h[1] = __floats2bfloat162_rn(a.z + pa.z, a.w + pa.w);
    h[2] = __floats2bfloat162_rn(b.x + pb.x, b.y + pb.y);
    h[3] = __floats2bfloat162_rn(b.z + pb.z, b.w + pb.w);
    *(uint4*)(d_Xh + e) = *(uint4*)h;
}

// ------------------------- kernel 2: weight transpose -> bf16 -------------
__global__ void wtrans(const float* __restrict__ kw, const float* __restrict__ vw) {
    __shared__ float t[32][33];
    int p  = blockIdx.z;
    int n0 = blockIdx.x * 32, k0 = blockIdx.y * 32;
    const float* W = ((p < 2) ? kw : vw) + (size_t)((p & 1) * FEAT) * DOUT;
    #pragma unroll
    for (int i = 0; i < 4; i++) {
        int k = k0 + threadIdx.y + i * 8;
        t[threadIdx.y + i * 8][threadIdx.x] = W[(size_t)k * DOUT + n0 + threadIdx.x];
    }
    __syncthreads();
    #pragma unroll
    for (int i = 0; i < 4; i++) {
        int n = n0 + threadIdx.y + i * 8;
        d_WT[(size_t)(p * DOUT + n) * FEAT + k0 + threadIdx.x] =
            __float2bfloat16(t[threadIdx.x][threadIdx.y + i * 8]);
    }
}

// ------------------------- bf16 mma.sync NT GEMM --------------------------
// C[M,N] = A[M,K] @ B[N,K]^T, fp32 accumulate.
// 128x128 tile, BK=32, 8 warps (2x4), 4 smem buffers / 3 cp.async groups.
#define MG_STRIDE 40                           /* smem row stride in halves */
#define MG_STAGE_B (128 * MG_STRIDE * 2)       /* 10240 bytes per operand   */
#define MG_SMEM (4 * 2 * MG_STAGE_B)           /* 81920 bytes               */

template<int OUTBF>
__global__ void __launch_bounds__(256) mgemm(const __nv_bfloat16* __restrict__ A,
                                             const __nv_bfloat16* __restrict__ B,
                                             void* __restrict__ Cv,
                                             int M, int N, int K,
                                             int lda, int ldb, int ldc)
{
    extern __shared__ __align__(16) char smem[];
    const uint32_t sbase = smem_u32(smem);
    const int tid  = threadIdx.x;
    const int wid  = tid >> 5, lane = tid & 31;
    const int wm   = wid >> 2, wn = wid & 3;      // warp grid 2x4
    const int m0   = blockIdx.y * 128, n0 = blockIdx.x * 128;
    const int nk   = (K + 31) >> 5;

    float acc[4][4][4];
    #pragma unroll
    for (int i = 0; i < 4; i++)
        #pragma unroll
        for (int j = 0; j < 4; j++)
            #pragma unroll
            for (int r = 0; r < 4; r++) acc[i][j][r] = 0.f;

    auto load_stage = [&](int sidx, int kc) {
        const int k0 = kc * 32;
        const uint32_t st = sbase + sidx * (2 * MG_STAGE_B);
        #pragma unroll
        for (int it = 0; it < 4; it++) {
            int idx = it * 256 + tid;            // 0..1023
            int isB = idx >> 9;
            int li  = idx & 511;
            int row = li >> 2, ch = li & 3;      // 128 rows x 4 chunks of 8 halves
            int ke  = k0 + ch * 8;
            int gr  = (isB ? n0 : m0) + row;
            int lim = isB ? N : M;
            const __nv_bfloat16* base = isB ? B : A;
            int ld  = isB ? ldb : lda;
            int sz  = 0;
            long off = 0;
            if (gr < lim && ke < K) {
                int rem = (K - ke) * 2;
                sz = rem >= 16 ? 16 : rem;
                off = (long)gr * ld + ke;
            }
            const void* src = base + off;
            uint32_t dst = st + (isB ? MG_STAGE_B : 0u) + (uint32_t)(row * (MG_STRIDE * 2) + ch * 16);
            asm volatile("cp.async.cg.shared.global [%0], [%1], 16, %2;"
                         :: "r"(dst), "l"(src), "r"(sz) : "memory");
        }
        asm volatile("cp.async.commit_group;" ::: "memory");
    };

    const int pst = nk < 3 ? nk : 3;
    for (int s = 0; s < pst; s++) load_stage(s, s);

    for (int i = 0; i < nk; i++) {
        int pend = nk - 1 - i; if (pend > 2) pend = 2;
        if (pend == 2)      asm volatile("cp.async.wait_group 2;" ::: "memory");
        else if (pend == 1) asm volatile("cp.async.wait_group 1;" ::: "memory");
        else                asm volatile("cp.async.wait_group 0;" ::: "memory");
        __syncthreads();

        if (i + 3 < nk) load_stage((i + 3) & 3, i + 3);

        const uint32_t stA = sbase + (i & 3) * (2 * MG_STAGE_B);
        const uint32_t stB = stA + MG_STAGE_B;

        #pragma unroll
        for (int ks = 0; ks < 2; ks++) {
            uint32_t a[4][4], b[4][2];
            #pragma unroll
            for (int mt = 0; mt < 4; mt++) {
                uint32_t addr = stA + (uint32_t)(((wm * 64 + mt * 16 + (lane & 15)) * MG_STRIDE
                                                  + ks * 16 + (lane >> 4) * 8) * 2);
                asm volatile("ldmatrix.sync.aligned.m8n8.x4.shared.b16 {%0,%1,%2,%3}, [%4];"
                             : "=r"(a[mt][0]), "=r"(a[mt][1]), "=r"(a[mt][2]), "=r"(a[mt][3])
                             : "r"(addr));
            }
            #pragma unroll
            for (int nh = 0; nh < 2; nh++) {
                int nrow = nh * 16 + ((lane >> 4) * 8) + (lane & 7);
                int kof  = ks * 16 + ((lane >> 3) & 1) * 8;
                uint32_t addr = stB + (uint32_t)(((wn * 32 + nrow) * MG_STRIDE + kof) * 2);
                uint32_t r0, r1, r2, r3;
                asm volatile("ldmatrix.sync.aligned.m8n8.x4.shared.b16 {%0,%1,%2,%3}, [%4];"
                             : "=r"(r0), "=r"(r1), "=r"(r2), "=r"(r3) : "r"(addr));
                b[nh * 2][0] = r0;     b[nh * 2][1] = r1;
                b[nh * 2 + 1][0] = r2; b[nh * 2 + 1][1] = r3;
            }
            #pragma unroll
            for (int mt = 0; mt < 4; mt++)
                #pragma unroll
                for (int nt = 0; nt < 4; nt++) {
                    asm volatile(
                        "mma.sync.aligned.m16n8k16.row.col.f32.bf16.bf16.f32 "
                        "{%0,%1,%2,%3}, {%4,%5,%6,%7}, {%8,%9}, {%0,%1,%2,%3};"
                        : "+f"(acc[mt][nt][0]), "+f"(acc[mt][nt][1]),
                          "+f"(acc[mt][nt][2]), "+f"(acc[mt][nt][3])
                        : "r"(a[mt][0]), "r"(a[mt][1]), "r"(a[mt][2]), "r"(a[mt][3]),
                          "r"(b[nt][0]), "r"(b[nt][1]));
                }
        }
    }

    // epilogue
    #pragma unroll
    for (int mt = 0; mt < 4; mt++) {
        #pragma unroll
        for (int nt = 0; nt < 4; nt++) {
            int mb = m0 + wm * 64 + mt * 16 + (lane >> 2);
            int nb = n0 + wn * 32 + nt * 8 + (lane & 3) * 2;
            if (nb >= N) continue;
            if (OUTBF) {
                __nv_bfloat16* C = (__nv_bfloat16*)Cv;
                if (mb < M)
                    *(__nv_bfloat162*)(C + (size_t)mb * ldc + nb) =
                        __floats2bfloat162_rn(acc[mt][nt][0], acc[mt][nt][1]);
                if (mb + 8 < M)
                    *(__nv_bfloat162*)(C + (size_t)(mb + 8) * ldc + nb) =
                        __floats2bfloat162_rn(acc[mt][nt][2], acc[mt][nt][3]);
            } else {
                float* C = (float*)Cv;
                if (mb < M)
                    *(float2*)(C + (size_t)mb * ldc + nb) =
                        make_float2(acc[mt][nt][0], acc[mt][nt][1]);
                if (mb + 8 < M)
                    *(float2*)(C + (size_t)(mb + 8) * ldc + nb) =
                        make_float2(acc[mt][nt][2], acc[mt][nt][3]);
            }
        }
    }
}

// ------------------------- block reduction helper -------------------------
__device__ __forceinline__ float block_sum_256(float v, float* sh) {
    int tid = threadIdx.x;
    sh[tid] = v; __syncthreads();
    #pragma unroll
    for (int s = 128; s > 0; s >>= 1) {
        if (tid < s) sh[tid] += sh[tid + s];
        __syncthreads();
    }
    float r = sh[0]; __syncthreads();
    return r;
}

// ------------------------- kernel 3: assemble K (LN) and V rows -----------
__global__ void assemble(const float* __restrict__ k_b, const float* __restrict__ v_b,
                         const float* __restrict__ gamma, const float* __restrict__ beta)
{
    __shared__ float sh[256];
    int r = blockIdx.x;
    int t, fbase;
    if (r < SROWS) { fbase = (r / TLEN) * SEQ;                       t = r % TLEN; }
    else { int qr = r - SROWS; fbase = NS * SEQ + (qr / TLEN) * SEQ; t = qr % TLEN; }
    int fa = fbase + c_TA[t];
    int fb = fbase + c_TB[t];

    const float* pa = d_P + (size_t)fa * WSTK;
    const float* pb = d_P + (size_t)fb * WSTK;

    int tid = threadIdx.x;
    float kr[5];
    float s1 = 0.f, s2 = 0.f, vn = 0.f;
    #pragma unroll
    for (int i = 0; i < 5; i++) {
        int j = tid + i * 256;
        if (j < DOUT) {
            float k = pa[j] + pb[DOUT + j] + k_b[j];
            kr[i] = k; s1 += k; s2 += k * k;
            float v = pa[2 * DOUT + j] + pb[3 * DOUT + j] + v_b[j];
            d_VSh[(size_t)r * DOUT + j] = __float2bfloat16(v);
            vn += v * v;
        }
    }
    float S1 = block_sum_256(s1, sh);
    float S2 = block_sum_256(s2, sh);
    float VN = block_sum_256(vn, sh);
    float mu  = S1 / (float)DOUT;
    float var = S2 / (float)DOUT - mu * mu;
    float inv = rsqrtf(var + LN_EPS);
    #pragma unroll
    for (int i = 0; i < 5; i++) {
        int j = tid + i * 256;
        if (j < DOUT)
            d_KSh[(size_t)r * DOUT + j] = __float2bfloat16((kr[i] - mu) * inv * gamma[j] + beta[j]);
    }
    if (tid == 0) d_VN[r] = VN;
}

// ------------------------- kernel 4: softmax (fp32 + bf16 copy) -----------
__global__ void softmax_k(float scale) {
    int row  = blockIdx.x;
    int c    = threadIdx.x >> 5;
    int lane = threadIdx.x & 31;
    float* p = d_QK + (size_t)row * SROWS + c * CLS;
    __nv_bfloat16* pb = d_Ab + (size_t)row * ABLD + c * CPAD;

    float v[5];
    float mx = -1e30f;
    #pragma unroll
    for (int i = 0; i < 5; i++) {
        int j = lane + 32 * i;
        v[i] = (j < CLS) ? p[j] * scale : -1e30f;
        mx = fmaxf(mx, v[i]);
    }
    #pragma unroll
    for (int s = 16; s > 0; s >>= 1) mx = fmaxf(mx, __shfl_xor_sync(0xffffffffu, mx, s));
    float sum = 0.f;
    #pragma unroll
    for (int i = 0; i < 5; i++) {
        int j = lane + 32 * i;
        if (j < CLS) { v[i] = expf(v[i] - mx); sum += v[i]; }
    }
    #pragma unroll
    for (int s = 16; s > 0; s >>= 1) sum += __shfl_xor_sync(0xffffffffu, sum, s);
    float invs = 1.0f / sum;
    #pragma unroll
    for (int i = 0; i < 5; i++) {
        int j = lane + 32 * i;
        if (j < CLS) {
            float a = v[i] * invs;
            p[j]  = a;
            pb[j] = __float2bfloat16(a);
        }
    }
}

// ------------------------- kernel 5: distance reduction + logits ----------
__global__ void final_k(const float* __restrict__ gt, const float* __restrict__ tw,
                        float* __restrict__ out)
{
    __shared__ float sh[256];
    int q = blockIdx.x;
    int tid = threadIdx.x;
    float temp = gt[0] * tw[0];

    float qp = (tid < TLEN) ? d_VN[SROWS + q * TLEN + tid] : 0.f;
    float qsum = block_sum_256(qp, sh);

    for (int c = 0; c < WAY; c++) {
        float part = 0.f;
        for (int idx = tid; idx < TLEN * CLS; idx += 256) {
            int t = idx / CLS, j = idx % CLS;
            size_t off = (size_t)(q * TLEN + t) * SROWS + c * CLS + j;
            float a = d_QK[off];
            part += a * (d_Hq[off] - 2.0f * d_QV[off]);
        }
        float total = block_sum_256(part, sh);
        if (tid == 0) {
            float dist = (qsum + total) / (float)TLEN;
            out[q * WAY + c] = -dist * temp;
        }
    }
}

// ------------------------- launch -----------------------------------------
extern "C" void kernel_launch(void* const* d_in, const int* in_sizes, int n_in,
                              void* d_out, int out_size) {
    const float* sup   = (const float*)d_in[0];
    const float* qry   = (const float*)d_in[2];
    const float* k_w   = (const float*)d_in[3];
    const float* k_b   = (const float*)d_in[4];
    const float* v_w   = (const float*)d_in[5];
    const float* v_b   = (const float*)d_in[6];
    const float* gamma = (const float*)d_in[7];
    const float* beta  = (const float*)d_in[8];
    const float* gt    = (const float*)d_in[9];
    const float* tw    = (const float*)d_in[10];
    float* out = (float*)d_out;

    __nv_bfloat16 *pXh, *pWT, *pKSh, *pVSh, *pAb, *pSSh;
    float *pP, *pQK, *pQV, *pH;
    cudaGetSymbolAddress((void**)&pXh,  d_Xh);
    cudaGetSymbolAddress((void**)&pWT,  d_WT);
    cudaGetSymbolAddress((void**)&pP,   d_P);
    cudaGetSymbolAddress((void**)&pKSh, d_KSh);
    cudaGetSymbolAddress((void**)&pVSh, d_VSh);
    cudaGetSymbolAddress((void**)&pQK,  d_QK);
    cudaGetSymbolAddress((void**)&pQV,  d_QV);
    cudaGetSymbolAddress((void**)&pH,   d_Hq);
    cudaGetSymbolAddress((void**)&pAb,  d_Ab);
    cudaGetSymbolAddress((void**)&pSSh, d_SSh);

    cudaFuncSetAttribute(mgemm<0>, cudaFuncAttributeMaxDynamicSharedMemorySize, MG_SMEM);
    cudaFuncSetAttribute(mgemm<1>, cudaFuncAttributeMaxDynamicSharedMemorySize, MG_SMEM);

    pe_kernel<<<(SEQ * FEAT + 255) / 256, 256>>>();
    build_x<<<(NFRAMES * FEAT / 8 + 255) / 256, 256>>>(sup, qry);
    wtrans<<<dim3(DOUT / 32, FEAT / 32, 4), dim3(32, 8)>>>(k_w, v_w);

    // Projections: P[4200, 4608] = Xh[4200, 2048] @ WT[4608, 2048]^T
    {
        dim3 g((WSTK + 127) / 128, (NFRAMES + 127) / 128);
        mgemm<0><<<g, 256, MG_SMEM>>>(pXh, pWT, pP, NFRAMES, WSTK, FEAT, FEAT, FEAT, WSTK);
    }

    assemble<<<NROWS, 256>>>(k_b, v_b, gamma, beta);

    // QK / QV: [14000, 700]
    {
        dim3 g((SROWS + 127) / 128, (QROWS + 127) / 128);
        mgemm<0><<<g, 256, MG_SMEM>>>(pKSh + (size_t)SROWS * DOUT, pKSh, pQK,
                                      QROWS, SROWS, DOUT, DOUT, DOUT, SROWS);
        mgemm<0><<<g, 256, MG_SMEM>>>(pVSh + (size_t)SROWS * DOUT, pVSh, pQV,
                                      QROWS, SROWS, DOUT, DOUT, DOUT, SROWS);
    }

    // Per-class Gram blocks G_c[140,140] (bf16 out, ldc=144)
    {
        dim3 g((CLS + 127) / 128, (CLS + 127) / 128);
        for (int c = 0; c < WAY; c++) {
            mgemm<1><<<g, 256, MG_SMEM>>>(pVSh + (size_t)c * CLS * DOUT,
                                          pVSh + (size_t)c * CLS * DOUT,
                                          pSSh + (size_t)c * CLS * CPAD,
                                          CLS, CLS, DOUT, DOUT, DOUT, CPAD);
        }
    }

    softmax_k<<<QROWS, 160>>>(1.0f / sqrtf((float)DOUT));

    // H_c = attn_c @ G_c  (G symmetric -> NT form valid)
    {
        dim3 g((CLS + 127) / 128, (QROWS + 127) / 128);
        for (int c = 0; c < WAY; c++) {
            mgemm<0><<<g, 256, MG_SMEM>>>(pAb + (size_t)c * CPAD,
                                          pSSh + (size_t)c * CLS * CPAD,
                                          pH + (size_t)c * CLS,
                                          QROWS, CLS, CLS, ABLD, CPAD, SROWS);
        }
    }

    final_k<<<NQ, 256>>>(gt, tw, out);
}

// round 4
// speedup vs baseline: 6.1377x; 1.1695x over previous
#include <cuda_runtime.h>
#include <cuda_bf16.h>
#include <math.h>
#include <stdint.h>

#define SEQ 8
#define FEAT 2048
#define TLEN 28
#define DOUT 1152
#define WAY 5
#define SHOT 5
#define NQ 500
#define NS 25
#define NFRAMES ((NS + NQ) * SEQ)      /* 4200 */
#define NROWS ((NS + NQ) * TLEN)       /* 14700 */
#define SROWS (NS * TLEN)              /* 700 */
#define QROWS (NQ * TLEN)              /* 14000 */
#define CLS 140                        /* SHOT*TLEN */
#define LN_EPS 1e-5f
#define WSTK (4 * DOUT)                /* 4608 */
#define ABLD 720                       /* bf16 attn row stride (5*144) */
#define CPAD 144                       /* padded class block stride */

// ------------------------- scratch (device globals) -----------------------
__device__ float          d_PE [SEQ * FEAT];
__device__ __nv_bfloat16  d_Xh [NFRAMES * FEAT];
__device__ __nv_bfloat16  d_WT [WSTK * FEAT];
__device__ __nv_bfloat16  d_Ph [NFRAMES * WSTK];          // per-frame projections (bf16)
__device__ __nv_bfloat16  d_KSh[NROWS * DOUT];
__device__ __nv_bfloat16  d_VSh[NROWS * DOUT];
__device__ float          d_VN [NROWS];
__device__ float          d_QK [QROWS * SROWS];
__device__ __nv_bfloat16  d_Ab [QROWS * ABLD];
__device__ float          d_QV [QROWS * SROWS];
__device__ float          d_Hq [QROWS * SROWS];
__device__ __nv_bfloat16  d_SSh[WAY * CLS * CPAD];

__constant__ int c_TA[TLEN] = {0,0,0,0,0,0,0,1,1,1,1,1,1,2,2,2,2,2,3,3,3,3,4,4,4,5,5,6};
__constant__ int c_TB[TLEN] = {1,2,3,4,5,6,7,2,3,4,5,6,7,3,4,5,6,7,4,5,6,7,5,6,7,6,7,7};

__device__ __forceinline__ uint32_t smem_u32(const void* p) {
    uint32_t a;
    asm("{ .reg .u64 t; cvta.to.shared.u64 t, %1; cvt.u32.u64 %0, t; }" : "=r"(a) : "l"(p));
    return a;
}

// ------------------------- kernel 0: positional encoding ------------------
__global__ void pe_kernel() {
    int idx = blockIdx.x * blockDim.x + threadIdx.x;
    if (idx >= SEQ * FEAT) return;
    int pos = idx / FEAT, d = idx % FEAT;
    float coef = -logf(10000.0f) / (float)FEAT;
    float div  = expf((float)(d & ~1) * coef);
    float ang  = (float)pos * div;
    d_PE[idx]  = (d & 1) ? cosf(ang) : sinf(ang);
}

// ------------------------- kernel 1: gather frames + PE -> bf16 -----------
__global__ void build_x(const float* __restrict__ sup, const float* __restrict__ qry) {
    long e = ((long)blockIdx.x * blockDim.x + threadIdx.x) * 8;
    if (e >= (long)NFRAMES * FEAT) return;
    int f = (int)(e / FEAT);
    int d = (int)(e % FEAT);
    int frame = f % SEQ;
    const float* src = (f < NS * SEQ) ? (sup + (long)f * FEAT + d)
                                      : (qry + (long)(f - NS * SEQ) * FEAT + d);
    float4 a = *(const float4*)src;
    float4 b = *(const float4*)(src + 4);
    const float* pe = d_PE + frame * FEAT + d;
    float4 pa = *(const float4*)pe;
    float4 pb = *(const float4*)(pe + 4);
    __nv_bfloat162 h[4];
    h[0] = __floats2bfloat162_rn(a.x + pa.x, a.y + pa.y);
    h[1] = __floats2bfloat162_rn(a.z + pa.z, a.w + pa.w);
    h[2] = __floats2bfloat162_rn(b.x + pb.x, b.y + pb.y);
    h[3] = __floats2bfloat162_rn(b.z + pb.z, b.w + pb.w);
    *(uint4*)(d_Xh + e) = *(uint4*)h;
}

// ------------------------- kernel 2: weight transpose -> bf16 -------------
__global__ void wtrans(const float* __restrict__ kw, const float* __restrict__ vw) {
    __shared__ float t[32][33];
    int p  = blockIdx.z;
    int n0 = blockIdx.x * 32, k0 = blockIdx.y * 32;
    const float* W = ((p < 2) ? kw : vw) + (size_t)((p & 1) * FEAT) * DOUT;
    #pragma unroll
    for (int i = 0; i < 4; i++) {
        int k = k0 + threadIdx.y + i * 8;
        t[threadIdx.y + i * 8][threadIdx.x] = W[(size_t)k * DOUT + n0 + threadIdx.x];
    }
    __syncthreads();
    #pragma unroll
    for (int i = 0; i < 4; i++) {
        int n = n0 + threadIdx.y + i * 8;
        d_WT[(size_t)(p * DOUT + n) * FEAT + k0 + threadIdx.x] =
            __float2bfloat16(t[threadIdx.x][threadIdx.y + i * 8]);
    }
}

// ------------------------- bf16 mma.sync NT GEMM (batched) ----------------
// Per z: C[M,N] = A[M,K] @ B[N,K]^T, fp32 accumulate.
// 128x128 tile, BK=32, 8 warps (2x4), 4 smem buffers / 3 cp.async groups.
#define MG_STRIDE 40
#define MG_STAGE_B (128 * MG_STRIDE * 2)
#define MG_SMEM (4 * 2 * MG_STAGE_B)

struct BPtr { const __nv_bfloat16* A; const __nv_bfloat16* B; void* C; };
struct BatchArg { BPtr p[5]; };

template<int OUTBF>
__global__ void __launch_bounds__(256) mgemm(BatchArg ba,
                                             int M, int N, int K,
                                             int lda, int ldb, int ldc)
{
    extern __shared__ __align__(16) char smem[];
    const uint32_t sbase = smem_u32(smem);
    const int tid  = threadIdx.x;
    const int wid  = tid >> 5, lane = tid & 31;
    const int wm   = wid >> 2, wn = wid & 3;
    const int m0   = blockIdx.y * 128, n0 = blockIdx.x * 128;
    const int nk   = (K + 31) >> 5;

    const __nv_bfloat16* __restrict__ A = ba.p[blockIdx.z].A;
    const __nv_bfloat16* __restrict__ B = ba.p[blockIdx.z].B;
    void* __restrict__ Cv = ba.p[blockIdx.z].C;

    float acc[4][4][4];
    #pragma unroll
    for (int i = 0; i < 4; i++)
        #pragma unroll
        for (int j = 0; j < 4; j++)
            #pragma unroll
            for (int r = 0; r < 4; r++) acc[i][j][r] = 0.f;

    auto load_stage = [&](int sidx, int kc) {
        const int k0 = kc * 32;
        const uint32_t st = sbase + sidx * (2 * MG_STAGE_B);
        #pragma unroll
        for (int it = 0; it < 4; it++) {
            int idx = it * 256 + tid;
            int isB = idx >> 9;
            int li  = idx & 511;
            int row = li >> 2, ch = li & 3;
            int ke  = k0 + ch * 8;
            int gr  = (isB ? n0 : m0) + row;
            int lim = isB ? N : M;
            const __nv_bfloat16* base = isB ? B : A;
            int ld  = isB ? ldb : lda;
            int sz  = 0;
            long off = 0;
            if (gr < lim && ke < K) {
                int rem = (K - ke) * 2;
                sz = rem >= 16 ? 16 : rem;
                off = (long)gr * ld + ke;
            }
            const void* src = base + off;
            uint32_t dst = st + (isB ? MG_STAGE_B : 0u) + (uint32_t)(row * (MG_STRIDE * 2) + ch * 16);
            asm volatile("cp.async.cg.shared.global [%0], [%1], 16, %2;"
                         :: "r"(dst), "l"(src), "r"(sz) : "memory");
        }
        asm volatile("cp.async.commit_group;" ::: "memory");
    };

    const int pst = nk < 3 ? nk : 3;
    for (int s = 0; s < pst; s++) load_stage(s, s);

    for (int i = 0; i < nk; i++) {
        int pend = nk - 1 - i; if (pend > 2) pend = 2;
        if (pend == 2)      asm volatile("cp.async.wait_group 2;" ::: "memory");
        else if (pend == 1) asm volatile("cp.async.wait_group 1;" ::: "memory");
        else                asm volatile("cp.async.wait_group 0;" ::: "memory");
        __syncthreads();

        if (i + 3 < nk) load_stage((i + 3) & 3, i + 3);

        const uint32_t stA = sbase + (i & 3) * (2 * MG_STAGE_B);
        const uint32_t stB = stA + MG_STAGE_B;

        #pragma unroll
        for (int ks = 0; ks < 2; ks++) {
            uint32_t a[4][4], b[4][2];
            #pragma unroll
            for (int mt = 0; mt < 4; mt++) {
                uint32_t addr = stA + (uint32_t)(((wm * 64 + mt * 16 + (lane & 15)) * MG_STRIDE
                                                  + ks * 16 + (lane >> 4) * 8) * 2);
                asm volatile("ldmatrix.sync.aligned.m8n8.x4.shared.b16 {%0,%1,%2,%3}, [%4];"
                             : "=r"(a[mt][0]), "=r"(a[mt][1]), "=r"(a[mt][2]), "=r"(a[mt][3])
                             : "r"(addr));
            }
            #pragma unroll
            for (int nh = 0; nh < 2; nh++) {
                int nrow = nh * 16 + ((lane >> 4) * 8) + (lane & 7);
                int kof  = ks * 16 + ((lane >> 3) & 1) * 8;
                uint32_t addr = stB + (uint32_t)(((wn * 32 + nrow) * MG_STRIDE + kof) * 2);
                uint32_t r0, r1, r2, r3;
                asm volatile("ldmatrix.sync.aligned.m8n8.x4.shared.b16 {%0,%1,%2,%3}, [%4];"
                             : "=r"(r0), "=r"(r1), "=r"(r2), "=r"(r3) : "r"(addr));
                b[nh * 2][0] = r0;     b[nh * 2][1] = r1;
                b[nh * 2 + 1][0] = r2; b[nh * 2 + 1][1] = r3;
            }
            #pragma unroll
            for (int mt = 0; mt < 4; mt++)
                #pragma unroll
                for (int nt = 0; nt < 4; nt++) {
                    asm volatile(
                        "mma.sync.aligned.m16n8k16.row.col.f32.bf16.bf16.f32 "
                        "{%0,%1,%2,%3}, {%4,%5,%6,%7}, {%8,%9}, {%0,%1,%2,%3};"
                        : "+f"(acc[mt][nt][0]), "+f"(acc[mt][nt][1]),
                          "+f"(acc[mt][nt][2]), "+f"(acc[mt][nt][3])
                        : "r"(a[mt][0]), "r"(a[mt][1]), "r"(a[mt][2]), "r"(a[mt][3]),
                          "r"(b[nt][0]), "r"(b[nt][1]));
                }
        }
    }

    #pragma unroll
    for (int mt = 0; mt < 4; mt++) {
        #pragma unroll
        for (int nt = 0; nt < 4; nt++) {
            int mb = m0 + wm * 64 + mt * 16 + (lane >> 2);
            int nb = n0 + wn * 32 + nt * 8 + (lane & 3) * 2;
            if (nb >= N) continue;
            if (OUTBF) {
                __nv_bfloat16* C = (__nv_bfloat16*)Cv;
                if (mb < M)
                    *(__nv_bfloat162*)(C + (size_t)mb * ldc + nb) =
                        __floats2bfloat162_rn(acc[mt][nt][0], acc[mt][nt][1]);
                if (mb + 8 < M)
                    *(__nv_bfloat162*)(C + (size_t)(mb + 8) * ldc + nb) =
                        __floats2bfloat162_rn(acc[mt][nt][2], acc[mt][nt][3]);
            } else {
                float* C = (float*)Cv;
                if (mb < M)
                    *(float2*)(C + (size_t)mb * ldc + nb) =
                        make_float2(acc[mt][nt][0], acc[mt][nt][1]);
                if (mb + 8 < M)
                    *(float2*)(C + (size_t)(mb + 8) * ldc + nb) =
                        make_float2(acc[mt][nt][2], acc[mt][nt][3]);
            }
        }
    }
}

// ------------------------- block reduction helper -------------------------
__device__ __forceinline__ float block_sum_256(float v, float* sh) {
    int tid = threadIdx.x;
    sh[tid] = v; __syncthreads();
    #pragma unroll
    for (int s = 128; s > 0; s >>= 1) {
        if (tid < s) sh[tid] += sh[tid + s];
        __syncthreads();
    }
    float r = sh[0]; __syncthreads();
    return r;
}

// ------------------------- kernel 3: assemble K (LN) and V rows -----------
__global__ void assemble(const float* __restrict__ k_b, const float* __restrict__ v_b,
                         const float* __restrict__ gamma, const float* __restrict__ beta)
{
    __shared__ float sh[256];
    int r = blockIdx.x;
    int t, fbase;
    if (r < SROWS) { fbase = (r / TLEN) * SEQ;                       t = r % TLEN; }
    else { int qr = r - SROWS; fbase = NS * SEQ + (qr / TLEN) * SEQ; t = qr % TLEN; }
    int fa = fbase + c_TA[t];
    int fb = fbase + c_TB[t];

    const __nv_bfloat16* pa = d_Ph + (size_t)fa * WSTK;
    const __nv_bfloat16* pb = d_Ph + (size_t)fb * WSTK;

    int tid = threadIdx.x;
    float kr[5];
    float s1 = 0.f, s2 = 0.f, vn = 0.f;
    #pragma unroll
    for (int i = 0; i < 5; i++) {
        int j = tid + i * 256;
        if (j < DOUT) {
            float k = __bfloat162float(pa[j]) + __bfloat162float(pb[DOUT + j]) + k_b[j];
            kr[i] = k; s1 += k; s2 += k * k;
            float v = __bfloat162float(pa[2 * DOUT + j]) + __bfloat162float(pb[3 * DOUT + j]) + v_b[j];
            d_VSh[(size_t)r * DOUT + j] = __float2bfloat16(v);
            vn += v * v;
        }
    }
    float S1 = block_sum_256(s1, sh);
    float S2 = block_sum_256(s2, sh);
    float VN = block_sum_256(vn, sh);
    float mu  = S1 / (float)DOUT;
    float var = S2 / (float)DOUT - mu * mu;
    float inv = rsqrtf(var + LN_EPS);
    #pragma unroll
    for (int i = 0; i < 5; i++) {
        int j = tid + i * 256;
        if (j < DOUT)
            d_KSh[(size_t)r * DOUT + j] = __float2bfloat16((kr[i] - mu) * inv * gamma[j] + beta[j]);
    }
    if (tid == 0) d_VN[r] = VN;
}

// ------------------------- kernel 4: softmax (fp32 + bf16 copy) -----------
__global__ void softmax_k(float scale) {
    int row  = blockIdx.x;
    int c    = threadIdx.x >> 5;
    int lane = threadIdx.x & 31;
    float* p = d_QK + (size_t)row * SROWS + c * CLS;
    __nv_bfloat16* pb = d_Ab + (size_t)row * ABLD + c * CPAD;

    float v[5];
    float mx = -1e30f;
    #pragma unroll
    for (int i = 0; i < 5; i++) {
        int j = lane + 32 * i;
        v[i] = (j < CLS) ? p[j] * scale : -1e30f;
        mx = fmaxf(mx, v[i]);
    }
    #pragma unroll
    for (int s = 16; s > 0; s >>= 1) mx = fmaxf(mx, __shfl_xor_sync(0xffffffffu, mx, s));
    float sum = 0.f;
    #pragma unroll
    for (int i = 0; i < 5; i++) {
        int j = lane + 32 * i;
        if (j < CLS) { v[i] = expf(v[i] - mx); sum += v[i]; }
    }
    #pragma unroll
    for (int s = 16; s > 0; s >>= 1) sum += __shfl_xor_sync(0xffffffffu, sum, s);
    float invs = 1.0f / sum;
    #pragma unroll
    for (int i = 0; i < 5; i++) {
        int j = lane + 32 * i;
        if (j < CLS) {
            float a = v[i] * invs;
            p[j]  = a;
            pb[j] = __float2bfloat16(a);
        }
    }
}

// ------------------------- kernel 5: distance reduction + logits ----------
__global__ void final_k(const float* __restrict__ gt, const float* __restrict__ tw,
                        float* __restrict__ out)
{
    __shared__ float sh[256];
    int q = blockIdx.x;
    int tid = threadIdx.x;
    float temp = gt[0] * tw[0];

    float qp = (tid < TLEN) ? d_VN[SROWS + q * TLEN + tid] : 0.f;
    float qsum = block_sum_256(qp, sh);

    for (int c = 0; c < WAY; c++) {
        float part = 0.f;
        for (int idx = tid; idx < TLEN * CLS; idx += 256) {
            int t = idx / CLS, j = idx % CLS;
            size_t off = (size_t)(q * TLEN + t) * SROWS + c * CLS + j;
            float a = d_QK[off];
            part += a * (d_Hq[off] - 2.0f * d_QV[off]);
        }
        float total = block_sum_256(part, sh);
        if (tid == 0) {
            float dist = (qsum + total) / (float)TLEN;
            out[q * WAY + c] = -dist * temp;
        }
    }
}

// ------------------------- launch -----------------------------------------
extern "C" void kernel_launch(void* const* d_in, const int* in_sizes, int n_in,
                              void* d_out, int out_size) {
    const float* sup   = (const float*)d_in[0];
    const float* qry   = (const float*)d_in[2];
    const float* k_w   = (const float*)d_in[3];
    const float* k_b   = (const float*)d_in[4];
    const float* v_w   = (const float*)d_in[5];
    const float* v_b   = (const float*)d_in[6];
    const float* gamma = (const float*)d_in[7];
    const float* beta  = (const float*)d_in[8];
    const float* gt    = (const float*)d_in[9];
    const float* tw    = (const float*)d_in[10];
    float* out = (float*)d_out;

    __nv_bfloat16 *pXh, *pWT, *pPh, *pKSh, *pVSh, *pAb, *pSSh;
    float *pQK, *pQV, *pH;
    cudaGetSymbolAddress((void**)&pXh,  d_Xh);
    cudaGetSymbolAddress((void**)&pWT,  d_WT);
    cudaGetSymbolAddress((void**)&pPh,  d_Ph);
    cudaGetSymbolAddress((void**)&pKSh, d_KSh);
    cudaGetSymbolAddress((void**)&pVSh, d_VSh);
    cudaGetSymbolAddress((void**)&pQK,  d_QK);
    cudaGetSymbolAddress((void**)&pQV,  d_QV);
    cudaGetSymbolAddress((void**)&pH,   d_Hq);
    cudaGetSymbolAddress((void**)&pAb,  d_Ab);
    cudaGetSymbolAddress((void**)&pSSh, d_SSh);

    cudaFuncSetAttribute(mgemm<0>, cudaFuncAttributeMaxDynamicSharedMemorySize, MG_SMEM);
    cudaFuncSetAttribute(mgemm<1>, cudaFuncAttributeMaxDynamicSharedMemorySize, MG_SMEM);

    pe_kernel<<<(SEQ * FEAT + 255) / 256, 256>>>();
    build_x<<<(NFRAMES * FEAT / 8 + 255) / 256, 256>>>(sup, qry);
    wtrans<<<dim3(DOUT / 32, FEAT / 32, 4), dim3(32, 8)>>>(k_w, v_w);

    // Projections (bf16 out): Ph[4200, 4608] = Xh @ WT^T
    {
        BatchArg ba = {};
        ba.p[0] = { pXh, pWT, (void*)pPh };
        dim3 g((WSTK + 127) / 128, (NFRAMES + 127) / 128, 1);
        mgemm<1><<<g, 256, MG_SMEM>>>(ba, NFRAMES, WSTK, FEAT, FEAT, FEAT, WSTK);
    }

    assemble<<<NROWS, 256>>>(k_b, v_b, gamma, beta);

    // QK and QV in one batched launch (z=2)
    {
        BatchArg ba = {};
        ba.p[0] = { pKSh + (size_t)SROWS * DOUT, pKSh, (void*)pQK };
        ba.p[1] = { pVSh + (size_t)SROWS * DOUT, pVSh, (void*)pQV };
        dim3 g((SROWS + 127) / 128, (QROWS + 127) / 128, 2);
        mgemm<0><<<g, 256, MG_SMEM>>>(ba, QROWS, SROWS, DOUT, DOUT, DOUT, SROWS);
    }

    // Per-class Gram blocks in one batched launch (z=5), bf16 out, ldc=144
    {
        BatchArg ba = {};
        for (int c = 0; c < WAY; c++)
            ba.p[c] = { pVSh + (size_t)c * CLS * DOUT,
                        pVSh + (size_t)c * CLS * DOUT,
                        (void*)(pSSh + (size_t)c * CLS * CPAD) };
        dim3 g((CLS + 127) / 128, (CLS + 127) / 128, WAY);
        mgemm<1><<<g, 256, MG_SMEM>>>(ba, CLS, CLS, DOUT, DOUT, DOUT, CPAD);
    }

    softmax_k<<<QROWS, 160>>>(1.0f / sqrtf((float)DOUT));

    // H_c = attn_c @ G_c in one batched launch (z=5); G symmetric -> NT valid
    {
        BatchArg ba = {};
        for (int c = 0; c < WAY; c++)
            ba.p[c] = { pAb + (size_t)c * CPAD,
                        pSSh + (size_t)c * CLS * CPAD,
                        (void*)(pH + (size_t)c * CLS) };
        dim3 g((CLS + 127) / 128, (QROWS + 127) / 128, WAY);
        mgemm<0><<<g, 256, MG_SMEM>>>(ba, QROWS, CLS, CLS, ABLD, CPAD, SROWS);
    }

    final_k<<<NQ, 256>>>(gt, tw, out);
}

// round 5
// speedup vs baseline: 6.4654x; 1.0534x over previous
#include <cuda_runtime.h>
#include <cuda_bf16.h>
#include <math.h>
#include <stdint.h>

#define SEQ 8
#define FEAT 2048
#define TLEN 28
#define DOUT 1152
#define WAY 5
#define SHOT 5
#define NQ 500
#define NS 25
#define NFRAMES ((NS + NQ) * SEQ)      /* 4200 */
#define NROWS ((NS + NQ) * TLEN)       /* 14700 */
#define SROWS (NS * TLEN)              /* 700 */
#define QROWS (NQ * TLEN)              /* 14000 */
#define CLS 140                        /* SHOT*TLEN */
#define LN_EPS 1e-5f
#define WSTK (4 * DOUT)                /* 4608 */
#define ABLD 720                       /* bf16 attn row stride (5*144) */
#define CPAD 144                       /* padded class block stride */

// ------------------------- scratch (device globals) -----------------------
__device__ float          d_PE [SEQ * FEAT];
__device__ __nv_bfloat16  d_Xh [NFRAMES * FEAT];
__device__ __nv_bfloat16  d_WT [WSTK * FEAT];
__device__ __nv_bfloat16  d_Ph [NFRAMES * WSTK];
__device__ __nv_bfloat16  d_KSh[NROWS * DOUT];
__device__ __nv_bfloat16  d_VSh[NROWS * DOUT];
__device__ float          d_VN [NROWS];
__device__ float          d_QK [QROWS * SROWS];           // raw scores (fp32)
__device__ __nv_bfloat16  d_Ab [QROWS * ABLD];            // attn bf16, padded blocks
__device__ float          d_QV [QROWS * SROWS];
__device__ float          d_D2 [WAY * QROWS * 8];         // fused distance partials
__device__ __nv_bfloat16  d_SSh[WAY * CLS * CPAD];

__constant__ int c_TA[TLEN] = {0,0,0,0,0,0,0,1,1,1,1,1,1,2,2,2,2,2,3,3,3,3,4,4,4,5,5,6};
__constant__ int c_TB[TLEN] = {1,2,3,4,5,6,7,2,3,4,5,6,7,3,4,5,6,7,4,5,6,7,5,6,7,6,7,7};

__device__ __forceinline__ uint32_t smem_u32(const void* p) {
    uint32_t a;
    asm("{ .reg .u64 t; cvta.to.shared.u64 t, %1; cvt.u32.u64 %0, t; }" : "=r"(a) : "l"(p));
    return a;
}

// ------------------------- kernel 0: positional encoding ------------------
__global__ void pe_kernel() {
    int idx = blockIdx.x * blockDim.x + threadIdx.x;
    if (idx >= SEQ * FEAT) return;
    int pos = idx / FEAT, d = idx % FEAT;
    float coef = -logf(10000.0f) / (float)FEAT;
    float div  = expf((float)(d & ~1) * coef);
    float ang  = (float)pos * div;
    d_PE[idx]  = (d & 1) ? cosf(ang) : sinf(ang);
}

// ------------------------- kernel 1: gather frames + PE -> bf16 -----------
__global__ void build_x(const float* __restrict__ sup, const float* __restrict__ qry) {
    long e = ((long)blockIdx.x * blockDim.x + threadIdx.x) * 8;
    if (e >= (long)NFRAMES * FEAT) return;
    int f = (int)(e / FEAT);
    int d = (int)(e % FEAT);
    int frame = f % SEQ;
    const float* src = (f < NS * SEQ) ? (sup + (long)f * FEAT + d)
                                      : (qry + (long)(f - NS * SEQ) * FEAT + d);
    float4 a = *(const float4*)src;
    float4 b = *(const float4*)(src + 4);
    const float* pe = d_PE + frame * FEAT + d;
    float4 pa = *(const float4*)pe;
    float4 pb = *(const float4*)(pe + 4);
    __nv_bfloat162 h[4];
    h[0] = __floats2bfloat162_rn(a.x + pa.x, a.y + pa.y);
    h[1] = __floats2bfloat162_rn(a.z + pa.z, a.w + pa.w);
    h[2] = __floats2bfloat162_rn(b.x + pb.x, b.y + pb.y);
    h[3] = __floats2bfloat162_rn(b.z + pb.z, b.w + pb.w);
    *(uint4*)(d_Xh + e) = *(uint4*)h;
}

// ------------------------- kernel 2: weight transpose -> bf16 -------------
__global__ void wtrans(const float* __restrict__ kw, const float* __restrict__ vw) {
    __shared__ float t[32][33];
    int p  = blockIdx.z;
    int n0 = blockIdx.x * 32, k0 = blockIdx.y * 32;
    const float* W = ((p < 2) ? kw : vw) + (size_t)((p & 1) * FEAT) * DOUT;
    #pragma unroll
    for (int i = 0; i < 4; i++) {
        int k = k0 + threadIdx.y + i * 8;
        t[threadIdx.y + i * 8][threadIdx.x] = W[(size_t)k * DOUT + n0 + threadIdx.x];
    }
    __syncthreads();
    #pragma unroll
    for (int i = 0; i < 4; i++) {
        int n = n0 + threadIdx.y + i * 8;
        d_WT[(size_t)(p * DOUT + n) * FEAT + k0 + threadIdx.x] =
            __float2bfloat16(t[threadIdx.x][threadIdx.y + i * 8]);
    }
}

// ------------------------- bf16 mma.sync NT GEMM (batched) ----------------
// MODE 0: fp32 C out.  MODE 1: bf16 C out.  MODE 2: fused distance epilogue
// (no C write; computes attn*(acc - 2*QV) row-partials into Df; A IS attn).
#define MG_STRIDE 40
#define MG_STAGE_B (128 * MG_STRIDE * 2)
#define MG_SMEM (4 * 2 * MG_STAGE_B)

struct BPtr { const __nv_bfloat16* A; const __nv_bfloat16* B; void* C; const float* Q; };
struct BatchArg { BPtr p[5]; };

__device__ __forceinline__ void cp16(uint32_t dst, const void* src, int sz) {
    asm volatile("cp.async.cg.shared.global [%0], [%1], 16, %2;"
                 :: "r"(dst), "l"(src), "r"(sz) : "memory");
}

template<int MODE>
__global__ void __launch_bounds__(256) mgemm(BatchArg ba,
                                             int M, int N, int K,
                                             int lda, int ldb, int ldc,
                                             float* __restrict__ Df)
{
    extern __shared__ __align__(16) char smem[];
    const uint32_t sbase = smem_u32(smem);
    const int tid  = threadIdx.x;
    const int wid  = tid >> 5, lane = tid & 31;
    const int wm   = wid >> 2, wn = wid & 3;
    const int m0   = blockIdx.y * 128, n0 = blockIdx.x * 128;
    const int nk   = (K + 31) >> 5;

    const __nv_bfloat16* __restrict__ A = ba.p[blockIdx.z].A;
    const __nv_bfloat16* __restrict__ B = ba.p[blockIdx.z].B;
    void* __restrict__ Cv = ba.p[blockIdx.z].C;

    float acc[4][4][4];
    #pragma unroll
    for (int i = 0; i < 4; i++)
        #pragma unroll
        for (int j = 0; j < 4; j++)
            #pragma unroll
            for (int r = 0; r < 4; r++) acc[i][j][r] = 0.f;

    // ---- hoisted load setup: each thread owns 4 fixed (row, chunk) slots ----
    const int ch = tid & 3;
    const int r0 = tid >> 2;                    // 0..63
    const bool vA0 = (m0 + r0)      < M;
    const bool vA1 = (m0 + r0 + 64) < M;
    const bool vB0 = (n0 + r0)      < N;
    const bool vB1 = (n0 + r0 + 64) < N;
    const __nv_bfloat16* pA0 = A + (size_t)(vA0 ? m0 + r0      : 0) * lda + ch * 8;
    const __nv_bfloat16* pA1 = A + (size_t)(vA1 ? m0 + r0 + 64 : 0) * lda + ch * 8;
    const __nv_bfloat16* pB0 = B + (size_t)(vB0 ? n0 + r0      : 0) * ldb + ch * 8;
    const __nv_bfloat16* pB1 = B + (size_t)(vB1 ? n0 + r0 + 64 : 0) * ldb + ch * 8;
    const uint32_t dA0 = (uint32_t)(r0 * (MG_STRIDE * 2) + ch * 16);
    const uint32_t dA1 = dA0 + 64u * (MG_STRIDE * 2);
    const uint32_t dB0 = dA0 + MG_STAGE_B;
    const uint32_t dB1 = dA1 + MG_STAGE_B;

    auto load_stage = [&](int sidx, int kc) {
        const int k0 = kc * 32;
        const uint32_t st = sbase + sidx * (2 * MG_STAGE_B);
        int sA0, sA1, sB0, sB1;
        if (k0 + 32 <= K) {
            sA0 = vA0 ? 16 : 0; sA1 = vA1 ? 16 : 0;
            sB0 = vB0 ? 16 : 0; sB1 = vB1 ? 16 : 0;
        } else {
            int ke  = k0 + ch * 8;
            int rem = (K - ke) * 2;
            int szk = rem >= 16 ? 16 : (rem > 0 ? rem : 0);
            sA0 = vA0 ? szk : 0; sA1 = vA1 ? szk : 0;
            sB0 = vB0 ? szk : 0; sB1 = vB1 ? szk : 0;
        }
        cp16(st + dA0, pA0 + k0, sA0);
        cp16(st + dA1, pA1 + k0, sA1);
        cp16(st + dB0, pB0 + k0, sB0);
        cp16(st + dB1, pB1 + k0, sB1);
        asm volatile("cp.async.commit_group;" ::: "memory");
    };

    // ---- hoisted fragment smem offsets ----
    uint32_t offA[4], offB[2];
    #pragma unroll
    for (int mt = 0; mt < 4; mt++)
        offA[mt] = (uint32_t)(((wm * 64 + mt * 16 + (lane & 15)) * MG_STRIDE
                               + (lane >> 4) * 8) * 2);
    #pragma unroll
    for (int nh = 0; nh < 2; nh++) {
        int nrow = nh * 16 + ((lane >> 4) * 8) + (lane & 7);
        int kof  = ((lane >> 3) & 1) * 8;
        offB[nh] = (uint32_t)(((wn * 32 + nrow) * MG_STRIDE + kof) * 2) + MG_STAGE_B;
    }

    const int pst = nk < 3 ? nk : 3;
    for (int s = 0; s < pst; s++) load_stage(s, s);

    for (int i = 0; i < nk; i++) {
        int pend = nk - 1 - i; if (pend > 2) pend = 2;
        if (pend == 2)      asm volatile("cp.async.wait_group 2;" ::: "memory");
        else if (pend == 1) asm volatile("cp.async.wait_group 1;" ::: "memory");
        else                asm volatile("cp.async.wait_group 0;" ::: "memory");
        __syncthreads();

        if (i + 3 < nk) load_stage((i + 3) & 3, i + 3);

        const uint32_t stg = sbase + (i & 3) * (2 * MG_STAGE_B);

        #pragma unroll
        for (int ks = 0; ks < 2; ks++) {
            uint32_t a[4][4], b[4][2];
            #pragma unroll
            for (int mt = 0; mt < 4; mt++) {
                uint32_t addr = stg + offA[mt] + ks * 32;
                asm volatile("ldmatrix.sync.aligned.m8n8.x4.shared.b16 {%0,%1,%2,%3}, [%4];"
                             : "=r"(a[mt][0]), "=r"(a[mt][1]), "=r"(a[mt][2]), "=r"(a[mt][3])
                             : "r"(addr));
            }
            #pragma unroll
            for (int nh = 0; nh < 2; nh++) {
                uint32_t addr = stg + offB[nh] + ks * 32;
                uint32_t q0, q1, q2, q3;
                asm volatile("ldmatrix.sync.aligned.m8n8.x4.shared.b16 {%0,%1,%2,%3}, [%4];"
                             : "=r"(q0), "=r"(q1), "=r"(q2), "=r"(q3) : "r"(addr));
                b[nh * 2][0] = q0;     b[nh * 2][1] = q1;
                b[nh * 2 + 1][0] = q2; b[nh * 2 + 1][1] = q3;
            }
            #pragma unroll
            for (int mt = 0; mt < 4; mt++)
                #pragma unroll
                for (int nt = 0; nt < 4; nt++) {
                    asm volatile(
                        "mma.sync.aligned.m16n8k16.row.col.f32.bf16.bf16.f32 "
                        "{%0,%1,%2,%3}, {%4,%5,%6,%7}, {%8,%9}, {%0,%1,%2,%3};"
                        : "+f"(acc[mt][nt][0]), "+f"(acc[mt][nt][1]),
                          "+f"(acc[mt][nt][2]), "+f"(acc[mt][nt][3])
                        : "r"(a[mt][0]), "r"(a[mt][1]), "r"(a[mt][2]), "r"(a[mt][3]),
                          "r"(b[nt][0]), "r"(b[nt][1]));
                }
        }
    }

    if (MODE == 2) {
        // fused distance epilogue: per-row partial of attn * (acc - 2*QV)
        const float* __restrict__ Q = ba.p[blockIdx.z].Q;
        float* Dz = Df + (size_t)blockIdx.z * (size_t)M * 8;
        #pragma unroll
        for (int mt = 0; mt < 4; mt++) {
            #pragma unroll
            for (int r = 0; r < 2; r++) {
                int m = m0 + wm * 64 + mt * 16 + (lane >> 2) + r * 8;
                float p = 0.f;
                if (m < M) {
                    #pragma unroll
                    for (int nt = 0; nt < 4; nt++) {
                        int nb = n0 + wn * 32 + nt * 8 + (lane & 3) * 2;
                        if (nb < N) {
                            float at0 = __bfloat162float(A[(size_t)m * lda + nb]);
                            p += at0 * (acc[mt][nt][r * 2] - 2.f * Q[(size_t)m * ldc + nb]);
                            if (nb + 1 < N) {
                                float at1 = __bfloat162float(A[(size_t)m * lda + nb + 1]);
                                p += at1 * (acc[mt][nt][r * 2 + 1] - 2.f * Q[(size_t)m * ldc + nb + 1]);
                            }
                        }
                    }
                }
                p += __shfl_xor_sync(0xffffffffu, p, 1);
                p += __shfl_xor_sync(0xffffffffu, p, 2);
                if (m < M && (lane & 3) == 0)
                    Dz[(size_t)m * 8 + blockIdx.x * 4 + wn] = p;
            }
        }
        return;
    }

    #pragma unroll
    for (int mt = 0; mt < 4; mt++) {
        #pragma unroll
        for (int nt = 0; nt < 4; nt++) {
            int mb = m0 + wm * 64 + mt * 16 + (lane >> 2);
            int nb = n0 + wn * 32 + nt * 8 + (lane & 3) * 2;
            if (nb >= N) continue;
            if (MODE == 1) {
                __nv_bfloat16* C = (__nv_bfloat16*)Cv;
                if (mb < M)
                    *(__nv_bfloat162*)(C + (size_t)mb * ldc + nb) =
                        __floats2bfloat162_rn(acc[mt][nt][0], acc[mt][nt][1]);
                if (mb + 8 < M)
                    *(__nv_bfloat162*)(C + (size_t)(mb + 8) * ldc + nb) =
                        __floats2bfloat162_rn(acc[mt][nt][2], acc[mt][nt][3]);
            } else {
                float* C = (float*)Cv;
                if (mb < M)
                    *(float2*)(C + (size_t)mb * ldc + nb) =
                        make_float2(acc[mt][nt][0], acc[mt][nt][1]);
                if (mb + 8 < M)
                    *(float2*)(C + (size_t)(mb + 8) * ldc + nb) =
                        make_float2(acc[mt][nt][2], acc[mt][nt][3]);
            }
        }
    }
}

// ------------------------- block reduction helper -------------------------
__device__ __forceinline__ float block_sum_256(float v, float* sh) {
    int tid = threadIdx.x;
    sh[tid] = v; __syncthreads();
    #pragma unroll
    for (int s = 128; s > 0; s >>= 1) {
        if (tid < s) sh[tid] += sh[tid + s];
        __syncthreads();
    }
    float r = sh[0]; __syncthreads();
    return r;
}

// ------------------------- kernel 3: assemble K (LN) and V rows -----------
__global__ void assemble(const float* __restrict__ k_b, const float* __restrict__ v_b,
                         const float* __restrict__ gamma, const float* __restrict__ beta)
{
    __shared__ float sh[256];
    int r = blockIdx.x;
    int t, fbase;
    if (r < SROWS) { fbase = (r / TLEN) * SEQ;                       t = r % TLEN; }
    else { int qr = r - SROWS; fbase = NS * SEQ + (qr / TLEN) * SEQ; t = qr % TLEN; }
    int fa = fbase + c_TA[t];
    int fb = fbase + c_TB[t];

    const __nv_bfloat16* pa = d_Ph + (size_t)fa * WSTK;
    const __nv_bfloat16* pb = d_Ph + (size_t)fb * WSTK;

    int tid = threadIdx.x;
    bool act = tid < (DOUT / 8);            // 144 active lanes
    int j0 = tid * 8;

    float kv[8], vv[8];
    float s1 = 0.f, s2 = 0.f, vn = 0.f;
    if (act) {
        uint4 ka4 = *(const uint4*)(pa + j0);
        uint4 kb4 = *(const uint4*)(pb + DOUT + j0);
        uint4 va4 = *(const uint4*)(pa + 2 * DOUT + j0);
        uint4 vb4 = *(const uint4*)(pb + 3 * DOUT + j0);
        float4 kbias0 = *(const float4*)(k_b + j0), kbias1 = *(const float4*)(k_b + j0 + 4);
        float4 vbias0 = *(const float4*)(v_b + j0), vbias1 = *(const float4*)(v_b + j0 + 4);
        float kbias[8] = {kbias0.x, kbias0.y, kbias0.z, kbias0.w, kbias1.x, kbias1.y, kbias1.z, kbias1.w};
        float vbias[8] = {vbias0.x, vbias0.y, vbias0.z, vbias0.w, vbias1.x, vbias1.y, vbias1.z, vbias1.w};
        const __nv_bfloat162* hka = (const __nv_bfloat162*)&ka4;
        const __nv_bfloat162* hkb = (const __nv_bfloat162*)&kb4;
        const __nv_bfloat162* hva = (const __nv_bfloat162*)&va4;
        const __nv_bfloat162* hvb = (const __nv_bfloat162*)&vb4;
        #pragma unroll
        for (int i = 0; i < 4; i++) {
            kv[2*i]   = __low2float(hka[i])  + __low2float(hkb[i])  + kbias[2*i];
            kv[2*i+1] = __high2float(hka[i]) + __high2float(hkb[i]) + kbias[2*i+1];
            vv[2*i]   = __low2float(hva[i])  + __low2float(hvb[i])  + vbias[2*i];
            vv[2*i+1] = __high2float(hva[i]) + __high2float(hvb[i]) + vbias[2*i+1];
        }
        #pragma unroll
        for (int i = 0; i < 8; i++) {
            s1 += kv[i]; s2 += kv[i] * kv[i]; vn += vv[i] * vv[i];
        }
        // store V rows (bf16, vectorized)
        __nv_bfloat162 vo[4];
        #pragma unroll
        for (int i = 0; i < 4; i++) vo[i] = __floats2bfloat162_rn(vv[2*i], vv[2*i+1]);
        *(uint4*)(d_VSh + (size_t)r * DOUT + j0) = *(uint4*)vo;
    }
    float S1 = block_sum_256(s1, sh);
    float S2 = block_sum_256(s2, sh);
    float VN = block_sum_256(vn, sh);
    float mu  = S1 / (float)DOUT;
    float var = S2 / (float)DOUT - mu * mu;
    float inv = rsqrtf(var + LN_EPS);
    if (act) {
        float4 g0 = *(const float4*)(gamma + j0), g1 = *(const float4*)(gamma + j0 + 4);
        float4 b0 = *(const float4*)(beta + j0),  b1 = *(const float4*)(beta + j0 + 4);
        float gm[8] = {g0.x, g0.y, g0.z, g0.w, g1.x, g1.y, g1.z, g1.w};
        float bt[8] = {b0.x, b0.y, b0.z, b0.w, b1.x, b1.y, b1.z, b1.w};
        __nv_bfloat162 ko[4];
        #pragma unroll
        for (int i = 0; i < 4; i++)
            ko[i] = __floats2bfloat162_rn((kv[2*i]   - mu) * inv * gm[2*i]   + bt[2*i],
                                          (kv[2*i+1] - mu) * inv * gm[2*i+1] + bt[2*i+1]);
        *(uint4*)(d_KSh + (size_t)r * DOUT + j0) = *(uint4*)ko;
    }
    if (tid == 0) d_VN[r] = VN;
}

// ------------------------- kernel 4: softmax (bf16 out only) --------------
__global__ void softmax_k(float scale) {
    int row  = blockIdx.x;
    int c    = threadIdx.x >> 5;
    int lane = threadIdx.x & 31;
    const float* p = d_QK + (size_t)row * SROWS + c * CLS;
    __nv_bfloat16* pb = d_Ab + (size_t)row * ABLD + c * CPAD;

    float v[5];
    float mx = -1e30f;
    #pragma unroll
    for (int i = 0; i < 5; i++) {
        int j = lane + 32 * i;
        v[i] = (j < CLS) ? p[j] * scale : -1e30f;
        mx = fmaxf(mx, v[i]);
    }
    #pragma unroll
    for (int s = 16; s > 0; s >>= 1) mx = fmaxf(mx, __shfl_xor_sync(0xffffffffu, mx, s));
    float sum = 0.f;
    #pragma unroll
    for (int i = 0; i < 5; i++) {
        int j = lane + 32 * i;
        if (j < CLS) { v[i] = expf(v[i] - mx); sum += v[i]; }
    }
    #pragma unroll
    for (int s = 16; s > 0; s >>= 1) sum += __shfl_xor_sync(0xffffffffu, sum, s);
    float invs = 1.0f / sum;
    #pragma unroll
    for (int i = 0; i < 5; i++) {
        int j = lane + 32 * i;
        if (j < CLS) pb[j] = __float2bfloat16(v[i] * invs);
    }
}

// ------------------------- kernel 5: tiny final reduction -----------------
__global__ void final_k(const float* __restrict__ gt, const float* __restrict__ tw,
                        float* __restrict__ out)
{
    int q = blockIdx.x;
    int c = threadIdx.x >> 5;
    int lane = threadIdx.x & 31;
    float temp = gt[0] * tw[0];

    float tot = 0.f;
    if (lane < TLEN) {
        tot = d_VN[SROWS + q * TLEN + lane];
        const float* dd = d_D2 + ((size_t)c * QROWS + q * TLEN + lane) * 8;
        float4 x = *(const float4*)dd;
        float4 y = *(const float4*)(dd + 4);
        tot += x.x + x.y + x.z + x.w + y.x + y.y + y.z + y.w;
    }
    #pragma unroll
    for (int s = 16; s > 0; s >>= 1) tot += __shfl_xor_sync(0xffffffffu, tot, s);
    if (lane == 0) out[q * WAY + c] = -(tot / (float)TLEN) * temp;
}

// ------------------------- launch -----------------------------------------
extern "C" void kernel_launch(void* const* d_in, const int* in_sizes, int n_in,
                              void* d_out, int out_size) {
    const float* sup   = (const float*)d_in[0];
    const float* qry   = (const float*)d_in[2];
    const float* k_w   = (const float*)d_in[3];
    const float* k_b   = (const float*)d_in[4];
    const float* v_w   = (const float*)d_in[5];
    const float* v_b   = (const float*)d_in[6];
    const float* gamma = (const float*)d_in[7];
    const float* beta  = (const float*)d_in[8];
    const float* gt    = (const float*)d_in[9];
    const float* tw    = (const float*)d_in[10];
    float* out = (float*)d_out;

    __nv_bfloat16 *pXh, *pWT, *pPh, *pKSh, *pVSh, *pAb, *pSSh;
    float *pQK, *pQV, *pD2;
    cudaGetSymbolAddress((void**)&pXh,  d_Xh);
    cudaGetSymbolAddress((void**)&pWT,  d_WT);
    cudaGetSymbolAddress((void**)&pPh,  d_Ph);
    cudaGetSymbolAddress((void**)&pKSh, d_KSh);
    cudaGetSymbolAddress((void**)&pVSh, d_VSh);
    cudaGetSymbolAddress((void**)&pQK,  d_QK);
    cudaGetSymbolAddress((void**)&pQV,  d_QV);
    cudaGetSymbolAddress((void**)&pD2,  d_D2);
    cudaGetSymbolAddress((void**)&pAb,  d_Ab);
    cudaGetSymbolAddress((void**)&pSSh, d_SSh);

    cudaFuncSetAttribute(mgemm<0>, cudaFuncAttributeMaxDynamicSharedMemorySize, MG_SMEM);
    cudaFuncSetAttribute(mgemm<1>, cudaFuncAttributeMaxDynamicSharedMemorySize, MG_SMEM);
    cudaFuncSetAttribute(mgemm<2>, cudaFuncAttributeMaxDynamicSharedMemorySize, MG_SMEM);

    pe_kernel<<<(SEQ * FEAT + 255) / 256, 256>>>();
    build_x<<<(NFRAMES * FEAT / 8 + 255) / 256, 256>>>(sup, qry);
    wtrans<<<dim3(DOUT / 32, FEAT / 32, 4), dim3(32, 8)>>>(k_w, v_w);

    // Projections (bf16 out): Ph[4200, 4608] = Xh @ WT^T
    {
        BatchArg ba = {};
        ba.p[0] = { pXh, pWT, (void*)pPh, nullptr };
        dim3 g((WSTK + 127) / 128, (NFRAMES + 127) / 128, 1);
        mgemm<1><<<g, 256, MG_SMEM>>>(ba, NFRAMES, WSTK, FEAT, FEAT, FEAT, WSTK, nullptr);
    }

    assemble<<<NROWS, 256>>>(k_b, v_b, gamma, beta);

    // QK and QV in one batched launch (z=2)
    {
        BatchArg ba = {};
        ba.p[0] = { pKSh + (size_t)SROWS * DOUT, pKSh, (void*)pQK, nullptr };
        ba.p[1] = { pVSh + (size_t)SROWS * DOUT, pVSh, (void*)pQV, nullptr };
        dim3 g((SROWS + 127) / 128, (QROWS + 127) / 128, 2);
        mgemm<0><<<g, 256, MG_SMEM>>>(ba, QROWS, SROWS, DOUT, DOUT, DOUT, SROWS, nullptr);
    }

    // Per-class Gram blocks (z=5), bf16 out, ldc=144
    {
        BatchArg ba = {};
        for (int c = 0; c < WAY; c++)
            ba.p[c] = { pVSh + (size_t)c * CLS * DOUT,
                        pVSh + (size_t)c * CLS * DOUT,
                        (void*)(pSSh + (size_t)c * CLS * CPAD), nullptr };
        dim3 g((CLS + 127) / 128, (CLS + 127) / 128, WAY);
        mgemm<1><<<g, 256, MG_SMEM>>>(ba, CLS, CLS, DOUT, DOUT, DOUT, CPAD, nullptr);
    }

    softmax_k<<<QROWS, 160>>>(1.0f / sqrtf((float)DOUT));

    // Fused H + distance partials (z=5): D2[c][m][slot] = sum_n attn*(H - 2*QV)
    {
        BatchArg ba = {};
        for (int c = 0; c < WAY; c++)
            ba.p[c] = { pAb + (size_t)c * CPAD,
                        pSSh + (size_t)c * CLS * CPAD,
                        nullptr,
                        pQV + (size_t)c * CLS };
        dim3 g((CLS + 127) / 128, (QROWS + 127) / 128, WAY);
        mgemm<2><<<g, 256, MG_SMEM>>>(ba, QROWS, CLS, CLS, ABLD, CPAD, SROWS, pD2);
    }

    final_k<<<NQ, 160>>>(gt, tw, out);
}

// round 6
// speedup vs baseline: 6.9186x; 1.0701x over previous
#include <cuda_runtime.h>
#include <cuda_bf16.h>
#include <math.h>
#include <stdint.h>

#define SEQ 8
#define FEAT 2048
#define TLEN 28
#define DOUT 1152
#define WAY 5
#define SHOT 5
#define NQ 500
#define NS 25
#define NFRAMES ((NS + NQ) * SEQ)      /* 4200 */
#define NROWS ((NS + NQ) * TLEN)       /* 14700 */
#define SROWS (NS * TLEN)              /* 700 */
#define QROWS (NQ * TLEN)              /* 14000 */
#define CLS 140                        /* SHOT*TLEN */
#define LN_EPS 1e-5f
#define WSTK (4 * DOUT)                /* 4608 */
#define ABLD 720                       /* bf16 attn row stride (5*144) */
#define CPAD 144                       /* padded class block stride */

// ------------------------- scratch (device globals) -----------------------
__device__ float          d_PE [SEQ * FEAT];
__device__ __nv_bfloat16  d_Xh [NFRAMES * FEAT];
__device__ __nv_bfloat16  d_WT [WSTK * FEAT];
__device__ __nv_bfloat16  d_Ph [NFRAMES * WSTK];
__device__ __nv_bfloat16  d_KSh[NROWS * DOUT];
__device__ __nv_bfloat16  d_VSh[NROWS * DOUT];
__device__ float          d_VN [NROWS];
__device__ float          d_QK [QROWS * SROWS];           // raw scores (fp32)
__device__ __nv_bfloat16  d_Ab [QROWS * ABLD];            // attn bf16, padded blocks
__device__ float          d_QV [QROWS * SROWS];
__device__ float          d_D2 [WAY * QROWS * 8];         // fused distance partials
__device__ __nv_bfloat16  d_SSh[WAY * CLS * CPAD];

__constant__ int c_TA[TLEN] = {0,0,0,0,0,0,0,1,1,1,1,1,1,2,2,2,2,2,3,3,3,3,4,4,4,5,5,6};
__constant__ int c_TB[TLEN] = {1,2,3,4,5,6,7,2,3,4,5,6,7,3,4,5,6,7,4,5,6,7,5,6,7,6,7,7};

__device__ __forceinline__ uint32_t smem_u32(const void* p) {
    uint32_t a;
    asm("{ .reg .u64 t; cvta.to.shared.u64 t, %1; cvt.u32.u64 %0, t; }" : "=r"(a) : "l"(p));
    return a;
}

// ------------------------- kernel 0: positional encoding ------------------
__global__ void pe_kernel() {
    int idx = blockIdx.x * blockDim.x + threadIdx.x;
    if (idx >= SEQ * FEAT) return;
    int pos = idx / FEAT, d = idx % FEAT;
    float coef = -logf(10000.0f) / (float)FEAT;
    float div  = expf((float)(d & ~1) * coef);
    float ang  = (float)pos * div;
    d_PE[idx]  = (d & 1) ? cosf(ang) : sinf(ang);
}

// ------------------------- kernel 1: gather frames + PE -> bf16 -----------
__global__ void build_x(const float* __restrict__ sup, const float* __restrict__ qry) {
    long e = ((long)blockIdx.x * blockDim.x + threadIdx.x) * 8;
    if (e >= (long)NFRAMES * FEAT) return;
    int f = (int)(e / FEAT);
    int d = (int)(e % FEAT);
    int frame = f % SEQ;
    const float* src = (f < NS * SEQ) ? (sup + (long)f * FEAT + d)
                                      : (qry + (long)(f - NS * SEQ) * FEAT + d);
    float4 a = *(const float4*)src;
    float4 b = *(const float4*)(src + 4);
    const float* pe = d_PE + frame * FEAT + d;
    float4 pa = *(const float4*)pe;
    float4 pb = *(const float4*)(pe + 4);
    __nv_bfloat162 h[4];
    h[0] = __floats2bfloat162_rn(a.x + pa.x, a.y + pa.y);
    h[1] = __floats2bfloat162_rn(a.z + pa.z, a.w + pa.w);
    h[2] = __floats2bfloat162_rn(b.x + pb.x, b.y + pb.y);
    h[3] = __floats2bfloat162_rn(b.z + pb.z, b.w + pb.w);
    *(uint4*)(d_Xh + e) = *(uint4*)h;
}

// ------------------------- kernel 2: weight transpose -> bf16 -------------
__global__ void wtrans(const float* __restrict__ kw, const float* __restrict__ vw) {
    __shared__ float t[32][33];
    int p  = blockIdx.z;
    int n0 = blockIdx.x * 32, k0 = blockIdx.y * 32;
    const float* W = ((p < 2) ? kw : vw) + (size_t)((p & 1) * FEAT) * DOUT;
    #pragma unroll
    for (int i = 0; i < 4; i++) {
        int k = k0 + threadIdx.y + i * 8;
        t[threadIdx.y + i * 8][threadIdx.x] = W[(size_t)k * DOUT + n0 + threadIdx.x];
    }
    __syncthreads();
    #pragma unroll
    for (int i = 0; i < 4; i++) {
        int n = n0 + threadIdx.y + i * 8;
        d_WT[(size_t)(p * DOUT + n) * FEAT + k0 + threadIdx.x] =
            __float2bfloat16(t[threadIdx.x][threadIdx.y + i * 8]);
    }
}

// ------------------------- bf16 mma.sync NT GEMM (batched, BK=64) ---------
// MODE 0: fp32 C out.  MODE 1: bf16 C out.  MODE 2: fused distance epilogue.
#define MG_STRIDE 72                            /* halves; 144B rows (odd 16B units) */
#define MG_STAGE_B (128 * MG_STRIDE * 2)        /* 18432 bytes per operand           */
#define MG_SMEM (3 * 2 * MG_STAGE_B)            /* 110592 bytes                      */

struct BPtr { const __nv_bfloat16* A; const __nv_bfloat16* B; void* C; const float* Q; };
struct BatchArg { BPtr p[5]; };

__device__ __forceinline__ void cp16(uint32_t dst, const void* src, int sz) {
    asm volatile("cp.async.cg.shared.global [%0], [%1], 16, %2;"
                 :: "r"(dst), "l"(src), "r"(sz) : "memory");
}

template<int MODE>
__global__ void __launch_bounds__(256, 2) mgemm(BatchArg ba,
                                                int M, int N, int K,
                                                int lda, int ldb, int ldc,
                                                float* __restrict__ Df)
{
    extern __shared__ __align__(16) char smem[];
    const uint32_t sbase = smem_u32(smem);
    const int tid  = threadIdx.x;
    const int wid  = tid >> 5, lane = tid & 31;
    const int wm   = wid >> 2, wn = wid & 3;
    const int m0   = blockIdx.y * 128, n0 = blockIdx.x * 128;
    const int nk   = (K + 63) >> 6;

    const __nv_bfloat16* __restrict__ A = ba.p[blockIdx.z].A;
    const __nv_bfloat16* __restrict__ B = ba.p[blockIdx.z].B;
    void* __restrict__ Cv = ba.p[blockIdx.z].C;

    float acc[4][4][4];
    #pragma unroll
    for (int i = 0; i < 4; i++)
        #pragma unroll
        for (int j = 0; j < 4; j++)
            #pragma unroll
            for (int r = 0; r < 4; r++) acc[i][j][r] = 0.f;

    // ---- hoisted load setup: ch = 16B chunk (0..7), r0 = row (0..31) ----
    const int ch = tid & 7;
    const int r0 = tid >> 3;
    bool vA[4], vB[4];
    const __nv_bfloat16 *pA[4], *pB[4];
    uint32_t dA[4], dB[4];
    #pragma unroll
    for (int g = 0; g < 4; g++) {
        int row = r0 + 32 * g;
        vA[g] = (m0 + row) < M;
        vB[g] = (n0 + row) < N;
        pA[g] = A + (size_t)(vA[g] ? m0 + row : 0) * lda + ch * 8;
        pB[g] = B + (size_t)(vB[g] ? n0 + row : 0) * ldb + ch * 8;
        dA[g] = (uint32_t)(row * (MG_STRIDE * 2) + ch * 16);
        dB[g] = dA[g] + MG_STAGE_B;
    }

    auto load_stage = [&](int sidx, int kc) {
        const int k0 = kc * 64;
        const uint32_t st = sbase + sidx * (2 * MG_STAGE_B);
        int szk;
        if (k0 + 64 <= K) szk = 16;
        else {
            int ke  = k0 + ch * 8;
            int rem = (K - ke) * 2;
            szk = rem >= 16 ? 16 : (rem > 0 ? rem : 0);
        }
        #pragma unroll
        for (int g = 0; g < 4; g++) {
            cp16(st + dA[g], pA[g] + k0, vA[g] ? szk : 0);
            cp16(st + dB[g], pB[g] + k0, vB[g] ? szk : 0);
        }
        asm volatile("cp.async.commit_group;" ::: "memory");
    };

    // ---- hoisted fragment smem offsets ----
    uint32_t offA[4], offB[2];
    #pragma unroll
    for (int mt = 0; mt < 4; mt++)
        offA[mt] = (uint32_t)(((wm * 64 + mt * 16 + (lane & 15)) * MG_STRIDE
                               + (lane >> 4) * 8) * 2);
    #pragma unroll
    for (int nh = 0; nh < 2; nh++) {
        int nrow = nh * 16 + ((lane >> 4) * 8) + (lane & 7);
        int kof  = ((lane >> 3) & 1) * 8;
        offB[nh] = (uint32_t)(((wn * 32 + nrow) * MG_STRIDE + kof) * 2) + MG_STAGE_B;
    }

    const int pst = nk < 2 ? nk : 2;
    for (int s = 0; s < pst; s++) load_stage(s, s);

    for (int i = 0; i < nk; i++) {
        if (i + 1 < nk) asm volatile("cp.async.wait_group 1;" ::: "memory");
        else            asm volatile("cp.async.wait_group 0;" ::: "memory");
        __syncthreads();

        if (i + 2 < nk) load_stage((i + 2) % 3, i + 2);

        const uint32_t stg = sbase + (i % 3) * (2 * MG_STAGE_B);

        #pragma unroll
        for (int ks = 0; ks < 4; ks++) {
            uint32_t a[4][4], b[4][2];
            #pragma unroll
            for (int mt = 0; mt < 4; mt++) {
                uint32_t addr = stg + offA[mt] + ks * 32;
                asm volatile("ldmatrix.sync.aligned.m8n8.x4.shared.b16 {%0,%1,%2,%3}, [%4];"
                             : "=r"(a[mt][0]), "=r"(a[mt][1]), "=r"(a[mt][2]), "=r"(a[mt][3])
                             : "r"(addr));
            }
            #pragma unroll
            for (int nh = 0; nh < 2; nh++) {
                uint32_t addr = stg + offB[nh] + ks * 32;
                uint32_t q0, q1, q2, q3;
                asm volatile("ldmatrix.sync.aligned.m8n8.x4.shared.b16 {%0,%1,%2,%3}, [%4];"
                             : "=r"(q0), "=r"(q1), "=r"(q2), "=r"(q3) : "r"(addr));
                b[nh * 2][0] = q0;     b[nh * 2][1] = q1;
                b[nh * 2 + 1][0] = q2; b[nh * 2 + 1][1] = q3;
            }
            #pragma unroll
            for (int mt = 0; mt < 4; mt++)
                #pragma unroll
                for (int nt = 0; nt < 4; nt++) {
                    asm volatile(
                        "mma.sync.aligned.m16n8k16.row.col.f32.bf16.bf16.f32 "
                        "{%0,%1,%2,%3}, {%4,%5,%6,%7}, {%8,%9}, {%0,%1,%2,%3};"
                        : "+f"(acc[mt][nt][0]), "+f"(acc[mt][nt][1]),
                          "+f"(acc[mt][nt][2]), "+f"(acc[mt][nt][3])
                        : "r"(a[mt][0]), "r"(a[mt][1]), "r"(a[mt][2]), "r"(a[mt][3]),
                          "r"(b[nt][0]), "r"(b[nt][1]));
                }
        }
    }

    if (MODE == 2) {
        const float* __restrict__ Q = ba.p[blockIdx.z].Q;
        float* Dz = Df + (size_t)blockIdx.z * (size_t)M * 8;
        #pragma unroll
        for (int mt = 0; mt < 4; mt++) {
            #pragma unroll
            for (int r = 0; r < 2; r++) {
                int m = m0 + wm * 64 + mt * 16 + (lane >> 2) + r * 8;
                float p = 0.f;
                if (m < M) {
                    #pragma unroll
                    for (int nt = 0; nt < 4; nt++) {
                        int nb = n0 + wn * 32 + nt * 8 + (lane & 3) * 2;
                        if (nb < N) {
                            float at0 = __bfloat162float(A[(size_t)m * lda + nb]);
                            p += at0 * (acc[mt][nt][r * 2] - 2.f * Q[(size_t)m * ldc + nb]);
                            if (nb + 1 < N) {
                                float at1 = __bfloat162float(A[(size_t)m * lda + nb + 1]);
                                p += at1 * (acc[mt][nt][r * 2 + 1] - 2.f * Q[(size_t)m * ldc + nb + 1]);
                            }
                        }
                    }
                }
                p += __shfl_xor_sync(0xffffffffu, p, 1);
                p += __shfl_xor_sync(0xffffffffu, p, 2);
                if (m < M && (lane & 3) == 0)
                    Dz[(size_t)m * 8 + blockIdx.x * 4 + wn] = p;
            }
        }
        return;
    }

    #pragma unroll
    for (int mt = 0; mt < 4; mt++) {
        #pragma unroll
        for (int nt = 0; nt < 4; nt++) {
            int mb = m0 + wm * 64 + mt * 16 + (lane >> 2);
            int nb = n0 + wn * 32 + nt * 8 + (lane & 3) * 2;
            if (nb >= N) continue;
            if (MODE == 1) {
                __nv_bfloat16* C = (__nv_bfloat16*)Cv;
                if (mb < M)
                    *(__nv_bfloat162*)(C + (size_t)mb * ldc + nb) =
                        __floats2bfloat162_rn(acc[mt][nt][0], acc[mt][nt][1]);
                if (mb + 8 < M)
                    *(__nv_bfloat162*)(C + (size_t)(mb + 8) * ldc + nb) =
                        __floats2bfloat162_rn(acc[mt][nt][2], acc[mt][nt][3]);
            } else {
                float* C = (float*)Cv;
                if (mb < M)
                    *(float2*)(C + (size_t)mb * ldc + nb) =
                        make_float2(acc[mt][nt][0], acc[mt][nt][1]);
                if (mb + 8 < M)
                    *(float2*)(C + (size_t)(mb + 8) * ldc + nb) =
                        make_float2(acc[mt][nt][2], acc[mt][nt][3]);
            }
        }
    }
}

// ------------------------- block reduction helper -------------------------
__device__ __forceinline__ float block_sum_256(float v, float* sh) {
    int tid = threadIdx.x;
    sh[tid] = v; __syncthreads();
    #pragma unroll
    for (int s = 128; s > 0; s >>= 1) {
        if (tid < s) sh[tid] += sh[tid + s];
        __syncthreads();
    }
    float r = sh[0]; __syncthreads();
    return r;
}

// ------------------------- kernel 3: assemble K (LN) and V rows -----------
__global__ void assemble(const float* __restrict__ k_b, const float* __restrict__ v_b,
                         const float* __restrict__ gamma, const float* __restrict__ beta)
{
    __shared__ float sh[256];
    int r = blockIdx.x;
    int t, fbase;
    if (r < SROWS) { fbase = (r / TLEN) * SEQ;                       t = r % TLEN; }
    else { int qr = r - SROWS; fbase = NS * SEQ + (qr / TLEN) * SEQ; t = qr % TLEN; }
    int fa = fbase + c_TA[t];
    int fb = fbase + c_TB[t];

    const __nv_bfloat16* pa = d_Ph + (size_t)fa * WSTK;
    const __nv_bfloat16* pb = d_Ph + (size_t)fb * WSTK;

    int tid = threadIdx.x;
    bool act = tid < (DOUT / 8);
    int j0 = tid * 8;

    float kv[8], vv[8];
    float s1 = 0.f, s2 = 0.f, vn = 0.f;
    if (act) {
        uint4 ka4 = *(const uint4*)(pa + j0);
        uint4 kb4 = *(const uint4*)(pb + DOUT + j0);
        uint4 va4 = *(const uint4*)(pa + 2 * DOUT + j0);
        uint4 vb4 = *(const uint4*)(pb + 3 * DOUT + j0);
        float4 kbias0 = *(const float4*)(k_b + j0), kbias1 = *(const float4*)(k_b + j0 + 4);
        float4 vbias0 = *(const float4*)(v_b + j0), vbias1 = *(const float4*)(v_b + j0 + 4);
        float kbias[8] = {kbias0.x, kbias0.y, kbias0.z, kbias0.w, kbias1.x, kbias1.y, kbias1.z, kbias1.w};
        float vbias[8] = {vbias0.x, vbias0.y, vbias0.z, vbias0.w, vbias1.x, vbias1.y, vbias1.z, vbias1.w};
        const __nv_bfloat162* hka = (const __nv_bfloat162*)&ka4;
        const __nv_bfloat162* hkb = (const __nv_bfloat162*)&kb4;
        const __nv_bfloat162* hva = (const __nv_bfloat162*)&va4;
        const __nv_bfloat162* hvb = (const __nv_bfloat162*)&vb4;
        #pragma unroll
        for (int i = 0; i < 4; i++) {
            kv[2*i]   = __low2float(hka[i])  + __low2float(hkb[i])  + kbias[2*i];
            kv[2*i+1] = __high2float(hka[i]) + __high2float(hkb[i]) + kbias[2*i+1];
            vv[2*i]   = __low2float(hva[i])  + __low2float(hvb[i])  + vbias[2*i];
            vv[2*i+1] = __high2float(hva[i]) + __high2float(hvb[i]) + vbias[2*i+1];
        }
        #pragma unroll
        for (int i = 0; i < 8; i++) {
            s1 += kv[i]; s2 += kv[i] * kv[i]; vn += vv[i] * vv[i];
        }
        __nv_bfloat162 vo[4];
        #pragma unroll
        for (int i = 0; i < 4; i++) vo[i] = __floats2bfloat162_rn(vv[2*i], vv[2*i+1]);
        *(uint4*)(d_VSh + (size_t)r * DOUT + j0) = *(uint4*)vo;
    }
    float S1 = block_sum_256(s1, sh);
    float S2 = block_sum_256(s2, sh);
    float VN = block_sum_256(vn, sh);
    float mu  = S1 / (float)DOUT;
    float var = S2 / (float)DOUT - mu * mu;
    float inv = rsqrtf(var + LN_EPS);
    if (act) {
        float4 g0 = *(const float4*)(gamma + j0), g1 = *(const float4*)(gamma + j0 + 4);
        float4 b0 = *(const float4*)(beta + j0),  b1 = *(const float4*)(beta + j0 + 4);
        float gm[8] = {g0.x, g0.y, g0.z, g0.w, g1.x, g1.y, g1.z, g1.w};
        float bt[8] = {b0.x, b0.y, b0.z, b0.w, b1.x, b1.y, b1.z, b1.w};
        __nv_bfloat162 ko[4];
        #pragma unroll
        for (int i = 0; i < 4; i++)
            ko[i] = __floats2bfloat162_rn((kv[2*i]   - mu) * inv * gm[2*i]   + bt[2*i],
                                          (kv[2*i+1] - mu) * inv * gm[2*i+1] + bt[2*i+1]);
        *(uint4*)(d_KSh + (size_t)r * DOUT + j0) = *(uint4*)ko;
    }
    if (tid == 0) d_VN[r] = VN;
}

// ------------------------- kernel 4: softmax (bf16 out only) --------------
__global__ void softmax_k(float scale) {
    int row  = blockIdx.x;
    int c    = threadIdx.x >> 5;
    int lane = threadIdx.x & 31;
    const float* p = d_QK + (size_t)row * SROWS + c * CLS;
    __nv_bfloat16* pb = d_Ab + (size_t)row * ABLD + c * CPAD;

    float v[5];
    float mx = -1e30f;
    #pragma unroll
    for (int i = 0; i < 5; i++) {
        int j = lane + 32 * i;
        v[i] = (j < CLS) ? p[j] * scale : -1e30f;
        mx = fmaxf(mx, v[i]);
    }
    #pragma unroll
    for (int s = 16; s > 0; s >>= 1) mx = fmaxf(mx, __shfl_xor_sync(0xffffffffu, mx, s));
    float sum = 0.f;
    #pragma unroll
    for (int i = 0; i < 5; i++) {
        int j = lane + 32 * i;
        if (j < CLS) { v[i] = expf(v[i] - mx); sum += v[i]; }
    }
    #pragma unroll
    for (int s = 16; s > 0; s >>= 1) sum += __shfl_xor_sync(0xffffffffu, sum, s);
    float invs = 1.0f / sum;
    #pragma unroll
    for (int i = 0; i < 5; i++) {
        int j = lane + 32 * i;
        if (j < CLS) pb[j] = __float2bfloat16(v[i] * invs);
    }
}

// ------------------------- kernel 5: tiny final reduction -----------------
__global__ void final_k(const float* __restrict__ gt, const float* __restrict__ tw,
                        float* __restrict__ out)
{
    int q = blockIdx.x;
    int c = threadIdx.x >> 5;
    int lane = threadIdx.x & 31;
    float temp = gt[0] * tw[0];

    float tot = 0.f;
    if (lane < TLEN) {
        tot = d_VN[SROWS + q * TLEN + lane];
        const float* dd = d_D2 + ((size_t)c * QROWS + q * TLEN + lane) * 8;
        float4 x = *(const float4*)dd;
        float4 y = *(const float4*)(dd + 4);
        tot += x.x + x.y + x.z + x.w + y.x + y.y + y.z + y.w;
    }
    #pragma unroll
    for (int s = 16; s > 0; s >>= 1) tot += __shfl_xor_sync(0xffffffffu, tot, s);
    if (lane == 0) out[q * WAY + c] = -(tot / (float)TLEN) * temp;
}

// ------------------------- launch -----------------------------------------
extern "C" void kernel_launch(void* const* d_in, const int* in_sizes, int n_in,
                              void* d_out, int out_size) {
    const float* sup   = (const float*)d_in[0];
    const float* qry   = (const float*)d_in[2];
    const float* k_w   = (const float*)d_in[3];
    const float* k_b   = (const float*)d_in[4];
    const float* v_w   = (const float*)d_in[5];
    const float* v_b   = (const float*)d_in[6];
    const float* gamma = (const float*)d_in[7];
    const float* beta  = (const float*)d_in[8];
    const float* gt    = (const float*)d_in[9];
    const float* tw    = (const float*)d_in[10];
    float* out = (float*)d_out;

    __nv_bfloat16 *pXh, *pWT, *pPh, *pKSh, *pVSh, *pAb, *pSSh;
    float *pQK, *pQV, *pD2;
    cudaGetSymbolAddress((void**)&pXh,  d_Xh);
    cudaGetSymbolAddress((void**)&pWT,  d_WT);
    cudaGetSymbolAddress((void**)&pPh,  d_Ph);
    cudaGetSymbolAddress((void**)&pKSh, d_KSh);
    cudaGetSymbolAddress((void**)&pVSh, d_VSh);
    cudaGetSymbolAddress((void**)&pQK,  d_QK);
    cudaGetSymbolAddress((void**)&pQV,  d_QV);
    cudaGetSymbolAddress((void**)&pD2,  d_D2);
    cudaGetSymbolAddress((void**)&pAb,  d_Ab);
    cudaGetSymbolAddress((void**)&pSSh, d_SSh);

    cudaFuncSetAttribute(mgemm<0>, cudaFuncAttributeMaxDynamicSharedMemorySize, MG_SMEM);
    cudaFuncSetAttribute(mgemm<1>, cudaFuncAttributeMaxDynamicSharedMemorySize, MG_SMEM);
    cudaFuncSetAttribute(mgemm<2>, cudaFuncAttributeMaxDynamicSharedMemorySize, MG_SMEM);

    pe_kernel<<<(SEQ * FEAT + 255) / 256, 256>>>();
    build_x<<<(NFRAMES * FEAT / 8 + 255) / 256, 256>>>(sup, qry);
    wtrans<<<dim3(DOUT / 32, FEAT / 32, 4), dim3(32, 8)>>>(k_w, v_w);

    // Projections (bf16 out): Ph[4200, 4608] = Xh @ WT^T
    {
        BatchArg ba = {};
        ba.p[0] = { pXh, pWT, (void*)pPh, nullptr };
        dim3 g((WSTK + 127) / 128, (NFRAMES + 127) / 128, 1);
        mgemm<1><<<g, 256, MG_SMEM>>>(ba, NFRAMES, WSTK, FEAT, FEAT, FEAT, WSTK, nullptr);
    }

    assemble<<<NROWS, 256>>>(k_b, v_b, gamma, beta);

    // QK and QV in one batched launch (z=2)
    {
        BatchArg ba = {};
        ba.p[0] = { pKSh + (size_t)SROWS * DOUT, pKSh, (void*)pQK, nullptr };
        ba.p[1] = { pVSh + (size_t)SROWS * DOUT, pVSh, (void*)pQV, nullptr };
        dim3 g((SROWS + 127) / 128, (QROWS + 127) / 128, 2);
        mgemm<0><<<g, 256, MG_SMEM>>>(ba, QROWS, SROWS, DOUT, DOUT, DOUT, SROWS, nullptr);
    }

    // Per-class Gram blocks (z=5), bf16 out, ldc=144
    {
        BatchArg ba = {};
        for (int c = 0; c < WAY; c++)
            ba.p[c] = { pVSh + (size_t)c * CLS * DOUT,
                        pVSh + (size_t)c * CLS * DOUT,
                        (void*)(pSSh + (size_t)c * CLS * CPAD), nullptr };
        dim3 g((CLS + 127) / 128, (CLS + 127) / 128, WAY);
        mgemm<1><<<g, 256, MG_SMEM>>>(ba, CLS, CLS, DOUT, DOUT, DOUT, CPAD, nullptr);
    }

    softmax_k<<<QROWS, 160>>>(1.0f / sqrtf((float)DOUT));

    // Fused H + distance partials (z=5)
    {
        BatchArg ba = {};
        for (int c = 0; c < WAY; c++)
            ba.p[c] = { pAb + (size_t)c * CPAD,
                        pSSh + (size_t)c * CLS * CPAD,
                        nullptr,
                        pQV + (size_t)c * CLS };
        dim3 g((CLS + 127) / 128, (QROWS + 127) / 128, WAY);
        mgemm<2><<<g, 256, MG_SMEM>>>(ba, QROWS, CLS, CLS, ABLD, CPAD, SROWS, pD2);
    }

    final_k<<<NQ, 160>>>(gt, tw, out);
}

// round 7
// speedup vs baseline: 7.2178x; 1.0432x over previous
#include <cuda_runtime.h>
#include <cuda_bf16.h>
#include <math.h>
#include <stdint.h>

#define SEQ 8
#define FEAT 2048
#define TLEN 28
#define DOUT 1152
#define WAY 5
#define SHOT 5
#define NQ 500
#define NS 25
#define NFRAMES ((NS + NQ) * SEQ)      /* 4200 */
#define NROWS ((NS + NQ) * TLEN)       /* 14700 */
#define SROWS (NS * TLEN)              /* 700 */
#define QROWS (NQ * TLEN)              /* 14000 */
#define CLS 140                        /* SHOT*TLEN */
#define LN_EPS 1e-5f
#define WSTK (4 * DOUT)                /* 4608 */
#define ABLD 720                       /* bf16 attn row stride (5*144) */
#define CPAD 144                       /* padded class block stride */
#define QYT 110                        /* QROWS m-tiles */

// ------------------------- scratch (device globals) -----------------------
__device__ float          d_PE [SEQ * FEAT];
__device__ __nv_bfloat16  d_Xh [NFRAMES * FEAT];
__device__ __nv_bfloat16  d_WT [WSTK * FEAT];
__device__ __nv_bfloat16  d_Ph [NFRAMES * WSTK];
__device__ __nv_bfloat16  d_KSh[NROWS * DOUT];
__device__ __nv_bfloat16  d_VSh[NROWS * DOUT];
__device__ float          d_VN [NROWS];
__device__ float          d_QK [QROWS * SROWS];           // raw scores (fp32)
__device__ __nv_bfloat16  d_Ab [QROWS * ABLD];            // attn bf16, padded blocks
__device__ float          d_QV [QROWS * SROWS];
__device__ float          d_D2 [WAY * QROWS * 8];         // fused distance partials
__device__ __nv_bfloat16  d_SSh[WAY * CLS * CPAD];

__constant__ int c_TA[TLEN] = {0,0,0,0,0,0,0,1,1,1,1,1,1,2,2,2,2,2,3,3,3,3,4,4,4,5,5,6};
__constant__ int c_TB[TLEN] = {1,2,3,4,5,6,7,2,3,4,5,6,7,3,4,5,6,7,4,5,6,7,5,6,7,6,7,7};

__device__ __forceinline__ uint32_t smem_u32(const void* p) {
    uint32_t a;
    asm("{ .reg .u64 t; cvta.to.shared.u64 t, %1; cvt.u32.u64 %0, t; }" : "=r"(a) : "l"(p));
    return a;
}

// ------------------------- kernel 0: positional encoding ------------------
__global__ void pe_kernel() {
    int idx = blockIdx.x * blockDim.x + threadIdx.x;
    if (idx >= SEQ * FEAT) return;
    int pos = idx / FEAT, d = idx % FEAT;
    float coef = -logf(10000.0f) / (float)FEAT;
    float div  = expf((float)(d & ~1) * coef);
    float ang  = (float)pos * div;
    d_PE[idx]  = (d & 1) ? cosf(ang) : sinf(ang);
}

// ------------------------- kernel 1: gather frames + PE -> bf16 -----------
__global__ void build_x(const float* __restrict__ sup, const float* __restrict__ qry) {
    long e = ((long)blockIdx.x * blockDim.x + threadIdx.x) * 8;
    if (e >= (long)NFRAMES * FEAT) return;
    int f = (int)(e / FEAT);
    int d = (int)(e % FEAT);
    int frame = f % SEQ;
    const float* src = (f < NS * SEQ) ? (sup + (long)f * FEAT + d)
                                      : (qry + (long)(f - NS * SEQ) * FEAT + d);
    float4 a = *(const float4*)src;
    float4 b = *(const float4*)(src + 4);
    const float* pe = d_PE + frame * FEAT + d;
    float4 pa = *(const float4*)pe;
    float4 pb = *(const float4*)(pe + 4);
    __nv_bfloat162 h[4];
    h[0] = __floats2bfloat162_rn(a.x + pa.x, a.y + pa.y);
    h[1] = __floats2bfloat162_rn(a.z + pa.z, a.w + pa.w);
    h[2] = __floats2bfloat162_rn(b.x + pb.x, b.y + pb.y);
    h[3] = __floats2bfloat162_rn(b.z + pb.z, b.w + pb.w);
    *(uint4*)(d_Xh + e) = *(uint4*)h;
}

// ------------------------- kernel 2: weight transpose -> bf16 -------------
__global__ void wtrans(const float* __restrict__ kw, const float* __restrict__ vw) {
    __shared__ float t[32][33];
    int p  = blockIdx.z;
    int n0 = blockIdx.x * 32, k0 = blockIdx.y * 32;
    const float* W = ((p < 2) ? kw : vw) + (size_t)((p & 1) * FEAT) * DOUT;
    #pragma unroll
    for (int i = 0; i < 4; i++) {
        int k = k0 + threadIdx.y + i * 8;
        t[threadIdx.y + i * 8][threadIdx.x] = W[(size_t)k * DOUT + n0 + threadIdx.x];
    }
    __syncthreads();
    #pragma unroll
    for (int i = 0; i < 4; i++) {
        int n = n0 + threadIdx.y + i * 8;
        d_WT[(size_t)(p * DOUT + n) * FEAT + k0 + threadIdx.x] =
            __float2bfloat16(t[threadIdx.x][threadIdx.y + i * 8]);
    }
}

// ------------------------- bf16 mma.sync NT GEMM (batched, BK=64) ---------
// MODE 1: bf16 C out (geometry from args).
// MODE 2: fused distance epilogue (H GEMM; A is attn).
// MODE 3: merged QK/QV/SS launch, grid (6, 112, 2); per-CTA geometry.
#define MG_STRIDE 72                            /* halves; 144B rows */
#define MG_STAGE_B (128 * MG_STRIDE * 2)        /* 18432 bytes per operand */
#define MG_SMEM (3 * 2 * MG_STAGE_B)            /* 110592 bytes */

struct BPtr { const __nv_bfloat16* A; const __nv_bfloat16* B; void* C; const float* Q; };
struct BatchArg { BPtr p[5]; };

__device__ __forceinline__ void cp16(uint32_t dst, const void* src, int sz) {
    asm volatile("cp.async.cg.shared.global [%0], [%1], 16, %2;"
                 :: "r"(dst), "l"(src), "r"(sz) : "memory");
}

template<int MODE>
__global__ void __launch_bounds__(256, 2) mgemm(BatchArg ba,
                                                int Ma, int Na, int Ka,
                                                int lda_a, int ldb_a, int ldc_a,
                                                float* __restrict__ Df)
{
    extern __shared__ __align__(16) char smem[];
    // ---- geometry ----
    int m0, n0, M, N, K, lda, ldb, ldc;
    const __nv_bfloat16 *A, *B;
    void* Cv = nullptr;
    bool outbf;
    if (MODE == 3) {
        K = DOUT; lda = DOUT; ldb = DOUT;
        if (blockIdx.y < QYT) {
            const BPtr& bp = ba.p[blockIdx.z];
            A = bp.A; B = bp.B; Cv = bp.C;
            M = QROWS; N = SROWS; ldc = SROWS; outbf = false;
            m0 = blockIdx.y * 128; n0 = blockIdx.x * 128;
        } else {
            int idx = ((blockIdx.y - QYT) * 2 + blockIdx.z) * 6 + blockIdx.x;
            if (idx >= 20) return;
            int c = idx >> 2, sub = idx & 3;
            m0 = (sub >> 1) * 128; n0 = (sub & 1) * 128;
            A = ba.p[2].A + (size_t)c * CLS * DOUT;
            B = A;
            Cv = (void*)((__nv_bfloat16*)ba.p[2].C + (size_t)c * CLS * CPAD);
            M = CLS; N = CLS; ldc = CPAD; outbf = true;
        }
    } else {
        const BPtr& bp = ba.p[blockIdx.z];
        A = bp.A; B = bp.B; Cv = bp.C;
        M = Ma; N = Na; K = Ka; lda = lda_a; ldb = ldb_a; ldc = ldc_a;
        outbf = (MODE == 1);
        m0 = blockIdx.y * 128; n0 = blockIdx.x * 128;
    }

    const uint32_t sbase = smem_u32(smem);
    const int tid  = threadIdx.x;
    const int wid  = tid >> 5, lane = tid & 31;
    const int wm   = wid >> 2, wn = wid & 3;
    const int nk   = (K + 63) >> 6;

    float acc[4][4][4];
    #pragma unroll
    for (int i = 0; i < 4; i++)
        #pragma unroll
        for (int j = 0; j < 4; j++)
            #pragma unroll
            for (int r = 0; r < 4; r++) acc[i][j][r] = 0.f;

    // ---- hoisted load setup ----
    const int ch = tid & 7;
    const int r0 = tid >> 3;
    bool vA[4], vB[4];
    const __nv_bfloat16 *pA[4], *pB[4];
    uint32_t dA[4], dB[4];
    #pragma unroll
    for (int g = 0; g < 4; g++) {
        int row = r0 + 32 * g;
        vA[g] = (m0 + row) < M;
        vB[g] = (n0 + row) < N;
        pA[g] = A + (size_t)(vA[g] ? m0 + row : 0) * lda + ch * 8;
        pB[g] = B + (size_t)(vB[g] ? n0 + row : 0) * ldb + ch * 8;
        dA[g] = (uint32_t)(row * (MG_STRIDE * 2) + ch * 16);
        dB[g] = dA[g] + MG_STAGE_B;
    }

    auto load_stage = [&](int sidx, int kc) {
        const int k0 = kc * 64;
        const uint32_t st = sbase + sidx * (2 * MG_STAGE_B);
        int szk;
        if (k0 + 64 <= K) szk = 16;
        else {
            int ke  = k0 + ch * 8;
            int rem = (K - ke) * 2;
            szk = rem >= 16 ? 16 : (rem > 0 ? rem : 0);
        }
        #pragma unroll
        for (int g = 0; g < 4; g++) {
            cp16(st + dA[g], pA[g] + k0, vA[g] ? szk : 0);
            cp16(st + dB[g], pB[g] + k0, vB[g] ? szk : 0);
        }
        asm volatile("cp.async.commit_group;" ::: "memory");
    };

    // ---- hoisted fragment smem offsets ----
    uint32_t offA[4], offB[2];
    #pragma unroll
    for (int mt = 0; mt < 4; mt++)
        offA[mt] = (uint32_t)(((wm * 64 + mt * 16 + (lane & 15)) * MG_STRIDE
                               + (lane >> 4) * 8) * 2);
    #pragma unroll
    for (int nh = 0; nh < 2; nh++) {
        int nrow = nh * 16 + ((lane >> 4) * 8) + (lane & 7);
        int kof  = ((lane >> 3) & 1) * 8;
        offB[nh] = (uint32_t)(((wn * 32 + nrow) * MG_STRIDE + kof) * 2) + MG_STAGE_B;
    }

    const int pst = nk < 2 ? nk : 2;
    for (int s = 0; s < pst; s++) load_stage(s, s);

    for (int i = 0; i < nk; i++) {
        if (i + 1 < nk) asm volatile("cp.async.wait_group 1;" ::: "memory");
        else            asm volatile("cp.async.wait_group 0;" ::: "memory");
        __syncthreads();

        if (i + 2 < nk) load_stage((i + 2) % 3, i + 2);

        const uint32_t stg = sbase + (i % 3) * (2 * MG_STAGE_B);

        #pragma unroll
        for (int ks = 0; ks < 4; ks++) {
            uint32_t a[4][4], b[4][2];
            // B fragments first (needed by every MMA)
            #pragma unroll
            for (int nh = 0; nh < 2; nh++) {
                uint32_t addr = stg + offB[nh] + ks * 32;
                uint32_t q0, q1, q2, q3;
                asm volatile("ldmatrix.sync.aligned.m8n8.x4.shared.b16 {%0,%1,%2,%3}, [%4];"
                             : "=r"(q0), "=r"(q1), "=r"(q2), "=r"(q3) : "r"(addr));
                b[nh * 2][0] = q0;     b[nh * 2][1] = q1;
                b[nh * 2 + 1][0] = q2; b[nh * 2 + 1][1] = q3;
            }
            // A0, then alternate ldmatrix a[mt+1] with MMAs of tile mt
            {
                uint32_t addr = stg + offA[0] + ks * 32;
                asm volatile("ldmatrix.sync.aligned.m8n8.x4.shared.b16 {%0,%1,%2,%3}, [%4];"
                             : "=r"(a[0][0]), "=r"(a[0][1]), "=r"(a[0][2]), "=r"(a[0][3])
                             : "r"(addr));
            }
            #pragma unroll
            for (int mt = 0; mt < 4; mt++) {
                if (mt < 3) {
                    uint32_t addr = stg + offA[mt + 1] + ks * 32;
                    asm volatile("ldmatrix.sync.aligned.m8n8.x4.shared.b16 {%0,%1,%2,%3}, [%4];"
                                 : "=r"(a[mt+1][0]), "=r"(a[mt+1][1]),
                                   "=r"(a[mt+1][2]), "=r"(a[mt+1][3])
                                 : "r"(addr));
                }
                #pragma unroll
                for (int nt = 0; nt < 4; nt++) {
                    asm volatile(
                        "mma.sync.aligned.m16n8k16.row.col.f32.bf16.bf16.f32 "
                        "{%0,%1,%2,%3}, {%4,%5,%6,%7}, {%8,%9}, {%0,%1,%2,%3};"
                        : "+f"(acc[mt][nt][0]), "+f"(acc[mt][nt][1]),
                          "+f"(acc[mt][nt][2]), "+f"(acc[mt][nt][3])
                        : "r"(a[mt][0]), "r"(a[mt][1]), "r"(a[mt][2]), "r"(a[mt][3]),
                          "r"(b[nt][0]), "r"(b[nt][1]));
                }
            }
        }
    }

    if (MODE == 2) {
        const float* __restrict__ Q = ba.p[blockIdx.z].Q;
        float* Dz = Df + (size_t)blockIdx.z * (size_t)M * 8;
        #pragma unroll
        for (int mt = 0; mt < 4; mt++) {
            #pragma unroll
            for (int r = 0; r < 2; r++) {
                int m = m0 + wm * 64 + mt * 16 + (lane >> 2) + r * 8;
                float p = 0.f;
                if (m < M) {
                    #pragma unroll
                    for (int nt = 0; nt < 4; nt++) {
                        int nb = n0 + wn * 32 + nt * 8 + (lane & 3) * 2;
                        if (nb < N) {
                            float at0 = __bfloat162float(A[(size_t)m * lda + nb]);
                            p += at0 * (acc[mt][nt][r * 2] - 2.f * Q[(size_t)m * ldc + nb]);
                            if (nb + 1 < N) {
                                float at1 = __bfloat162float(A[(size_t)m * lda + nb + 1]);
                                p += at1 * (acc[mt][nt][r * 2 + 1] - 2.f * Q[(size_t)m * ldc + nb + 1]);
                            }
                        }
                    }
                }
                p += __shfl_xor_sync(0xffffffffu, p, 1);
                p += __shfl_xor_sync(0xffffffffu, p, 2);
                if (m < M && (lane & 3) == 0)
                    Dz[(size_t)m * 8 + blockIdx.x * 4 + wn] = p;
            }
        }
        return;
    }

    #pragma unroll
    for (int mt = 0; mt < 4; mt++) {
        #pragma unroll
        for (int nt = 0; nt < 4; nt++) {
            int mb = m0 + wm * 64 + mt * 16 + (lane >> 2);
            int nb = n0 + wn * 32 + nt * 8 + (lane & 3) * 2;
            if (nb >= N) continue;
            if (outbf) {
                __nv_bfloat16* C = (__nv_bfloat16*)Cv;
                if (mb < M)
                    *(__nv_bfloat162*)(C + (size_t)mb * ldc + nb) =
                        __floats2bfloat162_rn(acc[mt][nt][0], acc[mt][nt][1]);
                if (mb + 8 < M)
                    *(__nv_bfloat162*)(C + (size_t)(mb + 8) * ldc + nb) =
                        __floats2bfloat162_rn(acc[mt][nt][2], acc[mt][nt][3]);
            } else {
                float* C = (float*)Cv;
                if (mb < M)
                    *(float2*)(C + (size_t)mb * ldc + nb) =
                        make_float2(acc[mt][nt][0], acc[mt][nt][1]);
                if (mb + 8 < M)
                    *(float2*)(C + (size_t)(mb + 8) * ldc + nb) =
                        make_float2(acc[mt][nt][2], acc[mt][nt][3]);
            }
        }
    }
}

// ------------------------- block reduction helper -------------------------
__device__ __forceinline__ float block_sum_256(float v, float* sh) {
    int tid = threadIdx.x;
    sh[tid] = v; __syncthreads();
    #pragma unroll
    for (int s = 128; s > 0; s >>= 1) {
        if (tid < s) sh[tid] += sh[tid + s];
        __syncthreads();
    }
    float r = sh[0]; __syncthreads();
    return r;
}

// ------------------------- kernel 3: assemble K (LN) and V rows -----------
__global__ void assemble(const float* __restrict__ k_b, const float* __restrict__ v_b,
                         const float* __restrict__ gamma, const float* __restrict__ beta)
{
    __shared__ float sh[256];
    int r = blockIdx.x;
    int t, fbase;
    if (r < SROWS) { fbase = (r / TLEN) * SEQ;                       t = r % TLEN; }
    else { int qr = r - SROWS; fbase = NS * SEQ + (qr / TLEN) * SEQ; t = qr % TLEN; }
    int fa = fbase + c_TA[t];
    int fb = fbase + c_TB[t];

    const __nv_bfloat16* pa = d_Ph + (size_t)fa * WSTK;
    const __nv_bfloat16* pb = d_Ph + (size_t)fb * WSTK;

    int tid = threadIdx.x;
    bool act = tid < (DOUT / 8);
    int j0 = tid * 8;

    float kv[8], vv[8];
    float s1 = 0.f, s2 = 0.f, vn = 0.f;
    if (act) {
        uint4 ka4 = *(const uint4*)(pa + j0);
        uint4 kb4 = *(const uint4*)(pb + DOUT + j0);
        uint4 va4 = *(const uint4*)(pa + 2 * DOUT + j0);
        uint4 vb4 = *(const uint4*)(pb + 3 * DOUT + j0);
        float4 kbias0 = *(const float4*)(k_b + j0), kbias1 = *(const float4*)(k_b + j0 + 4);
        float4 vbias0 = *(const float4*)(v_b + j0), vbias1 = *(const float4*)(v_b + j0 + 4);
        float kbias[8] = {kbias0.x, kbias0.y, kbias0.z, kbias0.w, kbias1.x, kbias1.y, kbias1.z, kbias1.w};
        float vbias[8] = {vbias0.x, vbias0.y, vbias0.z, vbias0.w, vbias1.x, vbias1.y, vbias1.z, vbias1.w};
        const __nv_bfloat162* hka = (const __nv_bfloat162*)&ka4;
        const __nv_bfloat162* hkb = (const __nv_bfloat162*)&kb4;
        const __nv_bfloat162* hva = (const __nv_bfloat162*)&va4;
        const __nv_bfloat162* hvb = (const __nv_bfloat162*)&vb4;
        #pragma unroll
        for (int i = 0; i < 4; i++) {
            kv[2*i]   = __low2float(hka[i])  + __low2float(hkb[i])  + kbias[2*i];
            kv[2*i+1] = __high2float(hka[i]) + __high2float(hkb[i]) + kbias[2*i+1];
            vv[2*i]   = __low2float(hva[i])  + __low2float(hvb[i])  + vbias[2*i];
            vv[2*i+1] = __high2float(hva[i]) + __high2float(hvb[i]) + vbias[2*i+1];
        }
        #pragma unroll
        for (int i = 0; i < 8; i++) {
            s1 += kv[i]; s2 += kv[i] * kv[i]; vn += vv[i] * vv[i];
        }
        __nv_bfloat162 vo[4];
        #pragma unroll
        for (int i = 0; i < 4; i++) vo[i] = __floats2bfloat162_rn(vv[2*i], vv[2*i+1]);
        *(uint4*)(d_VSh + (size_t)r * DOUT + j0) = *(uint4*)vo;
    }
    float S1 = block_sum_256(s1, sh);
    float S2 = block_sum_256(s2, sh);
    float VN = block_sum_256(vn, sh);
    float mu  = S1 / (float)DOUT;
    float var = S2 / (float)DOUT - mu * mu;
    float inv = rsqrtf(var + LN_EPS);
    if (act) {
        float4 g0 = *(const float4*)(gamma + j0), g1 = *(const float4*)(gamma + j0 + 4);
        float4 b0 = *(const float4*)(beta + j0),  b1 = *(const float4*)(beta + j0 + 4);
        float gm[8] = {g0.x, g0.y, g0.z, g0.w, g1.x, g1.y, g1.z, g1.w};
        float bt[8] = {b0.x, b0.y, b0.z, b0.w, b1.x, b1.y, b1.z, b1.w};
        __nv_bfloat162 ko[4];
        #pragma unroll
        for (int i = 0; i < 4; i++)
            ko[i] = __floats2bfloat162_rn((kv[2*i]   - mu) * inv * gm[2*i]   + bt[2*i],
                                          (kv[2*i+1] - mu) * inv * gm[2*i+1] + bt[2*i+1]);
        *(uint4*)(d_KSh + (size_t)r * DOUT + j0) = *(uint4*)ko;
    }
    if (tid == 0) d_VN[r] = VN;
}

// ------------------------- kernel 4: softmax (bf16 out only) --------------
__global__ void softmax_k(float scale) {
    int row  = blockIdx.x;
    int c    = threadIdx.x >> 5;
    int lane = threadIdx.x & 31;
    const float* p = d_QK + (size_t)row * SROWS + c * CLS;
    __nv_bfloat16* pb = d_Ab + (size_t)row * ABLD + c * CPAD;

    float v[5];
    float mx = -1e30f;
    #pragma unroll
    for (int i = 0; i < 5; i++) {
        int j = lane + 32 * i;
        v[i] = (j < CLS) ? p[j] * scale : -1e30f;
        mx = fmaxf(mx, v[i]);
    }
    #pragma unroll
    for (int s = 16; s > 0; s >>= 1) mx = fmaxf(mx, __shfl_xor_sync(0xffffffffu, mx, s));
    float sum = 0.f;
    #pragma unroll
    for (int i = 0; i < 5; i++) {
        int j = lane + 32 * i;
        if (j < CLS) { v[i] = expf(v[i] - mx); sum += v[i]; }
    }
    #pragma unroll
    for (int s = 16; s > 0; s >>= 1) sum += __shfl_xor_sync(0xffffffffu, sum, s);
    float invs = 1.0f / sum;
    #pragma unroll
    for (int i = 0; i < 5; i++) {
        int j = lane + 32 * i;
        if (j < CLS) pb[j] = __float2bfloat16(v[i] * invs);
    }
}

// ------------------------- kernel 5: tiny final reduction -----------------
__global__ void final_k(const float* __restrict__ gt, const float* __restrict__ tw,
                        float* __restrict__ out)
{
    int q = blockIdx.x;
    int c = threadIdx.x >> 5;
    int lane = threadIdx.x & 31;
    float temp = gt[0] * tw[0];

    float tot = 0.f;
    if (lane < TLEN) {
        tot = d_VN[SROWS + q * TLEN + lane];
        const float* dd = d_D2 + ((size_t)c * QROWS + q * TLEN + lane) * 8;
        float4 x = *(const float4*)dd;
        float4 y = *(const float4*)(dd + 4);
        tot += x.x + x.y + x.z + x.w + y.x + y.y + y.z + y.w;
    }
    #pragma unroll
    for (int s = 16; s > 0; s >>= 1) tot += __shfl_xor_sync(0xffffffffu, tot, s);
    if (lane == 0) out[q * WAY + c] = -(tot / (float)TLEN) * temp;
}

// ------------------------- launch -----------------------------------------
extern "C" void kernel_launch(void* const* d_in, const int* in_sizes, int n_in,
                              void* d_out, int out_size) {
    const float* sup   = (const float*)d_in[0];
    const float* qry   = (const float*)d_in[2];
    const float* k_w   = (const float*)d_in[3];
    const float* k_b   = (const float*)d_in[4];
    const float* v_w   = (const float*)d_in[5];
    const float* v_b   = (const float*)d_in[6];
    const float* gamma = (const float*)d_in[7];
    const float* beta  = (const float*)d_in[8];
    const float* gt    = (const float*)d_in[9];
    const float* tw    = (const float*)d_in[10];
    float* out = (float*)d_out;

    __nv_bfloat16 *pXh, *pWT, *pPh, *pKSh, *pVSh, *pAb, *pSSh;
    float *pQK, *pQV, *pD2;
    cudaGetSymbolAddress((void**)&pXh,  d_Xh);
    cudaGetSymbolAddress((void**)&pWT,  d_WT);
    cudaGetSymbolAddress((void**)&pPh,  d_Ph);
    cudaGetSymbolAddress((void**)&pKSh, d_KSh);
    cudaGetSymbolAddress((void**)&pVSh, d_VSh);
    cudaGetSymbolAddress((void**)&pQK,  d_QK);
    cudaGetSymbolAddress((void**)&pQV,  d_QV);
    cudaGetSymbolAddress((void**)&pD2,  d_D2);
    cudaGetSymbolAddress((void**)&pAb,  d_Ab);
    cudaGetSymbolAddress((void**)&pSSh, d_SSh);

    cudaFuncSetAttribute(mgemm<1>, cudaFuncAttributeMaxDynamicSharedMemorySize, MG_SMEM);
    cudaFuncSetAttribute(mgemm<2>, cudaFuncAttributeMaxDynamicSharedMemorySize, MG_SMEM);
    cudaFuncSetAttribute(mgemm<3>, cudaFuncAttributeMaxDynamicSharedMemorySize, MG_SMEM);

    pe_kernel<<<(SEQ * FEAT + 255) / 256, 256>>>();
    build_x<<<(NFRAMES * FEAT / 8 + 255) / 256, 256>>>(sup, qry);
    wtrans<<<dim3(DOUT / 32, FEAT / 32, 4), dim3(32, 8)>>>(k_w, v_w);

    // Projections (bf16 out): Ph[4200, 4608] = Xh @ WT^T
    {
        BatchArg ba = {};
        ba.p[0] = { pXh, pWT, (void*)pPh, nullptr };
        dim3 g((WSTK + 127) / 128, (NFRAMES + 127) / 128, 1);
        mgemm<1><<<g, 256, MG_SMEM>>>(ba, NFRAMES, WSTK, FEAT, FEAT, FEAT, WSTK, nullptr);
    }

    assemble<<<NROWS, 256>>>(k_b, v_b, gamma, beta);

    // Merged QK + QV + per-class SS Gram (grid (6, 112, 2))
    {
        BatchArg ba = {};
        ba.p[0] = { pKSh + (size_t)SROWS * DOUT, pKSh, (void*)pQK, nullptr };
        ba.p[1] = { pVSh + (size_t)SROWS * DOUT, pVSh, (void*)pQV, nullptr };
        ba.p[2] = { pVSh, nullptr, (void*)pSSh, nullptr };
        dim3 g(6, QYT + 2, 2);
        mgemm<3><<<g, 256, MG_SMEM>>>(ba, 0, 0, 0, 0, 0, 0, nullptr);
    }

    softmax_k<<<QROWS, 160>>>(1.0f / sqrtf((float)DOUT));

    // Fused H + distance partials (z=5)
    {
        BatchArg ba = {};
        for (int c = 0; c < WAY; c++)
            ba.p[c] = { pAb + (size_t)c * CPAD,
                        pSSh + (size_t)c * CLS * CPAD,
                        nullptr,
                        pQV + (size_t)c * CLS };
        dim3 g((CLS + 127) / 128, (QROWS + 127) / 128, WAY);
        mgemm<2><<<g, 256, MG_SMEM>>>(ba, QROWS, CLS, CLS, ABLD, CPAD, SROWS, pD2);
    }

    final_k<<<NQ, 160>>>(gt, tw, out);
}

// round 8
// speedup vs baseline: 7.2538x; 1.0050x over previous
#include <cuda_runtime.h>
#include <cuda_bf16.h>
#include <math.h>
#include <stdint.h>

#define SEQ 8
#define FEAT 2048
#define TLEN 28
#define DOUT 1152
#define WAY 5
#define SHOT 5
#define NQ 500
#define NS 25
#define NFRAMES ((NS + NQ) * SEQ)      /* 4200 */
#define NROWS ((NS + NQ) * TLEN)       /* 14700 */
#define SROWS (NS * TLEN)              /* 700 */
#define QROWS (NQ * TLEN)              /* 14000 */
#define CLS 140                        /* SHOT*TLEN */
#define LN_EPS 1e-5f
#define WSTK (4 * DOUT)                /* 4608 */
#define ABLD 720                       /* bf16 attn row stride (5*144) */
#define CPAD 144                       /* padded class block stride */
#define QYT 110                        /* QROWS m-tiles */

// ------------------------- scratch (device globals) -----------------------
__device__ float          d_PE [SEQ * FEAT];
__device__ __nv_bfloat16  d_Xh [NFRAMES * FEAT];
__device__ __nv_bfloat16  d_WT [WSTK * FEAT];
__device__ __nv_bfloat16  d_Ph [NFRAMES * WSTK];
__device__ __nv_bfloat16  d_KSh[NROWS * DOUT];
__device__ __nv_bfloat16  d_VSh[NROWS * DOUT];
__device__ float          d_VN [NROWS];
__device__ float          d_QK [QROWS * SROWS];           // raw scores (fp32)
__device__ __nv_bfloat16  d_Ab [QROWS * ABLD];            // attn bf16, padded blocks
__device__ float          d_QV [QROWS * SROWS];
__device__ float          d_D2 [WAY * QROWS * 8];         // fused distance partials
__device__ __nv_bfloat16  d_SSh[WAY * CLS * CPAD];

__constant__ int c_TA[TLEN] = {0,0,0,0,0,0,0,1,1,1,1,1,1,2,2,2,2,2,3,3,3,3,4,4,4,5,5,6};
__constant__ int c_TB[TLEN] = {1,2,3,4,5,6,7,2,3,4,5,6,7,3,4,5,6,7,4,5,6,7,5,6,7,6,7,7};

__device__ __forceinline__ uint32_t smem_u32(const void* p) {
    uint32_t a;
    asm("{ .reg .u64 t; cvta.to.shared.u64 t, %1; cvt.u32.u64 %0, t; }" : "=r"(a) : "l"(p));
    return a;
}
__device__ __forceinline__ void cp16(uint32_t dst, const void* src, int sz) {
    asm volatile("cp.async.cg.shared.global [%0], [%1], 16, %2;"
                 :: "r"(dst), "l"(src), "r"(sz) : "memory");
}

// ------------------------- kernel 0: positional encoding ------------------
__global__ void pe_kernel() {
    int idx = blockIdx.x * blockDim.x + threadIdx.x;
    if (idx >= SEQ * FEAT) return;
    int pos = idx / FEAT, d = idx % FEAT;
    float coef = -logf(10000.0f) / (float)FEAT;
    float div  = expf((float)(d & ~1) * coef);
    float ang  = (float)pos * div;
    d_PE[idx]  = (d & 1) ? cosf(ang) : sinf(ang);
}

// ------------------------- kernel 1: gather frames + PE -> bf16 -----------
__global__ void build_x(const float* __restrict__ sup, const float* __restrict__ qry) {
    long e = ((long)blockIdx.x * blockDim.x + threadIdx.x) * 8;
    if (e >= (long)NFRAMES * FEAT) return;
    int f = (int)(e / FEAT);
    int d = (int)(e % FEAT);
    int frame = f % SEQ;
    const float* src = (f < NS * SEQ) ? (sup + (long)f * FEAT + d)
                                      : (qry + (long)(f - NS * SEQ) * FEAT + d);
    float4 a = *(const float4*)src;
    float4 b = *(const float4*)(src + 4);
    const float* pe = d_PE + frame * FEAT + d;
    float4 pa = *(const float4*)pe;
    float4 pb = *(const float4*)(pe + 4);
    __nv_bfloat162 h[4];
    h[0] = __floats2bfloat162_rn(a.x + pa.x, a.y + pa.y);
    h[1] = __floats2bfloat162_rn(a.z + pa.z, a.w + pa.w);
    h[2] = __floats2bfloat162_rn(b.x + pb.x, b.y + pb.y);
    h[3] = __floats2bfloat162_rn(b.z + pb.z, b.w + pb.w);
    *(uint4*)(d_Xh + e) = *(uint4*)h;
}

// ------------------------- kernel 2: weight transpose -> bf16 -------------
__global__ void wtrans(const float* __restrict__ kw, const float* __restrict__ vw) {
    __shared__ float t[32][33];
    int p  = blockIdx.z;
    int n0 = blockIdx.x * 32, k0 = blockIdx.y * 32;
    const float* W = ((p < 2) ? kw : vw) + (size_t)((p & 1) * FEAT) * DOUT;
    #pragma unroll
    for (int i = 0; i < 4; i++) {
        int k = k0 + threadIdx.y + i * 8;
        t[threadIdx.y + i * 8][threadIdx.x] = W[(size_t)k * DOUT + n0 + threadIdx.x];
    }
    __syncthreads();
    #pragma unroll
    for (int i = 0; i < 4; i++) {
        int n = n0 + threadIdx.y + i * 8;
        d_WT[(size_t)(p * DOUT + n) * FEAT + k0 + threadIdx.x] =
            __float2bfloat16(t[threadIdx.x][threadIdx.y + i * 8]);
    }
}

// ------------------------- 128x256 projection GEMM (64x64 warp tiles) -----
// C[M,N] = A[M,K] @ B[N,K]^T, bf16 out. BK=64, 3 stages, 1 CTA/SM.
#define PG_STRIDE 72
#define PG_ABYTES (128 * PG_STRIDE * 2)          /* 18432 */
#define PG_BBYTES (256 * PG_STRIDE * 2)          /* 36864 */
#define PG_STAGE  (PG_ABYTES + PG_BBYTES)        /* 55296 */
#define PG_SMEM   (3 * PG_STAGE)                 /* 165888 */

__global__ void __launch_bounds__(256, 1) pgemm(const __nv_bfloat16* __restrict__ A,
                                                const __nv_bfloat16* __restrict__ B,
                                                __nv_bfloat16* __restrict__ C,
                                                int M, int N, int K,
                                                int lda, int ldb, int ldc)
{
    extern __shared__ __align__(16) char smem[];
    const uint32_t sbase = smem_u32(smem);
    const int tid  = threadIdx.x;
    const int wid  = tid >> 5, lane = tid & 31;
    const int wm   = wid >> 2, wn = wid & 3;          // 2x4 warps, warp tile 64x64
    const int m0   = blockIdx.y * 128, n0 = blockIdx.x * 256;
    const int nk   = K >> 6;                          // K divisible by 64

    float acc[4][8][4];
    #pragma unroll
    for (int i = 0; i < 4; i++)
        #pragma unroll
        for (int j = 0; j < 8; j++)
            #pragma unroll
            for (int r = 0; r < 4; r++) acc[i][j][r] = 0.f;

    // ---- hoisted load setup: ch = 16B chunk (0..7), r0 = row (0..31) ----
    const int ch = tid & 7;
    const int r0 = tid >> 3;
    bool vA[4], vB[8];
    const __nv_bfloat16 *pA[4], *pB[8];
    uint32_t dA[4], dB[8];
    #pragma unroll
    for (int g = 0; g < 4; g++) {
        int row = r0 + 32 * g;
        vA[g] = (m0 + row) < M;
        pA[g] = A + (size_t)(vA[g] ? m0 + row : 0) * lda + ch * 8;
        dA[g] = (uint32_t)(row * (PG_STRIDE * 2) + ch * 16);
    }
    #pragma unroll
    for (int g = 0; g < 8; g++) {
        int row = r0 + 32 * g;
        vB[g] = (n0 + row) < N;
        pB[g] = B + (size_t)(vB[g] ? n0 + row : 0) * ldb + ch * 8;
        dB[g] = (uint32_t)(row * (PG_STRIDE * 2) + ch * 16) + PG_ABYTES;
    }

    auto load_stage = [&](int sidx, int kc) {
        const int k0 = kc * 64;
        const uint32_t st = sbase + sidx * PG_STAGE;
        #pragma unroll
        for (int g = 0; g < 4; g++) cp16(st + dA[g], pA[g] + k0, vA[g] ? 16 : 0);
        #pragma unroll
        for (int g = 0; g < 8; g++) cp16(st + dB[g], pB[g] + k0, vB[g] ? 16 : 0);
        asm volatile("cp.async.commit_group;" ::: "memory");
    };

    // ---- hoisted fragment smem offsets ----
    uint32_t offA[4], offB[4];
    #pragma unroll
    for (int mt = 0; mt < 4; mt++)
        offA[mt] = (uint32_t)(((wm * 64 + mt * 16 + (lane & 15)) * PG_STRIDE
                               + (lane >> 4) * 8) * 2);
    #pragma unroll
    for (int nh = 0; nh < 4; nh++) {
        int nrow = wn * 64 + nh * 16 + ((lane >> 4) * 8) + (lane & 7);
        int kof  = ((lane >> 3) & 1) * 8;
        offB[nh] = (uint32_t)((nrow * PG_STRIDE + kof) * 2) + PG_ABYTES;
    }

    const int pst = nk < 2 ? nk : 2;
    for (int s = 0; s < pst; s++) load_stage(s, s);

    for (int i = 0; i < nk; i++) {
        if (i + 1 < nk) asm volatile("cp.async.wait_group 1;" ::: "memory");
        else            asm volatile("cp.async.wait_group 0;" ::: "memory");
        __syncthreads();

        if (i + 2 < nk) load_stage((i + 2) % 3, i + 2);

        const uint32_t stg = sbase + (i % 3) * PG_STAGE;

        #pragma unroll
        for (int ks = 0; ks < 4; ks++) {
            uint32_t a[4][4], b[8][2];
            #pragma unroll
            for (int nh = 0; nh < 4; nh++) {
                uint32_t addr = stg + offB[nh] + ks * 32;
                uint32_t q0, q1, q2, q3;
                asm volatile("ldmatrix.sync.aligned.m8n8.x4.shared.b16 {%0,%1,%2,%3}, [%4];"
                             : "=r"(q0), "=r"(q1), "=r"(q2), "=r"(q3) : "r"(addr));
                b[nh * 2][0] = q0;     b[nh * 2][1] = q1;
                b[nh * 2 + 1][0] = q2; b[nh * 2 + 1][1] = q3;
            }
            {
                uint32_t addr = stg + offA[0] + ks * 32;
                asm volatile("ldmatrix.sync.aligned.m8n8.x4.shared.b16 {%0,%1,%2,%3}, [%4];"
                             : "=r"(a[0][0]), "=r"(a[0][1]), "=r"(a[0][2]), "=r"(a[0][3])
                             : "r"(addr));
            }
            #pragma unroll
            for (int mt = 0; mt < 4; mt++) {
                if (mt < 3) {
                    uint32_t addr = stg + offA[mt + 1] + ks * 32;
                    asm volatile("ldmatrix.sync.aligned.m8n8.x4.shared.b16 {%0,%1,%2,%3}, [%4];"
                                 : "=r"(a[mt+1][0]), "=r"(a[mt+1][1]),
                                   "=r"(a[mt+1][2]), "=r"(a[mt+1][3])
                                 : "r"(addr));
                }
                #pragma unroll
                for (int nt = 0; nt < 8; nt++) {
                    asm volatile(
                        "mma.sync.aligned.m16n8k16.row.col.f32.bf16.bf16.f32 "
                        "{%0,%1,%2,%3}, {%4,%5,%6,%7}, {%8,%9}, {%0,%1,%2,%3};"
                        : "+f"(acc[mt][nt][0]), "+f"(acc[mt][nt][1]),
                          "+f"(acc[mt][nt][2]), "+f"(acc[mt][nt][3])
                        : "r"(a[mt][0]), "r"(a[mt][1]), "r"(a[mt][2]), "r"(a[mt][3]),
                          "r"(b[nt][0]), "r"(b[nt][1]));
                }
            }
        }
    }

    #pragma unroll
    for (int mt = 0; mt < 4; mt++) {
        #pragma unroll
        for (int nt = 0; nt < 8; nt++) {
            int mb = m0 + wm * 64 + mt * 16 + (lane >> 2);
            int nb = n0 + wn * 64 + nt * 8 + (lane & 3) * 2;
            if (nb >= N) continue;
            if (mb < M)
                *(__nv_bfloat162*)(C + (size_t)mb * ldc + nb) =
                    __floats2bfloat162_rn(acc[mt][nt][0], acc[mt][nt][1]);
            if (mb + 8 < M)
                *(__nv_bfloat162*)(C + (size_t)(mb + 8) * ldc + nb) =
                    __floats2bfloat162_rn(acc[mt][nt][2], acc[mt][nt][3]);
        }
    }
}

// ------------------------- bf16 mma.sync NT GEMM (batched, BK=64) ---------
// MODE 2: fused distance epilogue (H GEMM; A is attn).
// MODE 3: merged QK/QV/SS launch, grid (6, 112, 2); per-CTA geometry.
#define MG_STRIDE 72
#define MG_STAGE_B (128 * MG_STRIDE * 2)
#define MG_SMEM (3 * 2 * MG_STAGE_B)

struct BPtr { const __nv_bfloat16* A; const __nv_bfloat16* B; void* C; const float* Q; };
struct BatchArg { BPtr p[5]; };

template<int MODE>
__global__ void __launch_bounds__(256, 2) mgemm(BatchArg ba,
                                                int Ma, int Na, int Ka,
                                                int lda_a, int ldb_a, int ldc_a,
                                                float* __restrict__ Df)
{
    extern __shared__ __align__(16) char smem[];
    int m0, n0, M, N, K, lda, ldb, ldc;
    const __nv_bfloat16 *A, *B;
    void* Cv = nullptr;
    bool outbf;
    if (MODE == 3) {
        K = DOUT; lda = DOUT; ldb = DOUT;
        if (blockIdx.y < QYT) {
            const BPtr& bp = ba.p[blockIdx.z];
            A = bp.A; B = bp.B; Cv = bp.C;
            M = QROWS; N = SROWS; ldc = SROWS; outbf = false;
            m0 = blockIdx.y * 128; n0 = blockIdx.x * 128;
        } else {
            int idx = ((blockIdx.y - QYT) * 2 + blockIdx.z) * 6 + blockIdx.x;
            if (idx >= 20) return;
            int c = idx >> 2, sub = idx & 3;
            m0 = (sub >> 1) * 128; n0 = (sub & 1) * 128;
            A = ba.p[2].A + (size_t)c * CLS * DOUT;
            B = A;
            Cv = (void*)((__nv_bfloat16*)ba.p[2].C + (size_t)c * CLS * CPAD);
            M = CLS; N = CLS; ldc = CPAD; outbf = true;
        }
    } else {
        const BPtr& bp = ba.p[blockIdx.z];
        A = bp.A; B = bp.B; Cv = bp.C;
        M = Ma; N = Na; K = Ka; lda = lda_a; ldb = ldb_a; ldc = ldc_a;
        outbf = false;
        m0 = blockIdx.y * 128; n0 = blockIdx.x * 128;
    }

    const uint32_t sbase = smem_u32(smem);
    const int tid  = threadIdx.x;
    const int wid  = tid >> 5, lane = tid & 31;
    const int wm   = wid >> 2, wn = wid & 3;
    const int nk   = (K + 63) >> 6;

    float acc[4][4][4];
    #pragma unroll
    for (int i = 0; i < 4; i++)
        #pragma unroll
        for (int j = 0; j < 4; j++)
            #pragma unroll
            for (int r = 0; r < 4; r++) acc[i][j][r] = 0.f;

    const int ch = tid & 7;
    const int r0 = tid >> 3;
    bool vA[4], vB[4];
    const __nv_bfloat16 *pA[4], *pB[4];
    uint32_t dA[4], dB[4];
    #pragma unroll
    for (int g = 0; g < 4; g++) {
        int row = r0 + 32 * g;
        vA[g] = (m0 + row) < M;
        vB[g] = (n0 + row) < N;
        pA[g] = A + (size_t)(vA[g] ? m0 + row : 0) * lda + ch * 8;
        pB[g] = B + (size_t)(vB[g] ? n0 + row : 0) * ldb + ch * 8;
        dA[g] = (uint32_t)(row * (MG_STRIDE * 2) + ch * 16);
        dB[g] = dA[g] + MG_STAGE_B;
    }

    auto load_stage = [&](int sidx, int kc) {
        const int k0 = kc * 64;
        const uint32_t st = sbase + sidx * (2 * MG_STAGE_B);
        int szk;
        if (k0 + 64 <= K) szk = 16;
        else {
            int ke  = k0 + ch * 8;
            int rem = (K - ke) * 2;
            szk = rem >= 16 ? 16 : (rem > 0 ? rem : 0);
        }
        #pragma unroll
        for (int g = 0; g < 4; g++) {
            cp16(st + dA[g], pA[g] + k0, vA[g] ? szk : 0);
            cp16(st + dB[g], pB[g] + k0, vB[g] ? szk : 0);
        }
        asm volatile("cp.async.commit_group;" ::: "memory");
    };

    uint32_t offA[4], offB[2];
    #pragma unroll
    for (int mt = 0; mt < 4; mt++)
        offA[mt] = (uint32_t)(((wm * 64 + mt * 16 + (lane & 15)) * MG_STRIDE
                               + (lane >> 4) * 8) * 2);
    #pragma unroll
    for (int nh = 0; nh < 2; nh++) {
        int nrow = nh * 16 + ((lane >> 4) * 8) + (lane & 7);
        int kof  = ((lane >> 3) & 1) * 8;
        offB[nh] = (uint32_t)(((wn * 32 + nrow) * MG_STRIDE + kof) * 2) + MG_STAGE_B;
    }

    const int pst = nk < 2 ? nk : 2;
    for (int s = 0; s < pst; s++) load_stage(s, s);

    for (int i = 0; i < nk; i++) {
        if (i + 1 < nk) asm volatile("cp.async.wait_group 1;" ::: "memory");
        else            asm volatile("cp.async.wait_group 0;" ::: "memory");
        __syncthreads();

        if (i + 2 < nk) load_stage((i + 2) % 3, i + 2);

        const uint32_t stg = sbase + (i % 3) * (2 * MG_STAGE_B);

        #pragma unroll
        for (int ks = 0; ks < 4; ks++) {
            uint32_t a[4][4], b[4][2];
            #pragma unroll
            for (int nh = 0; nh < 2; nh++) {
                uint32_t addr = stg + offB[nh] + ks * 32;
                uint32_t q0, q1, q2, q3;
                asm volatile("ldmatrix.sync.aligned.m8n8.x4.shared.b16 {%0,%1,%2,%3}, [%4];"
                             : "=r"(q0), "=r"(q1), "=r"(q2), "=r"(q3) : "r"(addr));
                b[nh * 2][0] = q0;     b[nh * 2][1] = q1;
                b[nh * 2 + 1][0] = q2; b[nh * 2 + 1][1] = q3;
            }
            {
                uint32_t addr = stg + offA[0] + ks * 32;
                asm volatile("ldmatrix.sync.aligned.m8n8.x4.shared.b16 {%0,%1,%2,%3}, [%4];"
                             : "=r"(a[0][0]), "=r"(a[0][1]), "=r"(a[0][2]), "=r"(a[0][3])
                             : "r"(addr));
            }
            #pragma unroll
            for (int mt = 0; mt < 4; mt++) {
                if (mt < 3) {
                    uint32_t addr = stg + offA[mt + 1] + ks * 32;
                    asm volatile("ldmatrix.sync.aligned.m8n8.x4.shared.b16 {%0,%1,%2,%3}, [%4];"
                                 : "=r"(a[mt+1][0]), "=r"(a[mt+1][1]),
                                   "=r"(a[mt+1][2]), "=r"(a[mt+1][3])
                                 : "r"(addr));
                }
                #pragma unroll
                for (int nt = 0; nt < 4; nt++) {
                    asm volatile(
                        "mma.sync.aligned.m16n8k16.row.col.f32.bf16.bf16.f32 "
                        "{%0,%1,%2,%3}, {%4,%5,%6,%7}, {%8,%9}, {%0,%1,%2,%3};"
                        : "+f"(acc[mt][nt][0]), "+f"(acc[mt][nt][1]),
                          "+f"(acc[mt][nt][2]), "+f"(acc[mt][nt][3])
                        : "r"(a[mt][0]), "r"(a[mt][1]), "r"(a[mt][2]), "r"(a[mt][3]),
                          "r"(b[nt][0]), "r"(b[nt][1]));
                }
            }
        }
    }

    if (MODE == 2) {
        const float* __restrict__ Q = ba.p[blockIdx.z].Q;
        float* Dz = Df + (size_t)blockIdx.z * (size_t)M * 8;
        #pragma unroll
        for (int mt = 0; mt < 4; mt++) {
            #pragma unroll
            for (int r = 0; r < 2; r++) {
                int m = m0 + wm * 64 + mt * 16 + (lane >> 2) + r * 8;
                float p = 0.f;
                if (m < M) {
                    #pragma unroll
                    for (int nt = 0; nt < 4; nt++) {
                        int nb = n0 + wn * 32 + nt * 8 + (lane & 3) * 2;
                        if (nb < N) {
                            float at0 = __bfloat162float(A[(size_t)m * lda + nb]);
                            p += at0 * (acc[mt][nt][r * 2] - 2.f * Q[(size_t)m * ldc + nb]);
                            if (nb + 1 < N) {
                                float at1 = __bfloat162float(A[(size_t)m * lda + nb + 1]);
                                p += at1 * (acc[mt][nt][r * 2 + 1] - 2.f * Q[(size_t)m * ldc + nb + 1]);
                            }
                        }
                    }
                }
                p += __shfl_xor_sync(0xffffffffu, p, 1);
                p += __shfl_xor_sync(0xffffffffu, p, 2);
                if (m < M && (lane & 3) == 0)
                    Dz[(size_t)m * 8 + blockIdx.x * 4 + wn] = p;
            }
        }
        return;
    }

    #pragma unroll
    for (int mt = 0; mt < 4; mt++) {
        #pragma unroll
        for (int nt = 0; nt < 4; nt++) {
            int mb = m0 + wm * 64 + mt * 16 + (lane >> 2);
            int nb = n0 + wn * 32 + nt * 8 + (lane & 3) * 2;
            if (nb >= N) continue;
            if (outbf) {
                __nv_bfloat16* C = (__nv_bfloat16*)Cv;
                if (mb < M)
                    *(__nv_bfloat162*)(C + (size_t)mb * ldc + nb) =
                        __floats2bfloat162_rn(acc[mt][nt][0], acc[mt][nt][1]);
                if (mb + 8 < M)
                    *(__nv_bfloat162*)(C + (size_t)(mb + 8) * ldc + nb) =
                        __floats2bfloat162_rn(acc[mt][nt][2], acc[mt][nt][3]);
            } else {
                float* C = (float*)Cv;
                if (mb < M)
                    *(float2*)(C + (size_t)mb * ldc + nb) =
                        make_float2(acc[mt][nt][0], acc[mt][nt][1]);
                if (mb + 8 < M)
                    *(float2*)(C + (size_t)(mb + 8) * ldc + nb) =
                        make_float2(acc[mt][nt][2], acc[mt][nt][3]);
            }
        }
    }
}

// ------------------------- block reduction helper -------------------------
__device__ __forceinline__ float block_sum_256(float v, float* sh) {
    int tid = threadIdx.x;
    sh[tid] = v; __syncthreads();
    #pragma unroll
    for (int s = 128; s > 0; s >>= 1) {
        if (tid < s) sh[tid] += sh[tid + s];
        __syncthreads();
    }
    float r = sh[0]; __syncthreads();
    return r;
}

// ------------------------- kernel 3: assemble K (LN) and V rows -----------
__global__ void assemble(const float* __restrict__ k_b, const float* __restrict__ v_b,
                         const float* __restrict__ gamma, const float* __restrict__ beta)
{
    __shared__ float sh[256];
    int r = blockIdx.x;
    int t, fbase;
    if (r < SROWS) { fbase = (r / TLEN) * SEQ;                       t = r % TLEN; }
    else { int qr = r - SROWS; fbase = NS * SEQ + (qr / TLEN) * SEQ; t = qr % TLEN; }
    int fa = fbase + c_TA[t];
    int fb = fbase + c_TB[t];

    const __nv_bfloat16* pa = d_Ph + (size_t)fa * WSTK;
    const __nv_bfloat16* pb = d_Ph + (size_t)fb * WSTK;

    int tid = threadIdx.x;
    bool act = tid < (DOUT / 8);
    int j0 = tid * 8;

    float kv[8], vv[8];
    float s1 = 0.f, s2 = 0.f, vn = 0.f;
    if (act) {
        uint4 ka4 = *(const uint4*)(pa + j0);
        uint4 kb4 = *(const uint4*)(pb + DOUT + j0);
        uint4 va4 = *(const uint4*)(pa + 2 * DOUT + j0);
        uint4 vb4 = *(const uint4*)(pb + 3 * DOUT + j0);
        float4 kbias0 = *(const float4*)(k_b + j0), kbias1 = *(const float4*)(k_b + j0 + 4);
        float4 vbias0 = *(const float4*)(v_b + j0), vbias1 = *(const float4*)(v_b + j0 + 4);
        float kbias[8] = {kbias0.x, kbias0.y, kbias0.z, kbias0.w, kbias1.x, kbias1.y, kbias1.z, kbias1.w};
        float vbias[8] = {vbias0.x, vbias0.y, vbias0.z, vbias0.w, vbias1.x, vbias1.y, vbias1.z, vbias1.w};
        const __nv_bfloat162* hka = (const __nv_bfloat162*)&ka4;
        const __nv_bfloat162* hkb = (const __nv_bfloat162*)&kb4;
        const __nv_bfloat162* hva = (const __nv_bfloat162*)&va4;
        const __nv_bfloat162* hvb = (const __nv_bfloat162*)&vb4;
        #pragma unroll
        for (int i = 0; i < 4; i++) {
            kv[2*i]   = __low2float(hka[i])  + __low2float(hkb[i])  + kbias[2*i];
            kv[2*i+1] = __high2float(hka[i]) + __high2float(hkb[i]) + kbias[2*i+1];
            vv[2*i]   = __low2float(hva[i])  + __low2float(hvb[i])  + vbias[2*i];
            vv[2*i+1] = __high2float(hva[i]) + __high2float(hvb[i]) + vbias[2*i+1];
        }
        #pragma unroll
        for (int i = 0; i < 8; i++) {
            s1 += kv[i]; s2 += kv[i] * kv[i]; vn += vv[i] * vv[i];
        }
        __nv_bfloat162 vo[4];
        #pragma unroll
        for (int i = 0; i < 4; i++) vo[i] = __floats2bfloat162_rn(vv[2*i], vv[2*i+1]);
        *(uint4*)(d_VSh + (size_t)r * DOUT + j0) = *(uint4*)vo;
    }
    float S1 = block_sum_256(s1, sh);
    float S2 = block_sum_256(s2, sh);
    float VN = block_sum_256(vn, sh);
    float mu  = S1 / (float)DOUT;
    float var = S2 / (float)DOUT - mu * mu;
    float inv = rsqrtf(var + LN_EPS);
    if (act) {
        float4 g0 = *(const float4*)(gamma + j0), g1 = *(const float4*)(gamma + j0 + 4);
        float4 b0 = *(const float4*)(beta + j0),  b1 = *(const float4*)(beta + j0 + 4);
        float gm[8] = {g0.x, g0.y, g0.z, g0.w, g1.x, g1.y, g1.z, g1.w};
        float bt[8] = {b0.x, b0.y, b0.z, b0.w, b1.x, b1.y, b1.z, b1.w};
        __nv_bfloat162 ko[4];
        #pragma unroll
        for (int i = 0; i < 4; i++)
            ko[i] = __floats2bfloat162_rn((kv[2*i]   - mu) * inv * gm[2*i]   + bt[2*i],
                                          (kv[2*i+1] - mu) * inv * gm[2*i+1] + bt[2*i+1]);
        *(uint4*)(d_KSh + (size_t)r * DOUT + j0) = *(uint4*)ko;
    }
    if (tid == 0) d_VN[r] = VN;
}

// ------------------------- kernel 4: softmax (bf16 out only) --------------
__global__ void softmax_k(float scale) {
    int row  = blockIdx.x;
    int c    = threadIdx.x >> 5;
    int lane = threadIdx.x & 31;
    const float* p = d_QK + (size_t)row * SROWS + c * CLS;
    __nv_bfloat16* pb = d_Ab + (size_t)row * ABLD + c * CPAD;

    float v[5];
    float mx = -1e30f;
    #pragma unroll
    for (int i = 0; i < 5; i++) {
        int j = lane + 32 * i;
        v[i] = (j < CLS) ? p[j] * scale : -1e30f;
        mx = fmaxf(mx, v[i]);
    }
    #pragma unroll
    for (int s = 16; s > 0; s >>= 1) mx = fmaxf(mx, __shfl_xor_sync(0xffffffffu, mx, s));
    float sum = 0.f;
    #pragma unroll
    for (int i = 0; i < 5; i++) {
        int j = lane + 32 * i;
        if (j < CLS) { v[i] = expf(v[i] - mx); sum += v[i]; }
    }
    #pragma unroll
    for (int s = 16; s > 0; s >>= 1) sum += __shfl_xor_sync(0xffffffffu, sum, s);
    float invs = 1.0f / sum;
    #pragma unroll
    for (int i = 0; i < 5; i++) {
        int j = lane + 32 * i;
        if (j < CLS) pb[j] = __float2bfloat16(v[i] * invs);
    }
}

// ------------------------- kernel 5: tiny final reduction -----------------
__global__ void final_k(const float* __restrict__ gt, const float* __restrict__ tw,
                        float* __restrict__ out)
{
    int q = blockIdx.x;
    int c = threadIdx.x >> 5;
    int lane = threadIdx.x & 31;
    float temp = gt[0] * tw[0];

    float tot = 0.f;
    if (lane < TLEN) {
        tot = d_VN[SROWS + q * TLEN + lane];
        const float* dd = d_D2 + ((size_t)c * QROWS + q * TLEN + lane) * 8;
        float4 x = *(const float4*)dd;
        float4 y = *(const float4*)(dd + 4);
        tot += x.x + x.y + x.z + x.w + y.x + y.y + y.z + y.w;
    }
    #pragma unroll
    for (int s = 16; s > 0; s >>= 1) tot += __shfl_xor_sync(0xffffffffu, tot, s);
    if (lane == 0) out[q * WAY + c] = -(tot / (float)TLEN) * temp;
}

// ------------------------- launch -----------------------------------------
extern "C" void kernel_launch(void* const* d_in, const int* in_sizes, int n_in,
                              void* d_out, int out_size) {
    const float* sup   = (const float*)d_in[0];
    const float* qry   = (const float*)d_in[2];
    const float* k_w   = (const float*)d_in[3];
    const float* k_b   = (const float*)d_in[4];
    const float* v_w   = (const float*)d_in[5];
    const float* v_b   = (const float*)d_in[6];
    const float* gamma = (const float*)d_in[7];
    const float* beta  = (const float*)d_in[8];
    const float* gt    = (const float*)d_in[9];
    const float* tw    = (const float*)d_in[10];
    float* out = (float*)d_out;

    __nv_bfloat16 *pXh, *pWT, *pPh, *pKSh, *pVSh, *pAb, *pSSh;
    float *pQK, *pQV, *pD2;
    cudaGetSymbolAddress((void**)&pXh,  d_Xh);
    cudaGetSymbolAddress((void**)&pWT,  d_WT);
    cudaGetSymbolAddress((void**)&pPh,  d_Ph);
    cudaGetSymbolAddress((void**)&pKSh, d_KSh);
    cudaGetSymbolAddress((void**)&pVSh, d_VSh);
    cudaGetSymbolAddress((void**)&pQK,  d_QK);
    cudaGetSymbolAddress((void**)&pQV,  d_QV);
    cudaGetSymbolAddress((void**)&pD2,  d_D2);
    cudaGetSymbolAddress((void**)&pAb,  d_Ab);
    cudaGetSymbolAddress((void**)&pSSh, d_SSh);

    cudaFuncSetAttribute(pgemm,    cudaFuncAttributeMaxDynamicSharedMemorySize, PG_SMEM);
    cudaFuncSetAttribute(mgemm<2>, cudaFuncAttributeMaxDynamicSharedMemorySize, MG_SMEM);
    cudaFuncSetAttribute(mgemm<3>, cudaFuncAttributeMaxDynamicSharedMemorySize, MG_SMEM);

    pe_kernel<<<(SEQ * FEAT + 255) / 256, 256>>>();
    build_x<<<(NFRAMES * FEAT / 8 + 255) / 256, 256>>>(sup, qry);
    wtrans<<<dim3(DOUT / 32, FEAT / 32, 4), dim3(32, 8)>>>(k_w, v_w);

    // Projections (bf16 out): Ph[4200, 4608] = Xh @ WT^T  (128x256 tiles)
    {
        dim3 g((WSTK + 255) / 256, (NFRAMES + 127) / 128);
        pgemm<<<g, 256, PG_SMEM>>>(pXh, pWT, pPh, NFRAMES, WSTK, FEAT, FEAT, FEAT, WSTK);
    }

    assemble<<<NROWS, 256>>>(k_b, v_b, gamma, beta);

    // Merged QK + QV + per-class SS Gram (grid (6, 112, 2))
    {
        BatchArg ba = {};
        ba.p[0] = { pKSh + (size_t)SROWS * DOUT, pKSh, (void*)pQK, nullptr };
        ba.p[1] = { pVSh + (size_t)SROWS * DOUT, pVSh, (void*)pQV, nullptr };
        ba.p[2] = { pVSh, nullptr, (void*)pSSh, nullptr };
        dim3 g(6, QYT + 2, 2);
        mgemm<3><<<g, 256, MG_SMEM>>>(ba, 0, 0, 0, 0, 0, 0, nullptr);
    }

    softmax_k<<<QROWS, 160>>>(1.0f / sqrtf((float)DOUT));

    // Fused H + distance partials (z=5)
    {
        BatchArg ba = {};
        for (int c = 0; c < WAY; c++)
            ba.p[c] = { pAb + (size_t)c * CPAD,
                        pSSh + (size_t)c * CLS * CPAD,
                        nullptr,
                        pQV + (size_t)c * CLS };
        dim3 g((CLS + 127) / 128, (QROWS + 127) / 128, WAY);
        mgemm<2><<<g, 256, MG_SMEM>>>(ba, QROWS, CLS, CLS, ABLD, CPAD, SROWS, pD2);
    }

    final_k<<<NQ, 160>>>(gt, tw, out);
}

// round 9
// speedup vs baseline: 7.5106x; 1.0354x over previous
#include <cuda_runtime.h>
#include <cuda_bf16.h>
#include <math.h>
#include <stdint.h>

#define SEQ 8
#define FEAT 2048
#define TLEN 28
#define DOUT 1152
#define WAY 5
#define SHOT 5
#define NQ 500
#define NS 25
#define CLIPS (NS + NQ)                /* 525 */
#define NFRAMES (CLIPS * SEQ)          /* 4200 */
#define NROWS (CLIPS * TLEN)           /* 14700 */
#define SROWS (NS * TLEN)              /* 700 */
#define QROWS (NQ * TLEN)              /* 14000 */
#define CLS 140                        /* SHOT*TLEN */
#define LN_EPS 1e-5f
#define WSTK (4 * DOUT)                /* 4608 */
#define ABLD 720                       /* bf16 attn row stride (5*144) */
#define CPAD 144                       /* padded class block stride */
#define QYT 110                        /* QROWS m-tiles */

// ------------------------- scratch (device globals) -----------------------
__device__ __nv_bfloat16  d_Xh [NFRAMES * FEAT];
__device__ __nv_bfloat16  d_WT [WSTK * FEAT];
__device__ __nv_bfloat16  d_Ph [NFRAMES * WSTK];
__device__ __nv_bfloat16  d_KSh[NROWS * DOUT];
__device__ __nv_bfloat16  d_VSh[NROWS * DOUT];
__device__ float          d_VN [NROWS];
__device__ float          d_QK [QROWS * SROWS];           // raw scores (fp32)
__device__ __nv_bfloat16  d_Ab [QROWS * ABLD];            // attn bf16, padded blocks
__device__ float          d_QV [QROWS * SROWS];
__device__ float          d_D2 [WAY * QROWS * 8];         // fused distance partials
__device__ __nv_bfloat16  d_SSh[WAY * CLS * CPAD];

__constant__ int c_TA[TLEN] = {0,0,0,0,0,0,0,1,1,1,1,1,1,2,2,2,2,2,3,3,3,3,4,4,4,5,5,6};
__constant__ int c_TB[TLEN] = {1,2,3,4,5,6,7,2,3,4,5,6,7,3,4,5,6,7,4,5,6,7,5,6,7,6,7,7};

__device__ __forceinline__ uint32_t smem_u32(const void* p) {
    uint32_t a;
    asm("{ .reg .u64 t; cvta.to.shared.u64 t, %1; cvt.u32.u64 %0, t; }" : "=r"(a) : "l"(p));
    return a;
}
__device__ __forceinline__ void cp16(uint32_t dst, const void* src, int sz) {
    asm volatile("cp.async.cg.shared.global [%0], [%1], 16, %2;"
                 :: "r"(dst), "l"(src), "r"(sz) : "memory");
}

// ------------------------- kernel 1: gather frames + inline PE -> bf16 ----
__global__ void build_x(const float* __restrict__ sup, const float* __restrict__ qry) {
    long e = ((long)blockIdx.x * blockDim.x + threadIdx.x) * 8;
    if (e >= (long)NFRAMES * FEAT) return;
    int f = (int)(e / FEAT);
    int d = (int)(e % FEAT);
    int frame = f % SEQ;
    const float* src = (f < NS * SEQ) ? (sup + (long)f * FEAT + d)
                                      : (qry + (long)(f - NS * SEQ) * FEAT + d);
    float4 a = *(const float4*)src;
    float4 b = *(const float4*)(src + 4);
    float x[8] = {a.x, a.y, a.z, a.w, b.x, b.y, b.z, b.w};
    const float coef = -logf(10000.0f) / (float)FEAT;
    #pragma unroll
    for (int p = 0; p < 4; p++) {
        float div = __expf((float)(d + 2 * p) * coef);
        float s, c;
        __sincosf((float)frame * div, &s, &c);
        x[2 * p]     += s;
        x[2 * p + 1] += c;
    }
    __nv_bfloat162 h[4];
    #pragma unroll
    for (int p = 0; p < 4; p++) h[p] = __floats2bfloat162_rn(x[2 * p], x[2 * p + 1]);
    *(uint4*)(d_Xh + e) = *(uint4*)h;
}

// ------------------------- kernel 2: weight transpose -> bf16 -------------
__global__ void wtrans(const float* __restrict__ kw, const float* __restrict__ vw) {
    __shared__ float t[32][33];
    int p  = blockIdx.z;
    int n0 = blockIdx.x * 32, k0 = blockIdx.y * 32;
    const float* W = ((p < 2) ? kw : vw) + (size_t)((p & 1) * FEAT) * DOUT;
    #pragma unroll
    for (int i = 0; i < 4; i++) {
        int k = k0 + threadIdx.y + i * 8;
        t[threadIdx.y + i * 8][threadIdx.x] = W[(size_t)k * DOUT + n0 + threadIdx.x];
    }
    __syncthreads();
    #pragma unroll
    for (int i = 0; i < 4; i++) {
        int n = n0 + threadIdx.y + i * 8;
        d_WT[(size_t)(p * DOUT + n) * FEAT + k0 + threadIdx.x] =
            __float2bfloat16(t[threadIdx.x][threadIdx.y + i * 8]);
    }
}

// ------------------------- 128x256 projection GEMM (64x64 warp tiles) -----
#define PG_STRIDE 72
#define PG_ABYTES (128 * PG_STRIDE * 2)
#define PG_BBYTES (256 * PG_STRIDE * 2)
#define PG_STAGE  (PG_ABYTES + PG_BBYTES)
#define PG_SMEM   (3 * PG_STAGE)

__global__ void __launch_bounds__(256, 1) pgemm(const __nv_bfloat16* __restrict__ A,
                                                const __nv_bfloat16* __restrict__ B,
                                                __nv_bfloat16* __restrict__ C,
                                                int M, int N, int K,
                                                int lda, int ldb, int ldc)
{
    extern __shared__ __align__(16) char smem[];
    const uint32_t sbase = smem_u32(smem);
    const int tid  = threadIdx.x;
    const int wid  = tid >> 5, lane = tid & 31;
    const int wm   = wid >> 2, wn = wid & 3;
    const int m0   = blockIdx.y * 128, n0 = blockIdx.x * 256;
    const int nk   = K >> 6;

    float acc[4][8][4];
    #pragma unroll
    for (int i = 0; i < 4; i++)
        #pragma unroll
        for (int j = 0; j < 8; j++)
            #pragma unroll
            for (int r = 0; r < 4; r++) acc[i][j][r] = 0.f;

    const int ch = tid & 7;
    const int r0 = tid >> 3;
    bool vA[4], vB[8];
    const __nv_bfloat16 *pA[4], *pB[8];
    uint32_t dA[4], dB[8];
    #pragma unroll
    for (int g = 0; g < 4; g++) {
        int row = r0 + 32 * g;
        vA[g] = (m0 + row) < M;
        pA[g] = A + (size_t)(vA[g] ? m0 + row : 0) * lda + ch * 8;
        dA[g] = (uint32_t)(row * (PG_STRIDE * 2) + ch * 16);
    }
    #pragma unroll
    for (int g = 0; g < 8; g++) {
        int row = r0 + 32 * g;
        vB[g] = (n0 + row) < N;
        pB[g] = B + (size_t)(vB[g] ? n0 + row : 0) * ldb + ch * 8;
        dB[g] = (uint32_t)(row * (PG_STRIDE * 2) + ch * 16) + PG_ABYTES;
    }

    auto load_stage = [&](int sidx, int kc) {
        const int k0 = kc * 64;
        const uint32_t st = sbase + sidx * PG_STAGE;
        #pragma unroll
        for (int g = 0; g < 4; g++) cp16(st + dA[g], pA[g] + k0, vA[g] ? 16 : 0);
        #pragma unroll
        for (int g = 0; g < 8; g++) cp16(st + dB[g], pB[g] + k0, vB[g] ? 16 : 0);
        asm volatile("cp.async.commit_group;" ::: "memory");
    };

    uint32_t offA[4], offB[4];
    #pragma unroll
    for (int mt = 0; mt < 4; mt++)
        offA[mt] = (uint32_t)(((wm * 64 + mt * 16 + (lane & 15)) * PG_STRIDE
                               + (lane >> 4) * 8) * 2);
    #pragma unroll
    for (int nh = 0; nh < 4; nh++) {
        int nrow = wn * 64 + nh * 16 + ((lane >> 4) * 8) + (lane & 7);
        int kof  = ((lane >> 3) & 1) * 8;
        offB[nh] = (uint32_t)((nrow * PG_STRIDE + kof) * 2) + PG_ABYTES;
    }

    const int pst = nk < 2 ? nk : 2;
    for (int s = 0; s < pst; s++) load_stage(s, s);

    for (int i = 0; i < nk; i++) {
        if (i + 1 < nk) asm volatile("cp.async.wait_group 1;" ::: "memory");
        else            asm volatile("cp.async.wait_group 0;" ::: "memory");
        __syncthreads();

        if (i + 2 < nk) load_stage((i + 2) % 3, i + 2);

        const uint32_t stg = sbase + (i % 3) * PG_STAGE;

        #pragma unroll
        for (int ks = 0; ks < 4; ks++) {
            uint32_t a[4][4], b[8][2];
            #pragma unroll
            for (int nh = 0; nh < 4; nh++) {
                uint32_t addr = stg + offB[nh] + ks * 32;
                uint32_t q0, q1, q2, q3;
                asm volatile("ldmatrix.sync.aligned.m8n8.x4.shared.b16 {%0,%1,%2,%3}, [%4];"
                             : "=r"(q0), "=r"(q1), "=r"(q2), "=r"(q3) : "r"(addr));
                b[nh * 2][0] = q0;     b[nh * 2][1] = q1;
                b[nh * 2 + 1][0] = q2; b[nh * 2 + 1][1] = q3;
            }
            {
                uint32_t addr = stg + offA[0] + ks * 32;
                asm volatile("ldmatrix.sync.aligned.m8n8.x4.shared.b16 {%0,%1,%2,%3}, [%4];"
                             : "=r"(a[0][0]), "=r"(a[0][1]), "=r"(a[0][2]), "=r"(a[0][3])
                             : "r"(addr));
            }
            #pragma unroll
            for (int mt = 0; mt < 4; mt++) {
                if (mt < 3) {
                    uint32_t addr = stg + offA[mt + 1] + ks * 32;
                    asm volatile("ldmatrix.sync.aligned.m8n8.x4.shared.b16 {%0,%1,%2,%3}, [%4];"
                                 : "=r"(a[mt+1][0]), "=r"(a[mt+1][1]),
                                   "=r"(a[mt+1][2]), "=r"(a[mt+1][3])
                                 : "r"(addr));
                }
                #pragma unroll
                for (int nt = 0; nt < 8; nt++) {
                    asm volatile(
                        "mma.sync.aligned.m16n8k16.row.col.f32.bf16.bf16.f32 "
                        "{%0,%1,%2,%3}, {%4,%5,%6,%7}, {%8,%9}, {%0,%1,%2,%3};"
                        : "+f"(acc[mt][nt][0]), "+f"(acc[mt][nt][1]),
                          "+f"(acc[mt][nt][2]), "+f"(acc[mt][nt][3])
                        : "r"(a[mt][0]), "r"(a[mt][1]), "r"(a[mt][2]), "r"(a[mt][3]),
                          "r"(b[nt][0]), "r"(b[nt][1]));
                }
            }
        }
    }

    #pragma unroll
    for (int mt = 0; mt < 4; mt++) {
        #pragma unroll
        for (int nt = 0; nt < 8; nt++) {
            int mb = m0 + wm * 64 + mt * 16 + (lane >> 2);
            int nb = n0 + wn * 64 + nt * 8 + (lane & 3) * 2;
            if (nb >= N) continue;
            if (mb < M)
                *(__nv_bfloat162*)(C + (size_t)mb * ldc + nb) =
                    __floats2bfloat162_rn(acc[mt][nt][0], acc[mt][nt][1]);
            if (mb + 8 < M)
                *(__nv_bfloat162*)(C + (size_t)(mb + 8) * ldc + nb) =
                    __floats2bfloat162_rn(acc[mt][nt][2], acc[mt][nt][3]);
        }
    }
}

// ------------------------- bf16 mma.sync NT GEMM (batched, BK=64) ---------
// MODE 2: fused distance epilogue.  MODE 3: merged QK/QV/SS launch.
#define MG_STRIDE 72
#define MG_STAGE_B (128 * MG_STRIDE * 2)
#define MG_SMEM (3 * 2 * MG_STAGE_B)

struct BPtr { const __nv_bfloat16* A; const __nv_bfloat16* B; void* C; const float* Q; };
struct BatchArg { BPtr p[5]; };

template<int MODE>
__global__ void __launch_bounds__(256, 2) mgemm(BatchArg ba,
                                                int Ma, int Na, int Ka,
                                                int lda_a, int ldb_a, int ldc_a,
                                                float* __restrict__ Df)
{
    extern __shared__ __align__(16) char smem[];
    int m0, n0, M, N, K, lda, ldb, ldc;
    const __nv_bfloat16 *A, *B;
    void* Cv = nullptr;
    bool outbf;
    if (MODE == 3) {
        K = DOUT; lda = DOUT; ldb = DOUT;
        if (blockIdx.y < QYT) {
            const BPtr& bp = ba.p[blockIdx.z];
            A = bp.A; B = bp.B; Cv = bp.C;
            M = QROWS; N = SROWS; ldc = SROWS; outbf = false;
            m0 = blockIdx.y * 128; n0 = blockIdx.x * 128;
        } else {
            int idx = ((blockIdx.y - QYT) * 2 + blockIdx.z) * 6 + blockIdx.x;
            if (idx >= 20) return;
            int c = idx >> 2, sub = idx & 3;
            m0 = (sub >> 1) * 128; n0 = (sub & 1) * 128;
            A = ba.p[2].A + (size_t)c * CLS * DOUT;
            B = A;
            Cv = (void*)((__nv_bfloat16*)ba.p[2].C + (size_t)c * CLS * CPAD);
            M = CLS; N = CLS; ldc = CPAD; outbf = true;
        }
    } else {
        const BPtr& bp = ba.p[blockIdx.z];
        A = bp.A; B = bp.B; Cv = bp.C;
        M = Ma; N = Na; K = Ka; lda = lda_a; ldb = ldb_a; ldc = ldc_a;
        outbf = false;
        m0 = blockIdx.y * 128; n0 = blockIdx.x * 128;
    }

    const uint32_t sbase = smem_u32(smem);
    const int tid  = threadIdx.x;
    const int wid  = tid >> 5, lane = tid & 31;
    const int wm   = wid >> 2, wn = wid & 3;
    const int nk   = (K + 63) >> 6;

    float acc[4][4][4];
    #pragma unroll
    for (int i = 0; i < 4; i++)
        #pragma unroll
        for (int j = 0; j < 4; j++)
            #pragma unroll
            for (int r = 0; r < 4; r++) acc[i][j][r] = 0.f;

    const int ch = tid & 7;
    const int r0 = tid >> 3;
    bool vA[4], vB[4];
    const __nv_bfloat16 *pA[4], *pB[4];
    uint32_t dA[4], dB[4];
    #pragma unroll
    for (int g = 0; g < 4; g++) {
        int row = r0 + 32 * g;
        vA[g] = (m0 + row) < M;
        vB[g] = (n0 + row) < N;
        pA[g] = A + (size_t)(vA[g] ? m0 + row : 0) * lda + ch * 8;
        pB[g] = B + (size_t)(vB[g] ? n0 + row : 0) * ldb + ch * 8;
        dA[g] = (uint32_t)(row * (MG_STRIDE * 2) + ch * 16);
        dB[g] = dA[g] + MG_STAGE_B;
    }

    auto load_stage = [&](int sidx, int kc) {
        const int k0 = kc * 64;
        const uint32_t st = sbase + sidx * (2 * MG_STAGE_B);
        int szk;
        if (k0 + 64 <= K) szk = 16;
        else {
            int ke  = k0 + ch * 8;
            int rem = (K - ke) * 2;
            szk = rem >= 16 ? 16 : (rem > 0 ? rem : 0);
        }
        #pragma unroll
        for (int g = 0; g < 4; g++) {
            cp16(st + dA[g], pA[g] + k0, vA[g] ? szk : 0);
            cp16(st + dB[g], pB[g] + k0, vB[g] ? szk : 0);
        }
        asm volatile("cp.async.commit_group;" ::: "memory");
    };

    uint32_t offA[4], offB[2];
    #pragma unroll
    for (int mt = 0; mt < 4; mt++)
        offA[mt] = (uint32_t)(((wm * 64 + mt * 16 + (lane & 15)) * MG_STRIDE
                               + (lane >> 4) * 8) * 2);
    #pragma unroll
    for (int nh = 0; nh < 2; nh++) {
        int nrow = nh * 16 + ((lane >> 4) * 8) + (lane & 7);
        int kof  = ((lane >> 3) & 1) * 8;
        offB[nh] = (uint32_t)(((wn * 32 + nrow) * MG_STRIDE + kof) * 2) + MG_STAGE_B;
    }

    const int pst = nk < 2 ? nk : 2;
    for (int s = 0; s < pst; s++) load_stage(s, s);

    for (int i = 0; i < nk; i++) {
        if (i + 1 < nk) asm volatile("cp.async.wait_group 1;" ::: "memory");
        else            asm volatile("cp.async.wait_group 0;" ::: "memory");
        __syncthreads();

        if (i + 2 < nk) load_stage((i + 2) % 3, i + 2);

        const uint32_t stg = sbase + (i % 3) * (2 * MG_STAGE_B);

        #pragma unroll
        for (int ks = 0; ks < 4; ks++) {
            uint32_t a[4][4], b[4][2];
            #pragma unroll
            for (int nh = 0; nh < 2; nh++) {
                uint32_t addr = stg + offB[nh] + ks * 32;
                uint32_t q0, q1, q2, q3;
                asm volatile("ldmatrix.sync.aligned.m8n8.x4.shared.b16 {%0,%1,%2,%3}, [%4];"
                             : "=r"(q0), "=r"(q1), "=r"(q2), "=r"(q3) : "r"(addr));
                b[nh * 2][0] = q0;     b[nh * 2][1] = q1;
                b[nh * 2 + 1][0] = q2; b[nh * 2 + 1][1] = q3;
            }
            {
                uint32_t addr = stg + offA[0] + ks * 32;
                asm volatile("ldmatrix.sync.aligned.m8n8.x4.shared.b16 {%0,%1,%2,%3}, [%4];"
                             : "=r"(a[0][0]), "=r"(a[0][1]), "=r"(a[0][2]), "=r"(a[0][3])
                             : "r"(addr));
            }
            #pragma unroll
            for (int mt = 0; mt < 4; mt++) {
                if (mt < 3) {
                    uint32_t addr = stg + offA[mt + 1] + ks * 32;
                    asm volatile("ldmatrix.sync.aligned.m8n8.x4.shared.b16 {%0,%1,%2,%3}, [%4];"
                                 : "=r"(a[mt+1][0]), "=r"(a[mt+1][1]),
                                   "=r"(a[mt+1][2]), "=r"(a[mt+1][3])
                                 : "r"(addr));
                }
                #pragma unroll
                for (int nt = 0; nt < 4; nt++) {
                    asm volatile(
                        "mma.sync.aligned.m16n8k16.row.col.f32.bf16.bf16.f32 "
                        "{%0,%1,%2,%3}, {%4,%5,%6,%7}, {%8,%9}, {%0,%1,%2,%3};"
                        : "+f"(acc[mt][nt][0]), "+f"(acc[mt][nt][1]),
                          "+f"(acc[mt][nt][2]), "+f"(acc[mt][nt][3])
                        : "r"(a[mt][0]), "r"(a[mt][1]), "r"(a[mt][2]), "r"(a[mt][3]),
                          "r"(b[nt][0]), "r"(b[nt][1]));
                }
            }
        }
    }

    if (MODE == 2) {
        const float* __restrict__ Q = ba.p[blockIdx.z].Q;
        float* Dz = Df + (size_t)blockIdx.z * (size_t)M * 8;
        #pragma unroll
        for (int mt = 0; mt < 4; mt++) {
            #pragma unroll
            for (int r = 0; r < 2; r++) {
                int m = m0 + wm * 64 + mt * 16 + (lane >> 2) + r * 8;
                float p = 0.f;
                if (m < M) {
                    #pragma unroll
                    for (int nt = 0; nt < 4; nt++) {
                        int nb = n0 + wn * 32 + nt * 8 + (lane & 3) * 2;
                        if (nb < N) {
                            float at0 = __bfloat162float(A[(size_t)m * lda + nb]);
                            p += at0 * (acc[mt][nt][r * 2] - 2.f * Q[(size_t)m * ldc + nb]);
                            if (nb + 1 < N) {
                                float at1 = __bfloat162float(A[(size_t)m * lda + nb + 1]);
                                p += at1 * (acc[mt][nt][r * 2 + 1] - 2.f * Q[(size_t)m * ldc + nb + 1]);
                            }
                        }
                    }
                }
                p += __shfl_xor_sync(0xffffffffu, p, 1);
                p += __shfl_xor_sync(0xffffffffu, p, 2);
                if (m < M && (lane & 3) == 0)
                    Dz[(size_t)m * 8 + blockIdx.x * 4 + wn] = p;
            }
        }
        return;
    }

    #pragma unroll
    for (int mt = 0; mt < 4; mt++) {
        #pragma unroll
        for (int nt = 0; nt < 4; nt++) {
            int mb = m0 + wm * 64 + mt * 16 + (lane >> 2);
            int nb = n0 + wn * 32 + nt * 8 + (lane & 3) * 2;
            if (nb >= N) continue;
            if (outbf) {
                __nv_bfloat16* C = (__nv_bfloat16*)Cv;
                if (mb < M)
                    *(__nv_bfloat162*)(C + (size_t)mb * ldc + nb) =
                        __floats2bfloat162_rn(acc[mt][nt][0], acc[mt][nt][1]);
                if (mb + 8 < M)
                    *(__nv_bfloat162*)(C + (size_t)(mb + 8) * ldc + nb) =
                        __floats2bfloat162_rn(acc[mt][nt][2], acc[mt][nt][3]);
            } else {
                float* C = (float*)Cv;
                if (mb < M)
                    *(float2*)(C + (size_t)mb * ldc + nb) =
                        make_float2(acc[mt][nt][0], acc[mt][nt][1]);
                if (mb + 8 < M)
                    *(float2*)(C + (size_t)(mb + 8) * ldc + nb) =
                        make_float2(acc[mt][nt][2], acc[mt][nt][3]);
            }
        }
    }
}

// ------------------------- kernel 3: clip-level assemble ------------------
// One block per clip: stage 8 frame rows of Ph (73.7 KB) in smem, then one
// warp per tuple-row computes K (LayerNorm) and V with warp-shuffle stats.
#define ASM_SMEM (8 * WSTK * 2)        /* 73728 bytes */

__global__ void __launch_bounds__(1024) assemble(const float* __restrict__ k_b,
                                                 const float* __restrict__ v_b,
                                                 const float* __restrict__ gamma,
                                                 const float* __restrict__ beta)
{
    extern __shared__ __align__(16) __nv_bfloat16 sf[];
    int clip = blockIdx.x;
    int tid = threadIdx.x;

    const uint4* src = (const uint4*)(d_Ph + (size_t)clip * 8 * WSTK);
    uint4* dst = (uint4*)sf;
    #pragma unroll
    for (int i = 0; i < 5; i++) {
        int idx = tid + 1024 * i;
        if (idx < (8 * WSTK) / 8) dst[idx] = src[idx];
    }
    __syncthreads();

    int w = tid >> 5, lane = tid & 31;
    if (w >= TLEN) return;
    int fa = c_TA[w], fb = c_TB[w];
    int r = (clip < NS) ? clip * TLEN + w : SROWS + (clip - NS) * TLEN + w;

    const __nv_bfloat162* A2 = (const __nv_bfloat162*)(sf + fa * WSTK);
    const __nv_bfloat162* B2 = (const __nv_bfloat162*)(sf + fb * WSTK);
    const float2* kb2 = (const float2*)k_b;
    const float2* vb2 = (const float2*)v_b;
    __nv_bfloat162* vout = (__nv_bfloat162*)(d_VSh + (size_t)r * DOUT);

    float s1 = 0.f, s2 = 0.f, vn = 0.f;
    #pragma unroll 6
    for (int i = 0; i < 18; i++) {
        int j2 = lane + 32 * i;
        __nv_bfloat162 ka = A2[j2];
        __nv_bfloat162 kb = B2[DOUT / 2 + j2];
        float2 kbias = kb2[j2];
        float k0 = __low2float(ka)  + __low2float(kb)  + kbias.x;
        float k1 = __high2float(ka) + __high2float(kb) + kbias.y;
        s1 += k0 + k1; s2 += k0 * k0 + k1 * k1;
        __nv_bfloat162 va = A2[DOUT + j2];
        __nv_bfloat162 vb = B2[3 * DOUT / 2 + j2];
        float2 vbias = vb2[j2];
        float v0 = __low2float(va)  + __low2float(vb)  + vbias.x;
        float v1 = __high2float(va) + __high2float(vb) + vbias.y;
        vn += v0 * v0 + v1 * v1;
        vout[j2] = __floats2bfloat162_rn(v0, v1);
    }
    #pragma unroll
    for (int s = 16; s > 0; s >>= 1) {
        s1 += __shfl_xor_sync(0xffffffffu, s1, s);
        s2 += __shfl_xor_sync(0xffffffffu, s2, s);
        vn += __shfl_xor_sync(0xffffffffu, vn, s);
    }
    float mu  = s1 / (float)DOUT;
    float var = s2 / (float)DOUT - mu * mu;
    float inv = rsqrtf(var + LN_EPS);

    const float2* g2 = (const float2*)gamma;
    const float2* b2 = (const float2*)beta;
    __nv_bfloat162* kout = (__nv_bfloat162*)(d_KSh + (size_t)r * DOUT);
    #pragma unroll 6
    for (int i = 0; i < 18; i++) {
        int j2 = lane + 32 * i;
        __nv_bfloat162 ka = A2[j2];
        __nv_bfloat162 kb = B2[DOUT / 2 + j2];
        float2 kbias = kb2[j2];
        float k0 = __low2float(ka)  + __low2float(kb)  + kbias.x;
        float k1 = __high2float(ka) + __high2float(kb) + kbias.y;
        float2 g = g2[j2], bt = b2[j2];
        kout[j2] = __floats2bfloat162_rn((k0 - mu) * inv * g.x + bt.x,
                                         (k1 - mu) * inv * g.y + bt.y);
    }
    if (lane == 0) d_VN[r] = vn;
}

// ------------------------- kernel 4: softmax (bf16 out only) --------------
__global__ void softmax_k(float scale) {
    int row  = blockIdx.x;
    int c    = threadIdx.x >> 5;
    int lane = threadIdx.x & 31;
    const float* p = d_QK + (size_t)row * SROWS + c * CLS;
    __nv_bfloat16* pb = d_Ab + (size_t)row * ABLD + c * CPAD;

    float v[5];
    float mx = -1e30f;
    #pragma unroll
    for (int i = 0; i < 5; i++) {
        int j = lane + 32 * i;
        v[i] = (j < CLS) ? p[j] * scale : -1e30f;
        mx = fmaxf(mx, v[i]);
    }
    #pragma unroll
    for (int s = 16; s > 0; s >>= 1) mx = fmaxf(mx, __shfl_xor_sync(0xffffffffu, mx, s));
    float sum = 0.f;
    #pragma unroll
    for (int i = 0; i < 5; i++) {
        int j = lane + 32 * i;
        if (j < CLS) { v[i] = expf(v[i] - mx); sum += v[i]; }
    }
    #pragma unroll
    for (int s = 16; s > 0; s >>= 1) sum += __shfl_xor_sync(0xffffffffu, sum, s);
    float invs = 1.0f / sum;
    #pragma unroll
    for (int i = 0; i < 5; i++) {
        int j = lane + 32 * i;
        if (j < CLS) pb[j] = __float2bfloat16(v[i] * invs);
    }
}

// ------------------------- kernel 5: tiny final reduction -----------------
__global__ void final_k(const float* __restrict__ gt, const float* __restrict__ tw,
                        float* __restrict__ out)
{
    int q = blockIdx.x;
    int c = threadIdx.x >> 5;
    int lane = threadIdx.x & 31;
    float temp = gt[0] * tw[0];

    float tot = 0.f;
    if (lane < TLEN) {
        tot = d_VN[SROWS + q * TLEN + lane];
        const float* dd = d_D2 + ((size_t)c * QROWS + q * TLEN + lane) * 8;
        float4 x = *(const float4*)dd;
        float4 y = *(const float4*)(dd + 4);
        tot += x.x + x.y + x.z + x.w + y.x + y.y + y.z + y.w;
    }
    #pragma unroll
    for (int s = 16; s > 0; s >>= 1) tot += __shfl_xor_sync(0xffffffffu, tot, s);
    if (lane == 0) out[q * WAY + c] = -(tot / (float)TLEN) * temp;
}

// ------------------------- launch -----------------------------------------
extern "C" void kernel_launch(void* const* d_in, const int* in_sizes, int n_in,
                              void* d_out, int out_size) {
    const float* sup   = (const float*)d_in[0];
    const float* qry   = (const float*)d_in[2];
    const float* k_w   = (const float*)d_in[3];
    const float* k_b   = (const float*)d_in[4];
    const float* v_w   = (const float*)d_in[5];
    const float* v_b   = (const float*)d_in[6];
    const float* gamma = (const float*)d_in[7];
    const float* beta  = (const float*)d_in[8];
    const float* gt    = (const float*)d_in[9];
    const float* tw    = (const float*)d_in[10];
    float* out = (float*)d_out;

    __nv_bfloat16 *pXh, *pWT, *pPh, *pKSh, *pVSh, *pAb, *pSSh;
    float *pQK, *pQV, *pD2;
    cudaGetSymbolAddress((void**)&pXh,  d_Xh);
    cudaGetSymbolAddress((void**)&pWT,  d_WT);
    cudaGetSymbolAddress((void**)&pPh,  d_Ph);
    cudaGetSymbolAddress((void**)&pKSh, d_KSh);
    cudaGetSymbolAddress((void**)&pVSh, d_VSh);
    cudaGetSymbolAddress((void**)&pQK,  d_QK);
    cudaGetSymbolAddress((void**)&pQV,  d_QV);
    cudaGetSymbolAddress((void**)&pD2,  d_D2);
    cudaGetSymbolAddress((void**)&pAb,  d_Ab);
    cudaGetSymbolAddress((void**)&pSSh, d_SSh);

    cudaFuncSetAttribute(pgemm,    cudaFuncAttributeMaxDynamicSharedMemorySize, PG_SMEM);
    cudaFuncSetAttribute(mgemm<2>, cudaFuncAttributeMaxDynamicSharedMemorySize, MG_SMEM);
    cudaFuncSetAttribute(mgemm<3>, cudaFuncAttributeMaxDynamicSharedMemorySize, MG_SMEM);
    cudaFuncSetAttribute(assemble, cudaFuncAttributeMaxDynamicSharedMemorySize, ASM_SMEM);

    build_x<<<(NFRAMES * FEAT / 8 + 255) / 256, 256>>>(sup, qry);
    wtrans<<<dim3(DOUT / 32, FEAT / 32, 4), dim3(32, 8)>>>(k_w, v_w);

    // Projections (bf16 out): Ph[4200, 4608] = Xh @ WT^T  (128x256 tiles)
    {
        dim3 g((WSTK + 255) / 256, (NFRAMES + 127) / 128);
        pgemm<<<g, 256, PG_SMEM>>>(pXh, pWT, pPh, NFRAMES, WSTK, FEAT, FEAT, FEAT, WSTK);
    }

    assemble<<<CLIPS, 1024, ASM_SMEM>>>(k_b, v_b, gamma, beta);

    // Merged QK + QV + per-class SS Gram (grid (6, 112, 2))
    {
        BatchArg ba = {};
        ba.p[0] = { pKSh + (size_t)SROWS * DOUT, pKSh, (void*)pQK, nullptr };
        ba.p[1] = { pVSh + (size_t)SROWS * DOUT, pVSh, (void*)pQV, nullptr };
        ba.p[2] = { pVSh, nullptr, (void*)pSSh, nullptr };
        dim3 g(6, QYT + 2, 2);
        mgemm<3><<<g, 256, MG_SMEM>>>(ba, 0, 0, 0, 0, 0, 0, nullptr);
    }

    softmax_k<<<QROWS, 160>>>(1.0f / sqrtf((float)DOUT));

    // Fused H + distance partials (z=5)
    {
        BatchArg ba = {};
        for (int c = 0; c < WAY; c++)
            ba.p[c] = { pAb + (size_t)c * CPAD,
                        pSSh + (size_t)c * CLS * CPAD,
                        nullptr,
                        pQV + (size_t)c * CLS };
        dim3 g((CLS + 127) / 128, (QROWS + 127) / 128, WAY);
        mgemm<2><<<g, 256, MG_SMEM>>>(ba, QROWS, CLS, CLS, ABLD, CPAD, SROWS, pD2);
    }

    final_k<<<NQ, 160>>>(gt, tw, out);
}